// round 5
// baseline (speedup 1.0000x reference)
#include <cuda_runtime.h>
#include <cstdint>

// Problem constants
#define Bb 32
#define Np 2048
#define NSd 512
#define KN 16
#define NT (Bb*NSd)          // 16384 tiles (b,ns)
#define JJ (NT*KN)           // 262144 columns
#define EPSf 1e-5

// ---------------- scratch (static __device__, no allocs) ----------------
__device__ float  g_grouped[NT*KN*3];          // 3 MB  grouped coords [tile][k][3]
__device__ double g_sum9[9];                   // Sg(3) + Sgg(6)
__device__ float  g_Weff2[256*3];
__device__ float  g_W3T[512*512];              // [c][o]
__device__ float  g_W4T[512*256];              // [c][o]
__device__ float  g_A1[256*3];
__device__ float  g_c1v[256];
__device__ float  g_H [256u*JJ];               // 268 MB  h (post BN1+ReLU) [c][j]
__device__ float  g_P [256u*NT];               // pooled [c][tile]
__device__ float  g_Zp[512u*NT];               // W3a @ pooled [o][tile]
__device__ float  g_Z [512u*JJ];               // 537 MB
__device__ float  g_Z4[256u*JJ];               // 268 MB
__device__ double g_bn3sum[512], g_bn3sq[512], g_bn4sum[256], g_bn4sq[256];
__device__ float  g_a3[512], g_d3[512], g_a4[256], g_d4[256];

// ---------------- zero accumulators (graph replays!) ----------------
__global__ void zerok() {
    int t = threadIdx.x;
    if (t < 9) g_sum9[t] = 0.0;
    for (int i = t; i < 512; i += blockDim.x) { g_bn3sum[i] = 0.0; g_bn3sq[i] = 0.0; }
    for (int i = t; i < 256; i += blockDim.x) { g_bn4sum[i] = 0.0; g_bn4sq[i] = 0.0; }
}

// ---------------- precompute Weff2 = W2 @ (w1[:, :3]+w1[:,3:]), transposes ----------------
__global__ void precompk(const float* __restrict__ w1, const float* __restrict__ w2,
                         const float* __restrict__ w3, const float* __restrict__ w4) {
    int t = threadIdx.x;
    if (t < 256) {
        double s0 = 0.0, s1 = 0.0, s2 = 0.0;
        for (int i = 0; i < 256; i++) {
            double wi = (double)w2[t*256 + i];
            s0 += wi * ((double)w1[i*6+0] + (double)w1[i*6+3]);
            s1 += wi * ((double)w1[i*6+1] + (double)w1[i*6+4]);
            s2 += wi * ((double)w1[i*6+2] + (double)w1[i*6+5]);
        }
        g_Weff2[t*3+0] = (float)s0; g_Weff2[t*3+1] = (float)s1; g_Weff2[t*3+2] = (float)s2;
    }
    for (int idx = t; idx < 512*512; idx += blockDim.x) {
        int o = idx >> 9, c = idx & 511;
        g_W3T[c*512 + o] = w3[idx];
    }
    for (int idx = t; idx < 256*512; idx += blockDim.x) {
        int o = idx >> 9, c = idx & 511;
        g_W4T[c*256 + o] = w4[idx];
    }
}

// ---------------- FPS: 32 blocks (one per batch), 512 threads, 4 pts/thread ----------------
__global__ void fpsk(const float* __restrict__ p, float* __restrict__ outc) {
    __shared__ float sp[Np*3];
    __shared__ unsigned long long skey[16];
    __shared__ int s_cs;
    int b = blockIdx.x, t = threadIdx.x;
    for (int i = t; i < Np*3; i += 512) sp[i] = p[b*Np*3 + i];
    __syncthreads();

    float px[4], py[4], pz[4], dist[4];
    #pragma unroll
    for (int i = 0; i < 4; i++) {
        int n = t + 512*i;
        px[i] = sp[n*3+0]; py[i] = sp[n*3+1]; pz[i] = sp[n*3+2];
        dist[i] = 1e10f;
    }
    int lane = t & 31, wid = t >> 5;
    int cs = 0;
    for (int s = 0; s < NSd; s++) {
        if (t == 0) {
            outc[(b*NSd + s)*3 + 0] = sp[cs*3+0];
            outc[(b*NSd + s)*3 + 1] = sp[cs*3+1];
            outc[(b*NSd + s)*3 + 2] = sp[cs*3+2];
        }
        float cx = sp[cs*3+0], cy = sp[cs*3+1], cz = sp[cs*3+2];
        unsigned long long best = 0ull;
        #pragma unroll
        for (int i = 0; i < 4; i++) {
            float dx = __fadd_rn(px[i], -cx);
            float dy = __fadd_rn(py[i], -cy);
            float dz = __fadd_rn(pz[i], -cz);
            float d = __fadd_rn(__fadd_rn(__fmul_rn(dx,dx), __fmul_rn(dy,dy)), __fmul_rn(dz,dz));
            dist[i] = fminf(dist[i], d);
            unsigned long long key = ((unsigned long long)__float_as_uint(dist[i]) << 32)
                                   | (unsigned)(Np - 1 - (t + 512*i));
            best = max(best, key);
        }
        #pragma unroll
        for (int off = 16; off; off >>= 1)
            best = max(best, __shfl_down_sync(0xffffffffu, best, off));
        if (lane == 0) skey[wid] = best;
        __syncthreads();
        if (t < 16) {
            unsigned long long k2 = skey[t];
            #pragma unroll
            for (int off = 8; off; off >>= 1)
                k2 = max(k2, __shfl_down_sync(0xffffu, k2, off));
            if (t == 0) s_cs = Np - 1 - (int)(unsigned)(k2 & 0xffffffffull);
        }
        __syncthreads();
        cs = s_cs;
    }
}

// ---------------- kNN: 64 blocks x 256 threads, 1 centroid/thread ----------------
__global__ void knnk(const float* __restrict__ p, const float* __restrict__ cntrd) {
    __shared__ float shp[Np*3];
    __shared__ float sp2[Np];
    __shared__ double s9[9];
    int t = threadIdx.x;
    int gc = blockIdx.x*256 + t;           // global centroid
    int b = blockIdx.x >> 1;               // 2 blocks per batch
    for (int i = t; i < Np*3; i += 256) shp[i] = p[b*Np*3 + i];
    if (t < 9) s9[t] = 0.0;
    __syncthreads();
    for (int n = t; n < Np; n += 256) {
        float x = shp[n*3], y = shp[n*3+1], z = shp[n*3+2];
        sp2[n] = __fadd_rn(__fadd_rn(__fmul_rn(x,x), __fmul_rn(y,y)), __fmul_rn(z,z));
    }
    __syncthreads();

    float cx = cntrd[gc*3+0], cy = cntrd[gc*3+1], cz = cntrd[gc*3+2];
    float c2 = __fadd_rn(__fadd_rn(__fmul_rn(cx,cx), __fmul_rn(cy,cy)), __fmul_rn(cz,cz));

    float hd[KN]; int hi[KN];
    #pragma unroll
    for (int k = 0; k < KN; k++) { hd[k] = 3.4e38f; hi[k] = 0; }

    for (int n = 0; n < Np; n++) {
        float dot = __fadd_rn(__fadd_rn(__fmul_rn(cx, shp[n*3]),
                                        __fmul_rn(cy, shp[n*3+1])),
                              __fmul_rn(cz, shp[n*3+2]));
        float d2 = __fadd_rn(__fadd_rn(c2, sp2[n]), -__fmul_rn(2.0f, dot));
        if (d2 < hd[KN-1]) {
            hd[KN-1] = d2; hi[KN-1] = n;
            #pragma unroll
            for (int j = KN-1; j > 0; --j) {
                bool sw = hd[j] < hd[j-1];
                float td = hd[j]; int ti = hi[j];
                float tdm = hd[j-1]; int tim = hi[j-1];
                hd[j]   = sw ? tdm : td;   hi[j]   = sw ? tim : ti;
                hd[j-1] = sw ? td  : tdm;  hi[j-1] = sw ? ti  : tim;
            }
        }
    }
    double sx=0, sy=0, sz=0, sxx=0, syy=0, szz=0, sxy=0, sxz=0, syz=0;
    #pragma unroll
    for (int k = 0; k < KN; k++) {
        int n = hi[k];
        float x = shp[n*3], y = shp[n*3+1], z = shp[n*3+2];
        g_grouped[(gc*KN + k)*3 + 0] = x;
        g_grouped[(gc*KN + k)*3 + 1] = y;
        g_grouped[(gc*KN + k)*3 + 2] = z;
        sx += x; sy += y; sz += z;
        sxx += (double)x*x; syy += (double)y*y; szz += (double)z*z;
        sxy += (double)x*y; sxz += (double)x*z; syz += (double)y*z;
    }
    atomicAdd(&s9[0], sx);  atomicAdd(&s9[1], sy);  atomicAdd(&s9[2], sz);
    atomicAdd(&s9[3], sxx); atomicAdd(&s9[4], syy); atomicAdd(&s9[5], szz);
    atomicAdd(&s9[6], sxy); atomicAdd(&s9[7], sxz); atomicAdd(&s9[8], syz);
    __syncthreads();
    if (t < 9) atomicAdd(&g_sum9[t], s9[t]);
}

// ---------------- BN1 affine from analytic moments ----------------
__global__ void bn1k(const float* __restrict__ b2, const float* __restrict__ g1,
                     const float* __restrict__ b1) {
    int o = threadIdx.x;
    if (o >= 256) return;
    double inv = 1.0 / (double)JJ;
    double Ex = g_sum9[0]*inv, Ey = g_sum9[1]*inv, Ez = g_sum9[2]*inv;
    double Mxx = g_sum9[3]*inv, Myy = g_sum9[4]*inv, Mzz = g_sum9[5]*inv;
    double Mxy = g_sum9[6]*inv, Mxz = g_sum9[7]*inv, Myz = g_sum9[8]*inv;
    double w0 = g_Weff2[o*3], w1v = g_Weff2[o*3+1], w2v = g_Weff2[o*3+2];
    double bo = b2[o];
    double wEg = w0*Ex + w1v*Ey + w2v*Ez;
    double m = wEg + bo;
    double Ex2 = w0*w0*Mxx + w1v*w1v*Myy + w2v*w2v*Mzz
               + 2.0*(w0*w1v*Mxy + w0*w2v*Mxz + w1v*w2v*Myz)
               + 2.0*bo*wEg + bo*bo;
    double var = Ex2 - m*m;
    double s = (double)g1[o] / sqrt(var + EPSf);
    g_A1[o*3+0] = (float)(s*w0);
    g_A1[o*3+1] = (float)(s*w1v);
    g_A1[o*3+2] = (float)(s*w2v);
    g_c1v[o] = (float)((double)b1[o] + s*(bo - m));
}

// ---------------- h generation + pooled ----------------
__global__ void hgenk() {
    __shared__ float gsh[48];
    int t = threadIdx.x;
    float a0 = g_A1[t*3], a1 = g_A1[t*3+1], a2 = g_A1[t*3+2], c1 = g_c1v[t];
    for (int it = 0; it < 8; it++) {
        int tile = blockIdx.x*8 + it;
        __syncthreads();
        if (t < 48) gsh[t] = g_grouped[tile*48 + t];
        __syncthreads();
        float hv[KN];
        float mx = 0.0f;
        #pragma unroll
        for (int k = 0; k < KN; k++) {
            float x = gsh[k*3], y = gsh[k*3+1], z = gsh[k*3+2];
            float h = fmaxf(0.0f, fmaf(a0, x, fmaf(a1, y, fmaf(a2, z, c1))));
            hv[k] = h;
            mx = fmaxf(mx, h);
        }
        float* dst = &g_H[(size_t)t*JJ + (size_t)tile*KN];
        #pragma unroll
        for (int q = 0; q < 4; q++)
            *(float4*)(dst + 4*q) = make_float4(hv[4*q], hv[4*q+1], hv[4*q+2], hv[4*q+3]);
        g_P[(size_t)t*NT + tile] = mx;
    }
}

// ---------------- generic 128x128 tiled GEMM, fused epilogues ----------------
// MODE 0: C = AT^T B                      (Zp)
// MODE 1: C = AT^T B + zp[o][j>>4], stats (Z, BN3)
// MODE 2: C = AT^T relu(a*B+d), stats     (Z4, BN4)
template<int MODE>
__global__ __launch_bounds__(256, 2)
void gemm128(const float* __restrict__ AT, int M,
             const float* __restrict__ Bm, int Nn,
             float* __restrict__ Cm, int Kdim,
             const float* __restrict__ zp,
             const float* __restrict__ ta, const float* __restrict__ tb,
             double* __restrict__ sumo, double* __restrict__ sqo) {
    __shared__ float As[2][8][128];
    __shared__ float Bs[2][8][128];
    __shared__ double shs[128], shq[128];
    int t = threadIdx.x;
    int tx = t & 15, ty = t >> 4;
    int o0 = blockIdx.y * 128, j0 = blockIdx.x * 128;
    int lk = t >> 5;            // 0..7
    int lo = (t & 31) * 4;      // 0..124

    float acc[8][8];
    #pragma unroll
    for (int r = 0; r < 8; r++)
        #pragma unroll
        for (int c = 0; c < 8; c++) acc[r][c] = 0.0f;

    // stage 0
    {
        float4 va = *(const float4*)&AT[(size_t)lk*M + o0 + lo];
        float4 vb = *(const float4*)&Bm[(size_t)lk*Nn + j0 + lo];
        if (MODE == 2) {
            float a = ta[lk], d = tb[lk];
            vb.x = fmaxf(0.0f, fmaf(vb.x, a, d));
            vb.y = fmaxf(0.0f, fmaf(vb.y, a, d));
            vb.z = fmaxf(0.0f, fmaf(vb.z, a, d));
            vb.w = fmaxf(0.0f, fmaf(vb.w, a, d));
        }
        *(float4*)&As[0][lk][lo] = va;
        *(float4*)&Bs[0][lk][lo] = vb;
    }
    __syncthreads();

    int cur = 0;
    for (int kc = 0; kc < Kdim; kc += 8) {
        bool has = (kc + 8) < Kdim;
        float4 ra, rb;
        if (has) {
            ra = *(const float4*)&AT[(size_t)(kc + 8 + lk)*M + o0 + lo];
            rb = *(const float4*)&Bm[(size_t)(kc + 8 + lk)*Nn + j0 + lo];
            if (MODE == 2) {
                float a = ta[kc + 8 + lk], d = tb[kc + 8 + lk];
                rb.x = fmaxf(0.0f, fmaf(rb.x, a, d));
                rb.y = fmaxf(0.0f, fmaf(rb.y, a, d));
                rb.z = fmaxf(0.0f, fmaf(rb.z, a, d));
                rb.w = fmaxf(0.0f, fmaf(rb.w, a, d));
            }
        }
        #pragma unroll
        for (int kk = 0; kk < 8; kk++) {
            float av[8], bv[8];
            *(float4*)&av[0] = *(float4*)&As[cur][kk][ty*8];
            *(float4*)&av[4] = *(float4*)&As[cur][kk][ty*8 + 4];
            *(float4*)&bv[0] = *(float4*)&Bs[cur][kk][tx*8];
            *(float4*)&bv[4] = *(float4*)&Bs[cur][kk][tx*8 + 4];
            #pragma unroll
            for (int r = 0; r < 8; r++)
                #pragma unroll
                for (int c = 0; c < 8; c++)
                    acc[r][c] = fmaf(av[r], bv[c], acc[r][c]);
        }
        if (has) {
            *(float4*)&As[cur^1][lk][lo] = ra;
            *(float4*)&Bs[cur^1][lk][lo] = rb;
        }
        __syncthreads();
        cur ^= 1;
    }

    if (MODE == 0) {
        #pragma unroll
        for (int r = 0; r < 8; r++) {
            int o = o0 + ty*8 + r;
            float* cp = &Cm[(size_t)o*Nn + j0 + tx*8];
            *(float4*)cp       = make_float4(acc[r][0], acc[r][1], acc[r][2], acc[r][3]);
            *(float4*)(cp + 4) = make_float4(acc[r][4], acc[r][5], acc[r][6], acc[r][7]);
        }
    } else {
        double rs[8], rq[8];
        #pragma unroll
        for (int r = 0; r < 8; r++) { rs[r] = 0.0; rq[r] = 0.0; }
        #pragma unroll
        for (int r = 0; r < 8; r++) {
            int o = o0 + ty*8 + r;
            float vals[8];
            #pragma unroll
            for (int c = 0; c < 8; c++) {
                int j = j0 + tx*8 + c;
                float v = acc[r][c];
                if (MODE == 1) v += zp[(size_t)o*NT + (j >> 4)];
                vals[c] = v;
                rs[r] += (double)v;
                rq[r] += (double)v * (double)v;
            }
            float* cp = &Cm[(size_t)o*Nn + j0 + tx*8];
            *(float4*)cp       = make_float4(vals[0], vals[1], vals[2], vals[3]);
            *(float4*)(cp + 4) = make_float4(vals[4], vals[5], vals[6], vals[7]);
        }
        if (t < 128) { shs[t] = 0.0; shq[t] = 0.0; }
        __syncthreads();
        #pragma unroll
        for (int r = 0; r < 8; r++) {
            atomicAdd(&shs[ty*8 + r], rs[r]);
            atomicAdd(&shq[ty*8 + r], rq[r]);
        }
        __syncthreads();
        if (t < 128) {
            atomicAdd(&sumo[o0 + t], shs[t]);
            atomicAdd(&sqo[o0 + t], shq[t]);
        }
    }
}

// ---------------- BN affine param kernels ----------------
__global__ void bn3aff(const float* __restrict__ g, const float* __restrict__ b) {
    int c = threadIdx.x;
    if (c >= 512) return;
    double inv = 1.0 / (double)JJ;
    double m = g_bn3sum[c]*inv;
    double var = g_bn3sq[c]*inv - m*m;
    float a = (float)((double)g[c] / sqrt(var + EPSf));
    g_a3[c] = a;
    g_d3[c] = b[c] - (float)m * a;
}
__global__ void bn4aff(const float* __restrict__ g, const float* __restrict__ b) {
    int c = threadIdx.x;
    if (c >= 256) return;
    double inv = 1.0 / (double)JJ;
    double m = g_bn4sum[c]*inv;
    double var = g_bn4sq[c]*inv - m*m;
    float a = (float)((double)g[c] / sqrt(var + EPSf));
    g_a4[c] = a;
    g_d4[c] = b[c] - (float)m * a;
}

// ---------------- final: BN4 + ReLU + max over k -> feat ----------------
__global__ void finalk(float* __restrict__ out) {
    int id = blockIdx.x*256 + threadIdx.x;            // b*131072 + o*512 + ns
    int b = id >> 17;
    int o = (id >> 9) & 255;
    int ns = id & 511;
    float a = g_a4[o], d = g_d4[o];
    const float4* zr = (const float4*)&g_Z4[(size_t)o*JJ + (size_t)((b << 9) | ns)*KN];
    float mx = 0.0f;
    #pragma unroll
    for (int q = 0; q < 4; q++) {
        float4 v = zr[q];
        mx = fmaxf(mx, fmaxf(0.0f, fmaf(v.x, a, d)));
        mx = fmaxf(mx, fmaxf(0.0f, fmaf(v.y, a, d)));
        mx = fmaxf(mx, fmaxf(0.0f, fmaf(v.z, a, d)));
        mx = fmaxf(mx, fmaxf(0.0f, fmaf(v.w, a, d)));
    }
    out[Bb*NSd*3 + id] = mx;
}

// ---------------- launch ----------------
extern "C" void kernel_launch(void* const* d_in, const int* in_sizes, int n_in,
                              void* d_out, int out_size) {
    const float* p    = (const float*)d_in[0];
    const float* w1   = (const float*)d_in[1];
    const float* w2   = (const float*)d_in[2];
    const float* b2   = (const float*)d_in[3];
    const float* bn1g = (const float*)d_in[4];
    const float* bn1b = (const float*)d_in[5];
    const float* w3   = (const float*)d_in[6];
    const float* bn3g = (const float*)d_in[7];
    const float* bn3b = (const float*)d_in[8];
    const float* w4   = (const float*)d_in[9];
    const float* bn4g = (const float*)d_in[10];
    const float* bn4b = (const float*)d_in[11];
    float* out = (float*)d_out;

    float*  dH;  cudaGetSymbolAddress((void**)&dH,  g_H);
    float*  dP;  cudaGetSymbolAddress((void**)&dP,  g_P);
    float*  dZp; cudaGetSymbolAddress((void**)&dZp, g_Zp);
    float*  dZ;  cudaGetSymbolAddress((void**)&dZ,  g_Z);
    float*  dZ4; cudaGetSymbolAddress((void**)&dZ4, g_Z4);
    float*  dW3T; cudaGetSymbolAddress((void**)&dW3T, g_W3T);
    float*  dW4T; cudaGetSymbolAddress((void**)&dW4T, g_W4T);
    float*  da3; cudaGetSymbolAddress((void**)&da3, g_a3);
    float*  dd3; cudaGetSymbolAddress((void**)&dd3, g_d3);
    double* ds3; cudaGetSymbolAddress((void**)&ds3, g_bn3sum);
    double* dq3; cudaGetSymbolAddress((void**)&dq3, g_bn3sq);
    double* ds4; cudaGetSymbolAddress((void**)&ds4, g_bn4sum);
    double* dq4; cudaGetSymbolAddress((void**)&dq4, g_bn4sq);

    zerok<<<1, 512>>>();
    precompk<<<1, 512>>>(w1, w2, w3, w4);
    fpsk<<<32, 512>>>(p, out);                 // writes cntrd to out[0:49152]
    knnk<<<64, 256>>>(p, out);
    bn1k<<<1, 256>>>(b2, bn1g, bn1b);
    hgenk<<<NT/8, 256>>>();
    // Zp = W3a @ pooled : M=512, K=256, N=16384
    gemm128<0><<<dim3(NT/128, 4), 256>>>(dW3T, 512, dP, NT, dZp, 256,
                                         nullptr, nullptr, nullptr, nullptr, nullptr);
    // Z = W3b @ H + zp, BN3 stats : M=512, K=256, N=262144
    gemm128<1><<<dim3(JJ/128, 4), 256>>>(dW3T + 256*512, 512, dH, JJ, dZ, 256,
                                         dZp, nullptr, nullptr, ds3, dq3);
    bn3aff<<<1, 512>>>(bn3g, bn3b);
    // Z4 = W4 @ relu(bn3(Z)), BN4 stats : M=256, K=512, N=262144
    gemm128<2><<<dim3(JJ/128, 2), 256>>>(dW4T, 256, dZ, JJ, dZ4, 512,
                                         nullptr, da3, dd3, ds4, dq4);
    bn4aff<<<1, 256>>>(bn4g, bn4b);
    finalk<<<Bb*256*NSd/256, 256>>>(out);
}

// round 6
// speedup vs baseline: 1.0008x; 1.0008x over previous
#include <cuda_runtime.h>
#include <cstdint>

// Problem constants
#define Bb 32
#define Np 2048
#define NSd 512
#define KN 16
#define NT (Bb*NSd)          // 16384 tiles (b,ns)
#define JJ (NT*KN)           // 262144 columns
#define EPSf 1e-5

// ---------------- scratch (static __device__, no allocs) ----------------
__device__ float  g_grouped[NT*KN*3];          // 3 MB  grouped coords [tile][k][3]
__device__ double g_sum9[9];                   // Sg(3) + Sgg(6)
__device__ float  g_Weff2[256*3];
__device__ float  g_W3T[512*512];              // [c][o]
__device__ float  g_W4T[512*256];              // [c][o]
__device__ float  g_A1[256*3];
__device__ float  g_c1v[256];
__device__ float  g_H [256u*JJ];               // 268 MB  h (post BN1+ReLU) [c][j]
__device__ float  g_P [256u*NT];               // pooled [c][tile]
__device__ float  g_Zp[512u*NT];               // W3a @ pooled [o][tile]
__device__ float  g_Z [512u*JJ];               // 537 MB
__device__ float  g_Z4[256u*JJ];               // 268 MB
__device__ double g_bn3sum[512], g_bn3sq[512], g_bn4sum[256], g_bn4sq[256];
__device__ float  g_a3[512], g_d3[512], g_a4[256], g_d4[256];

// ---------------- zero accumulators (graph replays!) ----------------
__global__ void zerok() {
    int t = threadIdx.x;
    if (t < 9) g_sum9[t] = 0.0;
    for (int i = t; i < 512; i += blockDim.x) { g_bn3sum[i] = 0.0; g_bn3sq[i] = 0.0; }
    for (int i = t; i < 256; i += blockDim.x) { g_bn4sum[i] = 0.0; g_bn4sq[i] = 0.0; }
}

// ---------------- precompute Weff2 = W2 @ (w1[:, :3]+w1[:,3:]), transposes ----------------
__global__ void precompk(const float* __restrict__ w1, const float* __restrict__ w2,
                         const float* __restrict__ w3, const float* __restrict__ w4) {
    int t = threadIdx.x;
    if (t < 256) {
        double s0 = 0.0, s1 = 0.0, s2 = 0.0;
        for (int i = 0; i < 256; i++) {
            double wi = (double)w2[t*256 + i];
            s0 += wi * ((double)w1[i*6+0] + (double)w1[i*6+3]);
            s1 += wi * ((double)w1[i*6+1] + (double)w1[i*6+4]);
            s2 += wi * ((double)w1[i*6+2] + (double)w1[i*6+5]);
        }
        g_Weff2[t*3+0] = (float)s0; g_Weff2[t*3+1] = (float)s1; g_Weff2[t*3+2] = (float)s2;
    }
    for (int idx = t; idx < 512*512; idx += blockDim.x) {
        int o = idx >> 9, c = idx & 511;
        g_W3T[c*512 + o] = w3[idx];
    }
    for (int idx = t; idx < 256*512; idx += blockDim.x) {
        int o = idx >> 9, c = idx & 511;
        g_W4T[c*256 + o] = w4[idx];
    }
}

// ---------------- FPS: 32 blocks (one per batch), 512 threads, 4 pts/thread ----------------
__global__ void fpsk(const float* __restrict__ p, float* __restrict__ outc) {
    __shared__ float sp[Np*3];
    __shared__ unsigned long long skey[16];
    __shared__ int s_cs;
    int b = blockIdx.x, t = threadIdx.x;
    for (int i = t; i < Np*3; i += 512) sp[i] = p[b*Np*3 + i];
    __syncthreads();

    float px[4], py[4], pz[4], dist[4];
    #pragma unroll
    for (int i = 0; i < 4; i++) {
        int n = t + 512*i;
        px[i] = sp[n*3+0]; py[i] = sp[n*3+1]; pz[i] = sp[n*3+2];
        dist[i] = 1e10f;
    }
    int lane = t & 31, wid = t >> 5;
    int cs = 0;
    for (int s = 0; s < NSd; s++) {
        if (t == 0) {
            outc[(b*NSd + s)*3 + 0] = sp[cs*3+0];
            outc[(b*NSd + s)*3 + 1] = sp[cs*3+1];
            outc[(b*NSd + s)*3 + 2] = sp[cs*3+2];
        }
        float cx = sp[cs*3+0], cy = sp[cs*3+1], cz = sp[cs*3+2];
        unsigned long long best = 0ull;
        #pragma unroll
        for (int i = 0; i < 4; i++) {
            float dx = __fadd_rn(px[i], -cx);
            float dy = __fadd_rn(py[i], -cy);
            float dz = __fadd_rn(pz[i], -cz);
            float d = __fadd_rn(__fadd_rn(__fmul_rn(dx,dx), __fmul_rn(dy,dy)), __fmul_rn(dz,dz));
            dist[i] = fminf(dist[i], d);
            unsigned long long key = ((unsigned long long)__float_as_uint(dist[i]) << 32)
                                   | (unsigned)(Np - 1 - (t + 512*i));
            best = max(best, key);
        }
        #pragma unroll
        for (int off = 16; off; off >>= 1)
            best = max(best, __shfl_down_sync(0xffffffffu, best, off));
        if (lane == 0) skey[wid] = best;
        __syncthreads();
        if (t < 16) {
            unsigned long long k2 = skey[t];
            #pragma unroll
            for (int off = 8; off; off >>= 1)
                k2 = max(k2, __shfl_down_sync(0xffffu, k2, off));
            if (t == 0) s_cs = Np - 1 - (int)(unsigned)(k2 & 0xffffffffull);
        }
        __syncthreads();
        cs = s_cs;
    }
}

// ---------------- kNN: 64 blocks x 256 threads, 1 centroid/thread ----------------
__global__ void knnk(const float* __restrict__ p, const float* __restrict__ cntrd) {
    __shared__ float shp[Np*3];
    __shared__ float sp2[Np];
    __shared__ double s9[9];
    int t = threadIdx.x;
    int gc = blockIdx.x*256 + t;           // global centroid
    int b = blockIdx.x >> 1;               // 2 blocks per batch
    for (int i = t; i < Np*3; i += 256) shp[i] = p[b*Np*3 + i];
    if (t < 9) s9[t] = 0.0;
    __syncthreads();
    for (int n = t; n < Np; n += 256) {
        float x = shp[n*3], y = shp[n*3+1], z = shp[n*3+2];
        sp2[n] = __fadd_rn(__fadd_rn(__fmul_rn(x,x), __fmul_rn(y,y)), __fmul_rn(z,z));
    }
    __syncthreads();

    float cx = cntrd[gc*3+0], cy = cntrd[gc*3+1], cz = cntrd[gc*3+2];
    float c2 = __fadd_rn(__fadd_rn(__fmul_rn(cx,cx), __fmul_rn(cy,cy)), __fmul_rn(cz,cz));

    float hd[KN]; int hi[KN];
    #pragma unroll
    for (int k = 0; k < KN; k++) { hd[k] = 3.4e38f; hi[k] = 0; }

    for (int n = 0; n < Np; n++) {
        float dot = __fadd_rn(__fadd_rn(__fmul_rn(cx, shp[n*3]),
                                        __fmul_rn(cy, shp[n*3+1])),
                              __fmul_rn(cz, shp[n*3+2]));
        float d2 = __fadd_rn(__fadd_rn(c2, sp2[n]), -__fmul_rn(2.0f, dot));
        if (d2 < hd[KN-1]) {
            hd[KN-1] = d2; hi[KN-1] = n;
            #pragma unroll
            for (int j = KN-1; j > 0; --j) {
                bool sw = hd[j] < hd[j-1];
                float td = hd[j]; int ti = hi[j];
                float tdm = hd[j-1]; int tim = hi[j-1];
                hd[j]   = sw ? tdm : td;   hi[j]   = sw ? tim : ti;
                hd[j-1] = sw ? td  : tdm;  hi[j-1] = sw ? ti  : tim;
            }
        }
    }
    double sx=0, sy=0, sz=0, sxx=0, syy=0, szz=0, sxy=0, sxz=0, syz=0;
    #pragma unroll
    for (int k = 0; k < KN; k++) {
        int n = hi[k];
        float x = shp[n*3], y = shp[n*3+1], z = shp[n*3+2];
        g_grouped[(gc*KN + k)*3 + 0] = x;
        g_grouped[(gc*KN + k)*3 + 1] = y;
        g_grouped[(gc*KN + k)*3 + 2] = z;
        sx += x; sy += y; sz += z;
        sxx += (double)x*x; syy += (double)y*y; szz += (double)z*z;
        sxy += (double)x*y; sxz += (double)x*z; syz += (double)y*z;
    }
    atomicAdd(&s9[0], sx);  atomicAdd(&s9[1], sy);  atomicAdd(&s9[2], sz);
    atomicAdd(&s9[3], sxx); atomicAdd(&s9[4], syy); atomicAdd(&s9[5], szz);
    atomicAdd(&s9[6], sxy); atomicAdd(&s9[7], sxz); atomicAdd(&s9[8], syz);
    __syncthreads();
    if (t < 9) atomicAdd(&g_sum9[t], s9[t]);
}

// ---------------- BN1 affine from analytic moments ----------------
__global__ void bn1k(const float* __restrict__ b2, const float* __restrict__ g1,
                     const float* __restrict__ b1) {
    int o = threadIdx.x;
    if (o >= 256) return;
    double inv = 1.0 / (double)JJ;
    double Ex = g_sum9[0]*inv, Ey = g_sum9[1]*inv, Ez = g_sum9[2]*inv;
    double Mxx = g_sum9[3]*inv, Myy = g_sum9[4]*inv, Mzz = g_sum9[5]*inv;
    double Mxy = g_sum9[6]*inv, Mxz = g_sum9[7]*inv, Myz = g_sum9[8]*inv;
    double w0 = g_Weff2[o*3], w1v = g_Weff2[o*3+1], w2v = g_Weff2[o*3+2];
    double bo = b2[o];
    double wEg = w0*Ex + w1v*Ey + w2v*Ez;
    double m = wEg + bo;
    double Ex2 = w0*w0*Mxx + w1v*w1v*Myy + w2v*w2v*Mzz
               + 2.0*(w0*w1v*Mxy + w0*w2v*Mxz + w1v*w2v*Myz)
               + 2.0*bo*wEg + bo*bo;
    double var = Ex2 - m*m;
    double s = (double)g1[o] / sqrt(var + EPSf);
    g_A1[o*3+0] = (float)(s*w0);
    g_A1[o*3+1] = (float)(s*w1v);
    g_A1[o*3+2] = (float)(s*w2v);
    g_c1v[o] = (float)((double)b1[o] + s*(bo - m));
}

// ---------------- h generation + pooled ----------------
__global__ void hgenk() {
    __shared__ float gsh[48];
    int t = threadIdx.x;
    float a0 = g_A1[t*3], a1 = g_A1[t*3+1], a2 = g_A1[t*3+2], c1 = g_c1v[t];
    for (int it = 0; it < 8; it++) {
        int tile = blockIdx.x*8 + it;
        __syncthreads();
        if (t < 48) gsh[t] = g_grouped[tile*48 + t];
        __syncthreads();
        float hv[KN];
        float mx = 0.0f;
        #pragma unroll
        for (int k = 0; k < KN; k++) {
            float x = gsh[k*3], y = gsh[k*3+1], z = gsh[k*3+2];
            float h = fmaxf(0.0f, fmaf(a0, x, fmaf(a1, y, fmaf(a2, z, c1))));
            hv[k] = h;
            mx = fmaxf(mx, h);
        }
        float* dst = &g_H[(size_t)t*JJ + (size_t)tile*KN];
        #pragma unroll
        for (int q = 0; q < 4; q++)
            *(float4*)(dst + 4*q) = make_float4(hv[4*q], hv[4*q+1], hv[4*q+2], hv[4*q+3]);
        g_P[(size_t)t*NT + tile] = mx;
    }
}

// ---------------- generic 128x128 tiled GEMM, fused epilogues ----------------
// MODE 0: C = AT^T B                      (Zp)
// MODE 1: C = AT^T B + zp[o][j>>4], stats (Z, BN3)
// MODE 2: C = AT^T relu(a*B+d), stats     (Z4, BN4)
template<int MODE>
__global__ __launch_bounds__(256, 2)
void gemm128(const float* __restrict__ AT, int M,
             const float* __restrict__ Bm, int Nn,
             float* __restrict__ Cm, int Kdim,
             const float* __restrict__ zp,
             const float* __restrict__ ta, const float* __restrict__ tb,
             double* __restrict__ sumo, double* __restrict__ sqo) {
    __shared__ float As[2][8][128];
    __shared__ float Bs[2][8][128];
    __shared__ double shs[128], shq[128];
    int t = threadIdx.x;
    int tx = t & 15, ty = t >> 4;
    int o0 = blockIdx.y * 128, j0 = blockIdx.x * 128;
    int lk = t >> 5;            // 0..7
    int lo = (t & 31) * 4;      // 0..124

    float acc[8][8];
    #pragma unroll
    for (int r = 0; r < 8; r++)
        #pragma unroll
        for (int c = 0; c < 8; c++) acc[r][c] = 0.0f;

    // stage 0
    {
        float4 va = *(const float4*)&AT[(size_t)lk*M + o0 + lo];
        float4 vb = *(const float4*)&Bm[(size_t)lk*Nn + j0 + lo];
        if (MODE == 2) {
            float a = ta[lk], d = tb[lk];
            vb.x = fmaxf(0.0f, fmaf(vb.x, a, d));
            vb.y = fmaxf(0.0f, fmaf(vb.y, a, d));
            vb.z = fmaxf(0.0f, fmaf(vb.z, a, d));
            vb.w = fmaxf(0.0f, fmaf(vb.w, a, d));
        }
        *(float4*)&As[0][lk][lo] = va;
        *(float4*)&Bs[0][lk][lo] = vb;
    }
    __syncthreads();

    int cur = 0;
    for (int kc = 0; kc < Kdim; kc += 8) {
        bool has = (kc + 8) < Kdim;
        float4 ra, rb;
        if (has) {
            ra = *(const float4*)&AT[(size_t)(kc + 8 + lk)*M + o0 + lo];
            rb = *(const float4*)&Bm[(size_t)(kc + 8 + lk)*Nn + j0 + lo];
            if (MODE == 2) {
                float a = ta[kc + 8 + lk], d = tb[kc + 8 + lk];
                rb.x = fmaxf(0.0f, fmaf(rb.x, a, d));
                rb.y = fmaxf(0.0f, fmaf(rb.y, a, d));
                rb.z = fmaxf(0.0f, fmaf(rb.z, a, d));
                rb.w = fmaxf(0.0f, fmaf(rb.w, a, d));
            }
        }
        #pragma unroll
        for (int kk = 0; kk < 8; kk++) {
            float av[8], bv[8];
            *(float4*)&av[0] = *(float4*)&As[cur][kk][ty*8];
            *(float4*)&av[4] = *(float4*)&As[cur][kk][ty*8 + 4];
            *(float4*)&bv[0] = *(float4*)&Bs[cur][kk][tx*8];
            *(float4*)&bv[4] = *(float4*)&Bs[cur][kk][tx*8 + 4];
            #pragma unroll
            for (int r = 0; r < 8; r++)
                #pragma unroll
                for (int c = 0; c < 8; c++)
                    acc[r][c] = fmaf(av[r], bv[c], acc[r][c]);
        }
        if (has) {
            *(float4*)&As[cur^1][lk][lo] = ra;
            *(float4*)&Bs[cur^1][lk][lo] = rb;
        }
        __syncthreads();
        cur ^= 1;
    }

    if (MODE == 0) {
        #pragma unroll
        for (int r = 0; r < 8; r++) {
            int o = o0 + ty*8 + r;
            float* cp = &Cm[(size_t)o*Nn + j0 + tx*8];
            *(float4*)cp       = make_float4(acc[r][0], acc[r][1], acc[r][2], acc[r][3]);
            *(float4*)(cp + 4) = make_float4(acc[r][4], acc[r][5], acc[r][6], acc[r][7]);
        }
    } else {
        double rs[8], rq[8];
        #pragma unroll
        for (int r = 0; r < 8; r++) { rs[r] = 0.0; rq[r] = 0.0; }
        #pragma unroll
        for (int r = 0; r < 8; r++) {
            int o = o0 + ty*8 + r;
            float vals[8];
            #pragma unroll
            for (int c = 0; c < 8; c++) {
                int j = j0 + tx*8 + c;
                float v = acc[r][c];
                if (MODE == 1) v += zp[(size_t)o*NT + (j >> 4)];
                vals[c] = v;
                rs[r] += (double)v;
                rq[r] += (double)v * (double)v;
            }
            float* cp = &Cm[(size_t)o*Nn + j0 + tx*8];
            *(float4*)cp       = make_float4(vals[0], vals[1], vals[2], vals[3]);
            *(float4*)(cp + 4) = make_float4(vals[4], vals[5], vals[6], vals[7]);
        }
        if (t < 128) { shs[t] = 0.0; shq[t] = 0.0; }
        __syncthreads();
        #pragma unroll
        for (int r = 0; r < 8; r++) {
            atomicAdd(&shs[ty*8 + r], rs[r]);
            atomicAdd(&shq[ty*8 + r], rq[r]);
        }
        __syncthreads();
        if (t < 128) {
            atomicAdd(&sumo[o0 + t], shs[t]);
            atomicAdd(&sqo[o0 + t], shq[t]);
        }
    }
}

// ---------------- BN affine param kernels ----------------
__global__ void bn3aff(const float* __restrict__ g, const float* __restrict__ b) {
    int c = threadIdx.x;
    if (c >= 512) return;
    double inv = 1.0 / (double)JJ;
    double m = g_bn3sum[c]*inv;
    double var = g_bn3sq[c]*inv - m*m;
    float a = (float)((double)g[c] / sqrt(var + EPSf));
    g_a3[c] = a;
    g_d3[c] = b[c] - (float)m * a;
}
__global__ void bn4aff(const float* __restrict__ g, const float* __restrict__ b) {
    int c = threadIdx.x;
    if (c >= 256) return;
    double inv = 1.0 / (double)JJ;
    double m = g_bn4sum[c]*inv;
    double var = g_bn4sq[c]*inv - m*m;
    float a = (float)((double)g[c] / sqrt(var + EPSf));
    g_a4[c] = a;
    g_d4[c] = b[c] - (float)m * a;
}

// ---------------- final: BN4 + ReLU + max over k -> feat ----------------
__global__ void finalk(float* __restrict__ out) {
    int id = blockIdx.x*256 + threadIdx.x;            // b*131072 + o*512 + ns
    int b = id >> 17;
    int o = (id >> 9) & 255;
    int ns = id & 511;
    float a = g_a4[o], d = g_d4[o];
    const float4* zr = (const float4*)&g_Z4[(size_t)o*JJ + (size_t)((b << 9) | ns)*KN];
    float mx = 0.0f;
    #pragma unroll
    for (int q = 0; q < 4; q++) {
        float4 v = zr[q];
        mx = fmaxf(mx, fmaxf(0.0f, fmaf(v.x, a, d)));
        mx = fmaxf(mx, fmaxf(0.0f, fmaf(v.y, a, d)));
        mx = fmaxf(mx, fmaxf(0.0f, fmaf(v.z, a, d)));
        mx = fmaxf(mx, fmaxf(0.0f, fmaf(v.w, a, d)));
    }
    out[Bb*NSd*3 + id] = mx;
}

// ---------------- launch ----------------
extern "C" void kernel_launch(void* const* d_in, const int* in_sizes, int n_in,
                              void* d_out, int out_size) {
    const float* p    = (const float*)d_in[0];
    const float* w1   = (const float*)d_in[1];
    const float* w2   = (const float*)d_in[2];
    const float* b2   = (const float*)d_in[3];
    const float* bn1g = (const float*)d_in[4];
    const float* bn1b = (const float*)d_in[5];
    const float* w3   = (const float*)d_in[6];
    const float* bn3g = (const float*)d_in[7];
    const float* bn3b = (const float*)d_in[8];
    const float* w4   = (const float*)d_in[9];
    const float* bn4g = (const float*)d_in[10];
    const float* bn4b = (const float*)d_in[11];
    float* out = (float*)d_out;

    float*  dH;  cudaGetSymbolAddress((void**)&dH,  g_H);
    float*  dP;  cudaGetSymbolAddress((void**)&dP,  g_P);
    float*  dZp; cudaGetSymbolAddress((void**)&dZp, g_Zp);
    float*  dZ;  cudaGetSymbolAddress((void**)&dZ,  g_Z);
    float*  dZ4; cudaGetSymbolAddress((void**)&dZ4, g_Z4);
    float*  dW3T; cudaGetSymbolAddress((void**)&dW3T, g_W3T);
    float*  dW4T; cudaGetSymbolAddress((void**)&dW4T, g_W4T);
    float*  da3; cudaGetSymbolAddress((void**)&da3, g_a3);
    float*  dd3; cudaGetSymbolAddress((void**)&dd3, g_d3);
    double* ds3; cudaGetSymbolAddress((void**)&ds3, g_bn3sum);
    double* dq3; cudaGetSymbolAddress((void**)&dq3, g_bn3sq);
    double* ds4; cudaGetSymbolAddress((void**)&ds4, g_bn4sum);
    double* dq4; cudaGetSymbolAddress((void**)&dq4, g_bn4sq);

    zerok<<<1, 512>>>();
    precompk<<<1, 512>>>(w1, w2, w3, w4);
    fpsk<<<32, 512>>>(p, out);                 // writes cntrd to out[0:49152]
    knnk<<<64, 256>>>(p, out);
    bn1k<<<1, 256>>>(b2, bn1g, bn1b);
    hgenk<<<NT/8, 256>>>();
    // Zp = W3a @ pooled : M=512, K=256, N=16384
    gemm128<0><<<dim3(NT/128, 4), 256>>>(dW3T, 512, dP, NT, dZp, 256,
                                         nullptr, nullptr, nullptr, nullptr, nullptr);
    // Z = W3b @ H + zp, BN3 stats : M=512, K=256, N=262144
    gemm128<1><<<dim3(JJ/128, 4), 256>>>(dW3T + 256*512, 512, dH, JJ, dZ, 256,
                                         dZp, nullptr, nullptr, ds3, dq3);
    bn3aff<<<1, 512>>>(bn3g, bn3b);
    // Z4 = W4 @ relu(bn3(Z)), BN4 stats : M=256, K=512, N=262144
    gemm128<2><<<dim3(JJ/128, 2), 256>>>(dW4T, 256, dZ, JJ, dZ4, 512,
                                         nullptr, da3, dd3, ds4, dq4);
    bn4aff<<<1, 256>>>(bn4g, bn4b);
    finalk<<<Bb*256*NSd/256, 256>>>(out);
}

// round 7
// speedup vs baseline: 1.0019x; 1.0012x over previous
#include <cuda_runtime.h>
#include <cstdint>

// Problem constants
#define Bb 32
#define Np 2048
#define NSd 512
#define KN 16
#define NT (Bb*NSd)          // 16384 tiles (b,ns)
#define JJ (NT*KN)           // 262144 columns
#define EPSf 1e-5

// ---------------- scratch (static __device__, no allocs) ----------------
__device__ float  g_grouped[NT*KN*3];          // 3 MB  grouped coords [tile][k][3]
__device__ double g_sum9[9];                   // Sg(3) + Sgg(6)
__device__ float  g_Weff2[256*3];
__device__ float  g_W3T[512*512];              // [c][o]
__device__ float  g_W4T[512*256];              // [c][o]
__device__ float  g_A1[256*3];
__device__ float  g_c1v[256];
__device__ float  g_H [256u*JJ];               // 268 MB  h (post BN1+ReLU) [c][j]
__device__ float  g_P [256u*NT];               // pooled [c][tile]
__device__ float  g_Zp[512u*NT];               // W3a @ pooled [o][tile]
__device__ float  g_Z [512u*JJ];               // 537 MB
__device__ float  g_Z4[256u*JJ];               // 268 MB
__device__ double g_bn3sum[512], g_bn3sq[512], g_bn4sum[256], g_bn4sq[256];
__device__ float  g_a3[512], g_d3[512], g_a4[256], g_d4[256];

// ---------------- zero accumulators (graph replays!) ----------------
__global__ void zerok() {
    int t = threadIdx.x;
    if (t < 9) g_sum9[t] = 0.0;
    for (int i = t; i < 512; i += blockDim.x) { g_bn3sum[i] = 0.0; g_bn3sq[i] = 0.0; }
    for (int i = t; i < 256; i += blockDim.x) { g_bn4sum[i] = 0.0; g_bn4sq[i] = 0.0; }
}

// ---------------- precompute Weff2 = W2 @ (w1[:, :3]+w1[:,3:]), transposes ----------------
__global__ void precompk(const float* __restrict__ w1, const float* __restrict__ w2,
                         const float* __restrict__ w3, const float* __restrict__ w4) {
    int t = threadIdx.x;
    if (t < 256) {
        double s0 = 0.0, s1 = 0.0, s2 = 0.0;
        for (int i = 0; i < 256; i++) {
            double wi = (double)w2[t*256 + i];
            s0 += wi * ((double)w1[i*6+0] + (double)w1[i*6+3]);
            s1 += wi * ((double)w1[i*6+1] + (double)w1[i*6+4]);
            s2 += wi * ((double)w1[i*6+2] + (double)w1[i*6+5]);
        }
        g_Weff2[t*3+0] = (float)s0; g_Weff2[t*3+1] = (float)s1; g_Weff2[t*3+2] = (float)s2;
    }
    for (int idx = t; idx < 512*512; idx += blockDim.x) {
        int o = idx >> 9, c = idx & 511;
        g_W3T[c*512 + o] = w3[idx];
    }
    for (int idx = t; idx < 256*512; idx += blockDim.x) {
        int o = idx >> 9, c = idx & 511;
        g_W4T[c*256 + o] = w4[idx];
    }
}

// ---------------- FPS: 32 blocks (one per batch), 512 threads, 4 pts/thread ----------------
__global__ void fpsk(const float* __restrict__ p, float* __restrict__ outc) {
    __shared__ float sp[Np*3];
    __shared__ unsigned long long skey[16];
    __shared__ int s_cs;
    int b = blockIdx.x, t = threadIdx.x;
    for (int i = t; i < Np*3; i += 512) sp[i] = p[b*Np*3 + i];
    __syncthreads();

    float px[4], py[4], pz[4], dist[4];
    #pragma unroll
    for (int i = 0; i < 4; i++) {
        int n = t + 512*i;
        px[i] = sp[n*3+0]; py[i] = sp[n*3+1]; pz[i] = sp[n*3+2];
        dist[i] = 1e10f;
    }
    int lane = t & 31, wid = t >> 5;
    int cs = 0;
    for (int s = 0; s < NSd; s++) {
        if (t == 0) {
            outc[(b*NSd + s)*3 + 0] = sp[cs*3+0];
            outc[(b*NSd + s)*3 + 1] = sp[cs*3+1];
            outc[(b*NSd + s)*3 + 2] = sp[cs*3+2];
        }
        float cx = sp[cs*3+0], cy = sp[cs*3+1], cz = sp[cs*3+2];
        unsigned long long best = 0ull;
        #pragma unroll
        for (int i = 0; i < 4; i++) {
            float dx = __fadd_rn(px[i], -cx);
            float dy = __fadd_rn(py[i], -cy);
            float dz = __fadd_rn(pz[i], -cz);
            float d = __fadd_rn(__fadd_rn(__fmul_rn(dx,dx), __fmul_rn(dy,dy)), __fmul_rn(dz,dz));
            dist[i] = fminf(dist[i], d);
            unsigned long long key = ((unsigned long long)__float_as_uint(dist[i]) << 32)
                                   | (unsigned)(Np - 1 - (t + 512*i));
            best = max(best, key);
        }
        #pragma unroll
        for (int off = 16; off; off >>= 1)
            best = max(best, __shfl_down_sync(0xffffffffu, best, off));
        if (lane == 0) skey[wid] = best;
        __syncthreads();
        if (t < 16) {
            unsigned long long k2 = skey[t];
            #pragma unroll
            for (int off = 8; off; off >>= 1)
                k2 = max(k2, __shfl_down_sync(0xffffu, k2, off));
            if (t == 0) s_cs = Np - 1 - (int)(unsigned)(k2 & 0xffffffffull);
        }
        __syncthreads();
        cs = s_cs;
    }
}

// ---------------- kNN: 64 blocks x 256 threads, 1 centroid/thread ----------------
__global__ void knnk(const float* __restrict__ p, const float* __restrict__ cntrd) {
    __shared__ float shp[Np*3];
    __shared__ float sp2[Np];
    __shared__ double s9[9];
    int t = threadIdx.x;
    int gc = blockIdx.x*256 + t;           // global centroid
    int b = blockIdx.x >> 1;               // 2 blocks per batch
    for (int i = t; i < Np*3; i += 256) shp[i] = p[b*Np*3 + i];
    if (t < 9) s9[t] = 0.0;
    __syncthreads();
    for (int n = t; n < Np; n += 256) {
        float x = shp[n*3], y = shp[n*3+1], z = shp[n*3+2];
        sp2[n] = __fadd_rn(__fadd_rn(__fmul_rn(x,x), __fmul_rn(y,y)), __fmul_rn(z,z));
    }
    __syncthreads();

    float cx = cntrd[gc*3+0], cy = cntrd[gc*3+1], cz = cntrd[gc*3+2];
    float c2 = __fadd_rn(__fadd_rn(__fmul_rn(cx,cx), __fmul_rn(cy,cy)), __fmul_rn(cz,cz));

    float hd[KN]; int hi[KN];
    #pragma unroll
    for (int k = 0; k < KN; k++) { hd[k] = 3.4e38f; hi[k] = 0; }

    for (int n = 0; n < Np; n++) {
        float dot = __fadd_rn(__fadd_rn(__fmul_rn(cx, shp[n*3]),
                                        __fmul_rn(cy, shp[n*3+1])),
                              __fmul_rn(cz, shp[n*3+2]));
        float d2 = __fadd_rn(__fadd_rn(c2, sp2[n]), -__fmul_rn(2.0f, dot));
        if (d2 < hd[KN-1]) {
            hd[KN-1] = d2; hi[KN-1] = n;
            #pragma unroll
            for (int j = KN-1; j > 0; --j) {
                bool sw = hd[j] < hd[j-1];
                float td = hd[j]; int ti = hi[j];
                float tdm = hd[j-1]; int tim = hi[j-1];
                hd[j]   = sw ? tdm : td;   hi[j]   = sw ? tim : ti;
                hd[j-1] = sw ? td  : tdm;  hi[j-1] = sw ? ti  : tim;
            }
        }
    }
    double sx=0, sy=0, sz=0, sxx=0, syy=0, szz=0, sxy=0, sxz=0, syz=0;
    #pragma unroll
    for (int k = 0; k < KN; k++) {
        int n = hi[k];
        float x = shp[n*3], y = shp[n*3+1], z = shp[n*3+2];
        g_grouped[(gc*KN + k)*3 + 0] = x;
        g_grouped[(gc*KN + k)*3 + 1] = y;
        g_grouped[(gc*KN + k)*3 + 2] = z;
        sx += x; sy += y; sz += z;
        sxx += (double)x*x; syy += (double)y*y; szz += (double)z*z;
        sxy += (double)x*y; sxz += (double)x*z; syz += (double)y*z;
    }
    atomicAdd(&s9[0], sx);  atomicAdd(&s9[1], sy);  atomicAdd(&s9[2], sz);
    atomicAdd(&s9[3], sxx); atomicAdd(&s9[4], syy); atomicAdd(&s9[5], szz);
    atomicAdd(&s9[6], sxy); atomicAdd(&s9[7], sxz); atomicAdd(&s9[8], syz);
    __syncthreads();
    if (t < 9) atomicAdd(&g_sum9[t], s9[t]);
}

// ---------------- BN1 affine from analytic moments ----------------
__global__ void bn1k(const float* __restrict__ b2, const float* __restrict__ g1,
                     const float* __restrict__ b1) {
    int o = threadIdx.x;
    if (o >= 256) return;
    double inv = 1.0 / (double)JJ;
    double Ex = g_sum9[0]*inv, Ey = g_sum9[1]*inv, Ez = g_sum9[2]*inv;
    double Mxx = g_sum9[3]*inv, Myy = g_sum9[4]*inv, Mzz = g_sum9[5]*inv;
    double Mxy = g_sum9[6]*inv, Mxz = g_sum9[7]*inv, Myz = g_sum9[8]*inv;
    double w0 = g_Weff2[o*3], w1v = g_Weff2[o*3+1], w2v = g_Weff2[o*3+2];
    double bo = b2[o];
    double wEg = w0*Ex + w1v*Ey + w2v*Ez;
    double m = wEg + bo;
    double Ex2 = w0*w0*Mxx + w1v*w1v*Myy + w2v*w2v*Mzz
               + 2.0*(w0*w1v*Mxy + w0*w2v*Mxz + w1v*w2v*Myz)
               + 2.0*bo*wEg + bo*bo;
    double var = Ex2 - m*m;
    double s = (double)g1[o] / sqrt(var + EPSf);
    g_A1[o*3+0] = (float)(s*w0);
    g_A1[o*3+1] = (float)(s*w1v);
    g_A1[o*3+2] = (float)(s*w2v);
    g_c1v[o] = (float)((double)b1[o] + s*(bo - m));
}

// ---------------- h generation + pooled ----------------
__global__ void hgenk() {
    __shared__ float gsh[48];
    int t = threadIdx.x;
    float a0 = g_A1[t*3], a1 = g_A1[t*3+1], a2 = g_A1[t*3+2], c1 = g_c1v[t];
    for (int it = 0; it < 8; it++) {
        int tile = blockIdx.x*8 + it;
        __syncthreads();
        if (t < 48) gsh[t] = g_grouped[tile*48 + t];
        __syncthreads();
        float hv[KN];
        float mx = 0.0f;
        #pragma unroll
        for (int k = 0; k < KN; k++) {
            float x = gsh[k*3], y = gsh[k*3+1], z = gsh[k*3+2];
            float h = fmaxf(0.0f, fmaf(a0, x, fmaf(a1, y, fmaf(a2, z, c1))));
            hv[k] = h;
            mx = fmaxf(mx, h);
        }
        float* dst = &g_H[(size_t)t*JJ + (size_t)tile*KN];
        #pragma unroll
        for (int q = 0; q < 4; q++)
            *(float4*)(dst + 4*q) = make_float4(hv[4*q], hv[4*q+1], hv[4*q+2], hv[4*q+3]);
        g_P[(size_t)t*NT + tile] = mx;
    }
}

// ---------------- generic 128x128 tiled GEMM, fused epilogues ----------------
// MODE 0: C = AT^T B                      (Zp)
// MODE 1: C = AT^T B + zp[o][j>>4], stats (Z, BN3)
// MODE 2: C = AT^T relu(a*B+d), stats     (Z4, BN4)
template<int MODE>
__global__ __launch_bounds__(256, 2)
void gemm128(const float* __restrict__ AT, int M,
             const float* __restrict__ Bm, int Nn,
             float* __restrict__ Cm, int Kdim,
             const float* __restrict__ zp,
             const float* __restrict__ ta, const float* __restrict__ tb,
             double* __restrict__ sumo, double* __restrict__ sqo) {
    __shared__ float As[2][8][128];
    __shared__ float Bs[2][8][128];
    __shared__ double shs[128], shq[128];
    int t = threadIdx.x;
    int tx = t & 15, ty = t >> 4;
    int o0 = blockIdx.y * 128, j0 = blockIdx.x * 128;
    int lk = t >> 5;            // 0..7
    int lo = (t & 31) * 4;      // 0..124

    float acc[8][8];
    #pragma unroll
    for (int r = 0; r < 8; r++)
        #pragma unroll
        for (int c = 0; c < 8; c++) acc[r][c] = 0.0f;

    // stage 0
    {
        float4 va = *(const float4*)&AT[(size_t)lk*M + o0 + lo];
        float4 vb = *(const float4*)&Bm[(size_t)lk*Nn + j0 + lo];
        if (MODE == 2) {
            float a = ta[lk], d = tb[lk];
            vb.x = fmaxf(0.0f, fmaf(vb.x, a, d));
            vb.y = fmaxf(0.0f, fmaf(vb.y, a, d));
            vb.z = fmaxf(0.0f, fmaf(vb.z, a, d));
            vb.w = fmaxf(0.0f, fmaf(vb.w, a, d));
        }
        *(float4*)&As[0][lk][lo] = va;
        *(float4*)&Bs[0][lk][lo] = vb;
    }
    __syncthreads();

    int cur = 0;
    for (int kc = 0; kc < Kdim; kc += 8) {
        bool has = (kc + 8) < Kdim;
        float4 ra, rb;
        if (has) {
            ra = *(const float4*)&AT[(size_t)(kc + 8 + lk)*M + o0 + lo];
            rb = *(const float4*)&Bm[(size_t)(kc + 8 + lk)*Nn + j0 + lo];
            if (MODE == 2) {
                float a = ta[kc + 8 + lk], d = tb[kc + 8 + lk];
                rb.x = fmaxf(0.0f, fmaf(rb.x, a, d));
                rb.y = fmaxf(0.0f, fmaf(rb.y, a, d));
                rb.z = fmaxf(0.0f, fmaf(rb.z, a, d));
                rb.w = fmaxf(0.0f, fmaf(rb.w, a, d));
            }
        }
        #pragma unroll
        for (int kk = 0; kk < 8; kk++) {
            float av[8], bv[8];
            *(float4*)&av[0] = *(float4*)&As[cur][kk][ty*8];
            *(float4*)&av[4] = *(float4*)&As[cur][kk][ty*8 + 4];
            *(float4*)&bv[0] = *(float4*)&Bs[cur][kk][tx*8];
            *(float4*)&bv[4] = *(float4*)&Bs[cur][kk][tx*8 + 4];
            #pragma unroll
            for (int r = 0; r < 8; r++)
                #pragma unroll
                for (int c = 0; c < 8; c++)
                    acc[r][c] = fmaf(av[r], bv[c], acc[r][c]);
        }
        if (has) {
            *(float4*)&As[cur^1][lk][lo] = ra;
            *(float4*)&Bs[cur^1][lk][lo] = rb;
        }
        __syncthreads();
        cur ^= 1;
    }

    if (MODE == 0) {
        #pragma unroll
        for (int r = 0; r < 8; r++) {
            int o = o0 + ty*8 + r;
            float* cp = &Cm[(size_t)o*Nn + j0 + tx*8];
            *(float4*)cp       = make_float4(acc[r][0], acc[r][1], acc[r][2], acc[r][3]);
            *(float4*)(cp + 4) = make_float4(acc[r][4], acc[r][5], acc[r][6], acc[r][7]);
        }
    } else {
        double rs[8], rq[8];
        #pragma unroll
        for (int r = 0; r < 8; r++) { rs[r] = 0.0; rq[r] = 0.0; }
        #pragma unroll
        for (int r = 0; r < 8; r++) {
            int o = o0 + ty*8 + r;
            float vals[8];
            #pragma unroll
            for (int c = 0; c < 8; c++) {
                int j = j0 + tx*8 + c;
                float v = acc[r][c];
                if (MODE == 1) v += zp[(size_t)o*NT + (j >> 4)];
                vals[c] = v;
                rs[r] += (double)v;
                rq[r] += (double)v * (double)v;
            }
            float* cp = &Cm[(size_t)o*Nn + j0 + tx*8];
            *(float4*)cp       = make_float4(vals[0], vals[1], vals[2], vals[3]);
            *(float4*)(cp + 4) = make_float4(vals[4], vals[5], vals[6], vals[7]);
        }
        if (t < 128) { shs[t] = 0.0; shq[t] = 0.0; }
        __syncthreads();
        #pragma unroll
        for (int r = 0; r < 8; r++) {
            atomicAdd(&shs[ty*8 + r], rs[r]);
            atomicAdd(&shq[ty*8 + r], rq[r]);
        }
        __syncthreads();
        if (t < 128) {
            atomicAdd(&sumo[o0 + t], shs[t]);
            atomicAdd(&sqo[o0 + t], shq[t]);
        }
    }
}

// ---------------- BN affine param kernels ----------------
__global__ void bn3aff(const float* __restrict__ g, const float* __restrict__ b) {
    int c = threadIdx.x;
    if (c >= 512) return;
    double inv = 1.0 / (double)JJ;
    double m = g_bn3sum[c]*inv;
    double var = g_bn3sq[c]*inv - m*m;
    float a = (float)((double)g[c] / sqrt(var + EPSf));
    g_a3[c] = a;
    g_d3[c] = b[c] - (float)m * a;
}
__global__ void bn4aff(const float* __restrict__ g, const float* __restrict__ b) {
    int c = threadIdx.x;
    if (c >= 256) return;
    double inv = 1.0 / (double)JJ;
    double m = g_bn4sum[c]*inv;
    double var = g_bn4sq[c]*inv - m*m;
    float a = (float)((double)g[c] / sqrt(var + EPSf));
    g_a4[c] = a;
    g_d4[c] = b[c] - (float)m * a;
}

// ---------------- final: BN4 + ReLU + max over k -> feat ----------------
__global__ void finalk(float* __restrict__ out) {
    int id = blockIdx.x*256 + threadIdx.x;            // b*131072 + o*512 + ns
    int b = id >> 17;
    int o = (id >> 9) & 255;
    int ns = id & 511;
    float a = g_a4[o], d = g_d4[o];
    const float4* zr = (const float4*)&g_Z4[(size_t)o*JJ + (size_t)((b << 9) | ns)*KN];
    float mx = 0.0f;
    #pragma unroll
    for (int q = 0; q < 4; q++) {
        float4 v = zr[q];
        mx = fmaxf(mx, fmaxf(0.0f, fmaf(v.x, a, d)));
        mx = fmaxf(mx, fmaxf(0.0f, fmaf(v.y, a, d)));
        mx = fmaxf(mx, fmaxf(0.0f, fmaf(v.z, a, d)));
        mx = fmaxf(mx, fmaxf(0.0f, fmaf(v.w, a, d)));
    }
    out[Bb*NSd*3 + id] = mx;
}

// ---------------- launch ----------------
extern "C" void kernel_launch(void* const* d_in, const int* in_sizes, int n_in,
                              void* d_out, int out_size) {
    const float* p    = (const float*)d_in[0];
    const float* w1   = (const float*)d_in[1];
    const float* w2   = (const float*)d_in[2];
    const float* b2   = (const float*)d_in[3];
    const float* bn1g = (const float*)d_in[4];
    const float* bn1b = (const float*)d_in[5];
    const float* w3   = (const float*)d_in[6];
    const float* bn3g = (const float*)d_in[7];
    const float* bn3b = (const float*)d_in[8];
    const float* w4   = (const float*)d_in[9];
    const float* bn4g = (const float*)d_in[10];
    const float* bn4b = (const float*)d_in[11];
    float* out = (float*)d_out;

    float*  dH;  cudaGetSymbolAddress((void**)&dH,  g_H);
    float*  dP;  cudaGetSymbolAddress((void**)&dP,  g_P);
    float*  dZp; cudaGetSymbolAddress((void**)&dZp, g_Zp);
    float*  dZ;  cudaGetSymbolAddress((void**)&dZ,  g_Z);
    float*  dZ4; cudaGetSymbolAddress((void**)&dZ4, g_Z4);
    float*  dW3T; cudaGetSymbolAddress((void**)&dW3T, g_W3T);
    float*  dW4T; cudaGetSymbolAddress((void**)&dW4T, g_W4T);
    float*  da3; cudaGetSymbolAddress((void**)&da3, g_a3);
    float*  dd3; cudaGetSymbolAddress((void**)&dd3, g_d3);
    double* ds3; cudaGetSymbolAddress((void**)&ds3, g_bn3sum);
    double* dq3; cudaGetSymbolAddress((void**)&dq3, g_bn3sq);
    double* ds4; cudaGetSymbolAddress((void**)&ds4, g_bn4sum);
    double* dq4; cudaGetSymbolAddress((void**)&dq4, g_bn4sq);

    zerok<<<1, 512>>>();
    precompk<<<1, 512>>>(w1, w2, w3, w4);
    fpsk<<<32, 512>>>(p, out);                 // writes cntrd to out[0:49152]
    knnk<<<64, 256>>>(p, out);
    bn1k<<<1, 256>>>(b2, bn1g, bn1b);
    hgenk<<<NT/8, 256>>>();
    // Zp = W3a @ pooled : M=512, K=256, N=16384
    gemm128<0><<<dim3(NT/128, 4), 256>>>(dW3T, 512, dP, NT, dZp, 256,
                                         nullptr, nullptr, nullptr, nullptr, nullptr);
    // Z = W3b @ H + zp, BN3 stats : M=512, K=256, N=262144
    gemm128<1><<<dim3(JJ/128, 4), 256>>>(dW3T + 256*512, 512, dH, JJ, dZ, 256,
                                         dZp, nullptr, nullptr, ds3, dq3);
    bn3aff<<<1, 512>>>(bn3g, bn3b);
    // Z4 = W4 @ relu(bn3(Z)), BN4 stats : M=256, K=512, N=262144
    gemm128<2><<<dim3(JJ/128, 2), 256>>>(dW4T, 256, dZ, JJ, dZ4, 512,
                                         nullptr, da3, dd3, ds4, dq4);
    bn4aff<<<1, 256>>>(bn4g, bn4b);
    finalk<<<Bb*256*NSd/256, 256>>>(out);
}

// round 9
// speedup vs baseline: 1.9562x; 1.9524x over previous
#include <cuda_runtime.h>
#include <cstdint>

#define Bb 32
#define Np 2048
#define NSd 512
#define KN 16
#define NT (Bb*NSd)          // 16384 tiles
#define JJ (NT*KN)           // 262144 columns
#define EPSf 1e-5

// ---------------- scratch ----------------
__device__ float  g_grouped[NT*KN*3];
__device__ double g_sum9[9];
__device__ float  g_Weff2[256*3];
__device__ float  g_A1[256*3];
__device__ float  g_c1v[256];
__device__ float  g_P [NT*256];                // pooled [tile][c]
__device__ float  g_Z [(size_t)JJ*512];        // [j][c]
__device__ float  g_M4[NT*256];                // max_k conv4-out [tile][o]
__device__ double g_bn3sum[512], g_bn3sq[512], g_bn4sum[256], g_bn4sq[256];
__device__ float  g_a3[512], g_d3[512], g_a4[256], g_d4[256];

// ---------------- helpers ----------------
__device__ __forceinline__ uint32_t smem_u32(const void* p) {
    uint32_t a;
    asm("{ .reg .u64 t; cvta.to.shared.u64 t, %1; cvt.u32.u64 %0, t; }" : "=r"(a) : "l"(p));
    return a;
}
__device__ __forceinline__ float tf(float x) {
    float r; asm("cvt.rna.tf32.f32 %0, %1;" : "=f"(r) : "f"(x)); return r;
}
#define LDM4(r0,r1,r2,r3,addr) \
    asm volatile("ldmatrix.sync.aligned.m8n8.x4.shared.b16 {%0,%1,%2,%3}, [%4];" \
        : "=r"(r0),"=r"(r1),"=r"(r2),"=r"(r3) : "r"(addr))
#define MMA8(c, a, b) \
    asm volatile("mma.sync.aligned.m16n8k8.row.col.f32.tf32.tf32.f32 " \
        "{%0,%1,%2,%3}, {%4,%5,%6,%7}, {%8,%9}, {%0,%1,%2,%3};" \
        : "+f"((c)[0]),"+f"((c)[1]),"+f"((c)[2]),"+f"((c)[3]) \
        : "r"((a)[0]),"r"((a)[1]),"r"((a)[2]),"r"((a)[3]), "r"((b)[0]),"r"((b)[1]))

// ---------------- zero accumulators (graph replays!) ----------------
__global__ void zerok() {
    int t = threadIdx.x;
    if (t < 9) g_sum9[t] = 0.0;
    for (int i = t; i < 512; i += blockDim.x) { g_bn3sum[i] = 0.0; g_bn3sq[i] = 0.0; }
    for (int i = t; i < 256; i += blockDim.x) { g_bn4sum[i] = 0.0; g_bn4sq[i] = 0.0; }
}

__global__ void precompk(const float* __restrict__ w1, const float* __restrict__ w2) {
    int t = threadIdx.x;
    if (t < 256) {
        double s0 = 0.0, s1 = 0.0, s2 = 0.0;
        for (int i = 0; i < 256; i++) {
            double wi = (double)w2[t*256 + i];
            s0 += wi * ((double)w1[i*6+0] + (double)w1[i*6+3]);
            s1 += wi * ((double)w1[i*6+1] + (double)w1[i*6+4]);
            s2 += wi * ((double)w1[i*6+2] + (double)w1[i*6+5]);
        }
        g_Weff2[t*3+0] = (float)s0; g_Weff2[t*3+1] = (float)s1; g_Weff2[t*3+2] = (float)s2;
    }
}

// ---------------- FPS ----------------
__global__ void fpsk(const float* __restrict__ p, float* __restrict__ outc) {
    __shared__ float sp[Np*3];
    __shared__ unsigned long long skey[16];
    __shared__ int s_cs;
    int b = blockIdx.x, t = threadIdx.x;
    for (int i = t; i < Np*3; i += 512) sp[i] = p[b*Np*3 + i];
    __syncthreads();
    float px[4], py[4], pz[4], dist[4];
    #pragma unroll
    for (int i = 0; i < 4; i++) {
        int n = t + 512*i;
        px[i] = sp[n*3+0]; py[i] = sp[n*3+1]; pz[i] = sp[n*3+2];
        dist[i] = 1e10f;
    }
    int lane = t & 31, wid = t >> 5;
    int cs = 0;
    for (int s = 0; s < NSd; s++) {
        if (t == 0) {
            outc[(b*NSd + s)*3 + 0] = sp[cs*3+0];
            outc[(b*NSd + s)*3 + 1] = sp[cs*3+1];
            outc[(b*NSd + s)*3 + 2] = sp[cs*3+2];
        }
        float cx = sp[cs*3+0], cy = sp[cs*3+1], cz = sp[cs*3+2];
        unsigned long long best = 0ull;
        #pragma unroll
        for (int i = 0; i < 4; i++) {
            float dx = __fadd_rn(px[i], -cx);
            float dy = __fadd_rn(py[i], -cy);
            float dz = __fadd_rn(pz[i], -cz);
            float d = __fadd_rn(__fadd_rn(__fmul_rn(dx,dx), __fmul_rn(dy,dy)), __fmul_rn(dz,dz));
            dist[i] = fminf(dist[i], d);
            unsigned long long key = ((unsigned long long)__float_as_uint(dist[i]) << 32)
                                   | (unsigned)(Np - 1 - (t + 512*i));
            best = max(best, key);
        }
        #pragma unroll
        for (int off = 16; off; off >>= 1)
            best = max(best, __shfl_down_sync(0xffffffffu, best, off));
        if (lane == 0) skey[wid] = best;
        __syncthreads();
        if (t < 16) {
            unsigned long long k2 = skey[t];
            #pragma unroll
            for (int off = 8; off; off >>= 1)
                k2 = max(k2, __shfl_down_sync(0xffffu, k2, off));
            if (t == 0) s_cs = Np - 1 - (int)(unsigned)(k2 & 0xffffffffull);
        }
        __syncthreads();
        cs = s_cs;
    }
}

// ---------------- kNN ----------------
__global__ void knnk(const float* __restrict__ p, const float* __restrict__ cntrd) {
    __shared__ float shp[Np*3];
    __shared__ float sp2[Np];
    __shared__ double s9[9];
    int t = threadIdx.x;
    int gc = blockIdx.x*256 + t;
    int b = blockIdx.x >> 1;
    for (int i = t; i < Np*3; i += 256) shp[i] = p[b*Np*3 + i];
    if (t < 9) s9[t] = 0.0;
    __syncthreads();
    for (int n = t; n < Np; n += 256) {
        float x = shp[n*3], y = shp[n*3+1], z = shp[n*3+2];
        sp2[n] = __fadd_rn(__fadd_rn(__fmul_rn(x,x), __fmul_rn(y,y)), __fmul_rn(z,z));
    }
    __syncthreads();
    float cx = cntrd[gc*3+0], cy = cntrd[gc*3+1], cz = cntrd[gc*3+2];
    float c2 = __fadd_rn(__fadd_rn(__fmul_rn(cx,cx), __fmul_rn(cy,cy)), __fmul_rn(cz,cz));
    float hd[KN]; int hi[KN];
    #pragma unroll
    for (int k = 0; k < KN; k++) { hd[k] = 3.4e38f; hi[k] = 0; }
    for (int n = 0; n < Np; n++) {
        float dot = __fadd_rn(__fadd_rn(__fmul_rn(cx, shp[n*3]),
                                        __fmul_rn(cy, shp[n*3+1])),
                              __fmul_rn(cz, shp[n*3+2]));
        float d2 = __fadd_rn(__fadd_rn(c2, sp2[n]), -__fmul_rn(2.0f, dot));
        if (d2 < hd[KN-1]) {
            hd[KN-1] = d2; hi[KN-1] = n;
            #pragma unroll
            for (int j = KN-1; j > 0; --j) {
                bool sw = hd[j] < hd[j-1];
                float td = hd[j]; int ti = hi[j];
                float tdm = hd[j-1]; int tim = hi[j-1];
                hd[j]   = sw ? tdm : td;   hi[j]   = sw ? tim : ti;
                hd[j-1] = sw ? td  : tdm;  hi[j-1] = sw ? ti  : tim;
            }
        }
    }
    double sx=0, sy=0, sz=0, sxx=0, syy=0, szz=0, sxy=0, sxz=0, syz=0;
    #pragma unroll
    for (int k = 0; k < KN; k++) {
        int n = hi[k];
        float x = shp[n*3], y = shp[n*3+1], z = shp[n*3+2];
        g_grouped[(gc*KN + k)*3 + 0] = x;
        g_grouped[(gc*KN + k)*3 + 1] = y;
        g_grouped[(gc*KN + k)*3 + 2] = z;
        sx += x; sy += y; sz += z;
        sxx += (double)x*x; syy += (double)y*y; szz += (double)z*z;
        sxy += (double)x*y; sxz += (double)x*z; syz += (double)y*z;
    }
    atomicAdd(&s9[0], sx);  atomicAdd(&s9[1], sy);  atomicAdd(&s9[2], sz);
    atomicAdd(&s9[3], sxx); atomicAdd(&s9[4], syy); atomicAdd(&s9[5], szz);
    atomicAdd(&s9[6], sxy); atomicAdd(&s9[7], sxz); atomicAdd(&s9[8], syz);
    __syncthreads();
    if (t < 9) atomicAdd(&g_sum9[t], s9[t]);
}

// ---------------- BN1 affine from analytic moments ----------------
__global__ void bn1k(const float* __restrict__ b2, const float* __restrict__ g1,
                     const float* __restrict__ b1) {
    int o = threadIdx.x;
    if (o >= 256) return;
    double inv = 1.0 / (double)JJ;
    double Ex = g_sum9[0]*inv, Ey = g_sum9[1]*inv, Ez = g_sum9[2]*inv;
    double Mxx = g_sum9[3]*inv, Myy = g_sum9[4]*inv, Mzz = g_sum9[5]*inv;
    double Mxy = g_sum9[6]*inv, Mxz = g_sum9[7]*inv, Myz = g_sum9[8]*inv;
    double w0 = g_Weff2[o*3], w1v = g_Weff2[o*3+1], w2v = g_Weff2[o*3+2];
    double bo = b2[o];
    double wEg = w0*Ex + w1v*Ey + w2v*Ez;
    double m = wEg + bo;
    double Ex2 = w0*w0*Mxx + w1v*w1v*Myy + w2v*w2v*Mzz
               + 2.0*(w0*w1v*Mxy + w0*w2v*Mxz + w1v*w2v*Myz)
               + 2.0*bo*wEg + bo*bo;
    double var = Ex2 - m*m;
    double s = (double)g1[o] / sqrt(var + EPSf);
    g_A1[o*3+0] = (float)(s*w0);
    g_A1[o*3+1] = (float)(s*w1v);
    g_A1[o*3+2] = (float)(s*w2v);
    g_c1v[o] = (float)((double)b1[o] + s*(bo - m));
}

// ---------------- pooled: P[tile][c] = max_k relu(A1.xyz + c1) ----------------
__global__ void pgenk() {
    __shared__ float gsh[48];
    int t = threadIdx.x;
    float a0 = g_A1[t*3], a1 = g_A1[t*3+1], a2 = g_A1[t*3+2], c1 = g_c1v[t];
    for (int it = 0; it < 8; it++) {
        int tile = blockIdx.x*8 + it;
        __syncthreads();
        if (t < 48) gsh[t] = g_grouped[tile*48 + t];
        __syncthreads();
        float mx = 0.0f;
        #pragma unroll
        for (int k = 0; k < KN; k++)
            mx = fmaxf(mx, fmaxf(0.0f, fmaf(a0, gsh[k*3], fmaf(a1, gsh[k*3+1], fmaf(a2, gsh[k*3+2], c1)))));
        g_P[(size_t)tile*256 + t] = mx;
    }
}

// ================= GEMM1 (mma.sync tf32): Z[j][o] = sum_c w3[o][c]*Baug[j][c] =================
// CTA: 128 o x 128 j, K=512; 8 warps, warp tile 32x64.
// smem: stage A 2x16KB @0; stage B 2x16KB @32768; T union 0..67584; XYZ @67584; params @69120
#define G1_SMEM 73216
__global__ __launch_bounds__(256, 2) void tcg1(const float* __restrict__ w3) {
    extern __shared__ __align__(16) float smf[];
    uint32_t sb = smem_u32(smf);
    int t = threadIdx.x, lane = t & 31, wid = t >> 5;
    int wm = wid & 3, wn = wid >> 2;
    int j0 = blockIdx.x * 128, o0 = blockIdx.y * 128;
    float* sXYZ = smf + 16896;
    float* sA0 = smf + 17280;
    float* sA1p = sA0 + 256; float* sA2p = sA0 + 512; float* sCp = sA0 + 768;

    for (int i = t; i < 384; i += 256) sXYZ[i] = g_grouped[(size_t)j0*3 + i];
    sA0[t] = g_A1[t*3]; sA1p[t] = g_A1[t*3+1]; sA2p[t] = g_A1[t*3+2]; sCp[t] = g_c1v[t];
    __syncthreads();

    float acc[2][8][4];
    #pragma unroll
    for (int mf = 0; mf < 2; mf++)
        #pragma unroll
        for (int nf = 0; nf < 8; nf++)
            #pragma unroll
            for (int e = 0; e < 4; e++) acc[mf][nf][e] = 0.0f;

    int t0 = j0 >> 4;

    auto fill = [&](int buf, int kc) {
        int c0 = kc*32;
        float* A = smf + buf*4096;
        float* Bp = smf + 8192 + buf*4096;
        #pragma unroll
        for (int i = 0; i < 4; i++) {
            int slot = t + 256*i;
            int o = slot >> 3, chR = slot & 7;
            float4 v = *(const float4*)&w3[(size_t)(o0+o)*512 + c0 + chR*4];
            v.x = tf(v.x); v.y = tf(v.y); v.z = tf(v.z); v.w = tf(v.w);
            *(float4*)&A[o*32 + ((chR ^ (o & 7)) << 2)] = v;
        }
        if (kc < 8) {
            #pragma unroll
            for (int i = 0; i < 4; i++) {
                int slot = t + 256*i;
                int j = slot >> 3, chR = slot & 7;
                float4 v = *(const float4*)&g_P[(size_t)(t0 + (j >> 4))*256 + c0 + chR*4];
                v.x = tf(v.x); v.y = tf(v.y); v.z = tf(v.z); v.w = tf(v.w);
                *(float4*)&Bp[j*32 + ((chR ^ (j & 7)) << 2)] = v;
            }
        } else {
            int cb = c0 - 256;
            #pragma unroll
            for (int i = 0; i < 4; i++) {
                int slot = t + 256*i;
                int j = slot >> 3, chR = slot & 7;
                float x = sXYZ[j*3], y = sXYZ[j*3+1], z = sXYZ[j*3+2];
                int c = cb + chR*4;
                float4 v;
                v.x = tf(fmaxf(0.f, fmaf(sA0[c+0], x, fmaf(sA1p[c+0], y, fmaf(sA2p[c+0], z, sCp[c+0])))));
                v.y = tf(fmaxf(0.f, fmaf(sA0[c+1], x, fmaf(sA1p[c+1], y, fmaf(sA2p[c+1], z, sCp[c+1])))));
                v.z = tf(fmaxf(0.f, fmaf(sA0[c+2], x, fmaf(sA1p[c+2], y, fmaf(sA2p[c+2], z, sCp[c+2])))));
                v.w = tf(fmaxf(0.f, fmaf(sA0[c+3], x, fmaf(sA1p[c+3], y, fmaf(sA2p[c+3], z, sCp[c+3])))));
                *(float4*)&Bp[j*32 + ((chR ^ (j & 7)) << 2)] = v;
            }
        }
    };

    auto compute = [&](int buf) {
        uint32_t abase = sb + buf*16384;
        uint32_t bbase = sb + 32768 + buf*16384;
        int t7 = lane & 7, mi = lane >> 3;
        #pragma unroll
        for (int s = 0; s < 4; s++) {
            uint32_t a[2][4], b[8][2];
            #pragma unroll
            for (int mf = 0; mf < 2; mf++) {
                int row = wm*32 + mf*16 + ((mi & 1) << 3) + t7;
                int ch = 2*s + (mi >> 1);
                uint32_t ad = abase + row*128 + ((ch ^ (row & 7)) << 4);
                LDM4(a[mf][0], a[mf][1], a[mf][2], a[mf][3], ad);
            }
            #pragma unroll
            for (int np = 0; np < 4; np++) {
                int row = wn*64 + np*16 + ((mi >> 1) << 3) + t7;
                int ch = 2*s + (mi & 1);
                uint32_t ad = bbase + row*128 + ((ch ^ (row & 7)) << 4);
                LDM4(b[2*np][0], b[2*np][1], b[2*np+1][0], b[2*np+1][1], ad);
            }
            #pragma unroll
            for (int mf = 0; mf < 2; mf++)
                #pragma unroll
                for (int nf = 0; nf < 8; nf++)
                    MMA8(acc[mf][nf], a[mf], b[nf]);
        }
    };

    fill(0, 0);
    __syncthreads();
    for (int kc = 0; kc < 16; kc++) {
        int cur = kc & 1;
        if (kc + 1 < 16) fill(cur ^ 1, kc + 1);
        compute(cur);
        __syncthreads();
    }

    // stats via quad shuffles
    int t4 = lane & 3, gr = lane >> 2;
    #pragma unroll
    for (int mf = 0; mf < 2; mf++)
        #pragma unroll
        for (int rs = 0; rs < 2; rs++) {
            double s = 0.0, q = 0.0;
            #pragma unroll
            for (int nf = 0; nf < 8; nf++) {
                float v0 = acc[mf][nf][rs*2], v1 = acc[mf][nf][rs*2+1];
                s += (double)v0 + (double)v1;
                q += (double)v0*(double)v0 + (double)v1*(double)v1;
            }
            s += __shfl_xor_sync(0xffffffffu, s, 1); s += __shfl_xor_sync(0xffffffffu, s, 2);
            q += __shfl_xor_sync(0xffffffffu, q, 1); q += __shfl_xor_sync(0xffffffffu, q, 2);
            if (t4 == 0) {
                int o = o0 + wm*32 + mf*16 + rs*8 + gr;
                atomicAdd(&g_bn3sum[o], s); atomicAdd(&g_bn3sq[o], q);
            }
        }

    // transpose through smem (pad 132) then coalesced store
    float* T = smf;
    #pragma unroll
    for (int mf = 0; mf < 2; mf++)
        #pragma unroll
        for (int nf = 0; nf < 8; nf++) {
            int orw = wm*32 + mf*16 + gr;
            int jl = wn*64 + nf*8 + 2*t4;
            T[jl*132 + orw]       = acc[mf][nf][0];
            T[(jl+1)*132 + orw]   = acc[mf][nf][1];
            T[jl*132 + orw + 8]   = acc[mf][nf][2];
            T[(jl+1)*132 + orw+8] = acc[mf][nf][3];
        }
    __syncthreads();
    int col4 = t & 31, wrow = t >> 5;
    #pragma unroll
    for (int r = 0; r < 16; r++) {
        int row = wrow + 8*r;
        float4 v = *(float4*)&T[row*132 + col4*4];
        *(float4*)&g_Z[(size_t)(j0+row)*512 + o0 + col4*4] = v;
    }
}

// ================= GEMM2 (mma.sync tf32): stats + max_k of w4 @ relu(bn3(Z)) =================
// CTA: 256 o x 128 j, K=512; 8 warps, warp tile 64x64.
// smem: stage A 2x32KB @0; stage B 2x16KB @65536; params @98304
#define G2_SMEM 102400
__global__ __launch_bounds__(256, 1) void tcg2(const float* __restrict__ w4) {
    extern __shared__ __align__(16) float smf[];
    uint32_t sb = smem_u32(smf);
    int t = threadIdx.x, lane = t & 31, wid = t >> 5;
    int wm = wid & 3, wn = wid >> 2;
    int j0 = blockIdx.x * 128;
    float* sa3 = smf + 24576;
    float* sd3 = sa3 + 512;
    for (int i = t; i < 512; i += 256) { sa3[i] = g_a3[i]; sd3[i] = g_d3[i]; }
    __syncthreads();

    float acc[4][8][4];
    #pragma unroll
    for (int mf = 0; mf < 4; mf++)
        #pragma unroll
        for (int nf = 0; nf < 8; nf++)
            #pragma unroll
            for (int e = 0; e < 4; e++) acc[mf][nf][e] = 0.0f;

    auto fill = [&](int buf, int kc) {
        int c0 = kc*32;
        float* A = smf + buf*8192;
        float* Bp = smf + 16384 + buf*4096;
        #pragma unroll
        for (int i = 0; i < 8; i++) {
            int slot = t + 256*i;
            int o = slot >> 3, chR = slot & 7;
            float4 v = *(const float4*)&w4[(size_t)o*512 + c0 + chR*4];
            v.x = tf(v.x); v.y = tf(v.y); v.z = tf(v.z); v.w = tf(v.w);
            *(float4*)&A[o*32 + ((chR ^ (o & 7)) << 2)] = v;
        }
        #pragma unroll
        for (int i = 0; i < 4; i++) {
            int slot = t + 256*i;
            int j = slot >> 3, chR = slot & 7;
            float4 zv = *(const float4*)&g_Z[(size_t)(j0+j)*512 + c0 + chR*4];
            int c = c0 + chR*4;
            float4 v;
            v.x = tf(fmaxf(0.f, fmaf(zv.x, sa3[c+0], sd3[c+0])));
            v.y = tf(fmaxf(0.f, fmaf(zv.y, sa3[c+1], sd3[c+1])));
            v.z = tf(fmaxf(0.f, fmaf(zv.z, sa3[c+2], sd3[c+2])));
            v.w = tf(fmaxf(0.f, fmaf(zv.w, sa3[c+3], sd3[c+3])));
            *(float4*)&Bp[j*32 + ((chR ^ (j & 7)) << 2)] = v;
        }
    };

    auto compute = [&](int buf) {
        uint32_t abase = sb + buf*32768;
        uint32_t bbase = sb + 65536 + buf*16384;
        int t7 = lane & 7, mi = lane >> 3;
        #pragma unroll
        for (int s = 0; s < 4; s++) {
            uint32_t a[4][4], b[8][2];
            #pragma unroll
            for (int mf = 0; mf < 4; mf++) {
                int row = wm*64 + mf*16 + ((mi & 1) << 3) + t7;
                int ch = 2*s + (mi >> 1);
                uint32_t ad = abase + row*128 + ((ch ^ (row & 7)) << 4);
                LDM4(a[mf][0], a[mf][1], a[mf][2], a[mf][3], ad);
            }
            #pragma unroll
            for (int np = 0; np < 4; np++) {
                int row = wn*64 + np*16 + ((mi >> 1) << 3) + t7;
                int ch = 2*s + (mi & 1);
                uint32_t ad = bbase + row*128 + ((ch ^ (row & 7)) << 4);
                LDM4(b[2*np][0], b[2*np][1], b[2*np+1][0], b[2*np+1][1], ad);
            }
            #pragma unroll
            for (int mf = 0; mf < 4; mf++)
                #pragma unroll
                for (int nf = 0; nf < 8; nf++)
                    MMA8(acc[mf][nf], a[mf], b[nf]);
        }
    };

    fill(0, 0);
    __syncthreads();
    for (int kc = 0; kc < 16; kc++) {
        int cur = kc & 1;
        if (kc + 1 < 16) fill(cur ^ 1, kc + 1);
        compute(cur);
        __syncthreads();
    }

    int t4 = lane & 3, gr = lane >> 2;
    int jt0 = (j0 >> 4) + wn*4;
    #pragma unroll
    for (int mf = 0; mf < 4; mf++)
        #pragma unroll
        for (int rs = 0; rs < 2; rs++) {
            int o = wm*64 + mf*16 + rs*8 + gr;
            double s = 0.0, q = 0.0;
            #pragma unroll
            for (int nf = 0; nf < 8; nf++) {
                float v0 = acc[mf][nf][rs*2], v1 = acc[mf][nf][rs*2+1];
                s += (double)v0 + (double)v1;
                q += (double)v0*(double)v0 + (double)v1*(double)v1;
            }
            s += __shfl_xor_sync(0xffffffffu, s, 1); s += __shfl_xor_sync(0xffffffffu, s, 2);
            q += __shfl_xor_sync(0xffffffffu, q, 1); q += __shfl_xor_sync(0xffffffffu, q, 2);
            if (t4 == 0) { atomicAdd(&g_bn4sum[o], s); atomicAdd(&g_bn4sq[o], q); }
            #pragma unroll
            for (int tt = 0; tt < 4; tt++) {
                float m = fmaxf(fmaxf(acc[mf][2*tt][rs*2], acc[mf][2*tt][rs*2+1]),
                                fmaxf(acc[mf][2*tt+1][rs*2], acc[mf][2*tt+1][rs*2+1]));
                m = fmaxf(m, __shfl_xor_sync(0xffffffffu, m, 1));
                m = fmaxf(m, __shfl_xor_sync(0xffffffffu, m, 2));
                if (t4 == 0) g_M4[(size_t)(jt0 + tt)*256 + o] = m;
            }
        }
}

// ---------------- BN affine params ----------------
__global__ void bn3aff(const float* __restrict__ g, const float* __restrict__ b) {
    int c = threadIdx.x;
    if (c >= 512) return;
    double inv = 1.0 / (double)JJ;
    double m = g_bn3sum[c]*inv;
    double var = g_bn3sq[c]*inv - m*m;
    float a = (float)((double)g[c] / sqrt(var + EPSf));
    g_a3[c] = a;
    g_d3[c] = b[c] - (float)m * a;
}
__global__ void bn4aff(const float* __restrict__ g, const float* __restrict__ b) {
    int c = threadIdx.x;
    if (c >= 256) return;
    double inv = 1.0 / (double)JJ;
    double m = g_bn4sum[c]*inv;
    double var = g_bn4sq[c]*inv - m*m;
    float a = (float)((double)g[c] / sqrt(var + EPSf));
    g_a4[c] = a;
    g_d4[c] = b[c] - (float)m * a;
}

// ---------------- final: feat[b][o][ns] = relu(a4*M4 + d4)  (a4>0) ----------------
__global__ void finalk(float* __restrict__ out) {
    __shared__ float sm[32*257];
    int b = blockIdx.x >> 4, chunk = blockIdx.x & 15, t = threadIdx.x;
    int tile0 = b*512 + chunk*32;
    for (int i = t; i < 8192; i += 256) {
        int tl = i >> 8, o = i & 255;
        sm[tl*257 + o] = g_M4[(size_t)(tile0 + tl)*256 + o];
    }
    __syncthreads();
    int nsl = t & 31, og = t >> 5;
    for (int pass = 0; pass < 32; pass++) {
        int o = pass*8 + og;
        float a = g_a4[o], d = g_d4[o];
        float v = fmaxf(0.0f, fmaf(sm[nsl*257 + o], a, d));
        out[Bb*NSd*3 + b*131072 + o*512 + chunk*32 + nsl] = v;
    }
}

// ---------------- launch ----------------
extern "C" void kernel_launch(void* const* d_in, const int* in_sizes, int n_in,
                              void* d_out, int out_size) {
    const float* p    = (const float*)d_in[0];
    const float* w1   = (const float*)d_in[1];
    const float* w2   = (const float*)d_in[2];
    const float* b2   = (const float*)d_in[3];
    const float* bn1g = (const float*)d_in[4];
    const float* bn1b = (const float*)d_in[5];
    const float* w3   = (const float*)d_in[6];
    const float* bn3g = (const float*)d_in[7];
    const float* bn3b = (const float*)d_in[8];
    const float* w4   = (const float*)d_in[9];
    const float* bn4g = (const float*)d_in[10];
    const float* bn4b = (const float*)d_in[11];
    float* out = (float*)d_out;

    cudaFuncSetAttribute(tcg1, cudaFuncAttributeMaxDynamicSharedMemorySize, G1_SMEM);
    cudaFuncSetAttribute(tcg2, cudaFuncAttributeMaxDynamicSharedMemorySize, G2_SMEM);

    zerok<<<1, 512>>>();
    precompk<<<1, 256>>>(w1, w2);
    fpsk<<<32, 512>>>(p, out);                 // centroids -> out[0:49152]
    knnk<<<64, 256>>>(p, out);
    bn1k<<<1, 256>>>(b2, bn1g, bn1b);
    pgenk<<<NT/8, 256>>>();
    tcg1<<<dim3(JJ/128, 4), 256, G1_SMEM>>>(w3);
    bn3aff<<<1, 512>>>(bn3g, bn3b);
    tcg2<<<JJ/128, 256, G2_SMEM>>>(w4);
    bn4aff<<<1, 256>>>(bn4g, bn4b);
    finalk<<<Bb*16, 256>>>(out);
}

// round 10
// speedup vs baseline: 2.2932x; 1.1722x over previous
#include <cuda_runtime.h>
#include <cuda_fp16.h>
#include <cstdint>

#define Bb 32
#define Np 2048
#define NSd 512
#define KN 16
#define NT (Bb*NSd)          // 16384 tiles
#define JJ (NT*KN)           // 262144 columns
#define EPSf 1e-5

// ---------------- scratch ----------------
__device__ float  g_grouped[NT*KN*3];
__device__ double g_sum9[9];
__device__ float  g_Weff2[256*3];
__device__ float  g_A1[256*3];
__device__ float  g_c1v[256];
__device__ float  g_P [NT*256];                // pooled [tile][c], tf32-rounded
__device__ float  g_w3r[512*512];              // tf32-rounded w3
__device__ float  g_w4r[256*512];              // tf32-rounded w4
__device__ __half g_Zh[(size_t)JJ*512];        // 268 MB  [j][c] fp16
__device__ float  g_M4[NT*256];                // max_k conv4-out [tile][o]
__device__ double g_bn3sum[512], g_bn3sq[512], g_bn4sum[256], g_bn4sq[256];
__device__ float  g_a3[512], g_d3[512], g_a4[256], g_d4[256];

// ---------------- helpers ----------------
__device__ __forceinline__ uint32_t smem_u32(const void* p) {
    uint32_t a;
    asm("{ .reg .u64 t; cvta.to.shared.u64 t, %1; cvt.u32.u64 %0, t; }" : "=r"(a) : "l"(p));
    return a;
}
__device__ __forceinline__ float tf(float x) {
    float r; asm("cvt.rna.tf32.f32 %0, %1;" : "=f"(r) : "f"(x)); return r;
}
#define LDM4(r0,r1,r2,r3,addr) \
    asm volatile("ldmatrix.sync.aligned.m8n8.x4.shared.b16 {%0,%1,%2,%3}, [%4];" \
        : "=r"(r0),"=r"(r1),"=r"(r2),"=r"(r3) : "r"(addr))
#define MMA8(c, a, b) \
    asm volatile("mma.sync.aligned.m16n8k8.row.col.f32.tf32.tf32.f32 " \
        "{%0,%1,%2,%3}, {%4,%5,%6,%7}, {%8,%9}, {%0,%1,%2,%3};" \
        : "+f"((c)[0]),"+f"((c)[1]),"+f"((c)[2]),"+f"((c)[3]) \
        : "r"((a)[0]),"r"((a)[1]),"r"((a)[2]),"r"((a)[3]), "r"((b)[0]),"r"((b)[1]))
#define CPA(dst, src) asm volatile("cp.async.cg.shared.global [%0], [%1], 16;" ::"r"(dst),"l"(src))
#define CPA_COMMIT()  asm volatile("cp.async.commit_group;" ::: "memory")
#define CPA_WAIT0()   asm volatile("cp.async.wait_group 0;" ::: "memory")

// ---------------- zero accumulators (graph replays!) ----------------
__global__ void zerok() {
    int t = threadIdx.x;
    if (t < 9) g_sum9[t] = 0.0;
    for (int i = t; i < 512; i += blockDim.x) { g_bn3sum[i] = 0.0; g_bn3sq[i] = 0.0; }
    for (int i = t; i < 256; i += blockDim.x) { g_bn4sum[i] = 0.0; g_bn4sq[i] = 0.0; }
}

__global__ void precompk(const float* __restrict__ w1, const float* __restrict__ w2) {
    int t = threadIdx.x;
    if (t < 256) {
        double s0 = 0.0, s1 = 0.0, s2 = 0.0;
        for (int i = 0; i < 256; i++) {
            double wi = (double)w2[t*256 + i];
            s0 += wi * ((double)w1[i*6+0] + (double)w1[i*6+3]);
            s1 += wi * ((double)w1[i*6+1] + (double)w1[i*6+4]);
            s2 += wi * ((double)w1[i*6+2] + (double)w1[i*6+5]);
        }
        g_Weff2[t*3+0] = (float)s0; g_Weff2[t*3+1] = (float)s1; g_Weff2[t*3+2] = (float)s2;
    }
}

// pre-round weights to tf32 (so cp.async raw copies carry rna-rounded data)
__global__ void roundwk(const float* __restrict__ w3, const float* __restrict__ w4) {
    int i = blockIdx.x*512 + threadIdx.x;
    if (i < 512*512) g_w3r[i] = tf(w3[i]);
    if (i < 256*512) g_w4r[i] = tf(w4[i]);
}

// ---------------- FPS ----------------
__global__ void fpsk(const float* __restrict__ p, float* __restrict__ outc) {
    __shared__ float sp[Np*3];
    __shared__ unsigned long long skey[16];
    __shared__ int s_cs;
    int b = blockIdx.x, t = threadIdx.x;
    for (int i = t; i < Np*3; i += 512) sp[i] = p[b*Np*3 + i];
    __syncthreads();
    float px[4], py[4], pz[4], dist[4];
    #pragma unroll
    for (int i = 0; i < 4; i++) {
        int n = t + 512*i;
        px[i] = sp[n*3+0]; py[i] = sp[n*3+1]; pz[i] = sp[n*3+2];
        dist[i] = 1e10f;
    }
    int lane = t & 31, wid = t >> 5;
    int cs = 0;
    for (int s = 0; s < NSd; s++) {
        if (t == 0) {
            outc[(b*NSd + s)*3 + 0] = sp[cs*3+0];
            outc[(b*NSd + s)*3 + 1] = sp[cs*3+1];
            outc[(b*NSd + s)*3 + 2] = sp[cs*3+2];
        }
        float cx = sp[cs*3+0], cy = sp[cs*3+1], cz = sp[cs*3+2];
        unsigned long long best = 0ull;
        #pragma unroll
        for (int i = 0; i < 4; i++) {
            float dx = __fadd_rn(px[i], -cx);
            float dy = __fadd_rn(py[i], -cy);
            float dz = __fadd_rn(pz[i], -cz);
            float d = __fadd_rn(__fadd_rn(__fmul_rn(dx,dx), __fmul_rn(dy,dy)), __fmul_rn(dz,dz));
            dist[i] = fminf(dist[i], d);
            unsigned long long key = ((unsigned long long)__float_as_uint(dist[i]) << 32)
                                   | (unsigned)(Np - 1 - (t + 512*i));
            best = max(best, key);
        }
        #pragma unroll
        for (int off = 16; off; off >>= 1)
            best = max(best, __shfl_down_sync(0xffffffffu, best, off));
        if (lane == 0) skey[wid] = best;
        __syncthreads();
        if (t < 16) {
            unsigned long long k2 = skey[t];
            #pragma unroll
            for (int off = 8; off; off >>= 1)
                k2 = max(k2, __shfl_down_sync(0xffffu, k2, off));
            if (t == 0) s_cs = Np - 1 - (int)(unsigned)(k2 & 0xffffffffull);
        }
        __syncthreads();
        cs = s_cs;
    }
}

// ---------------- kNN: 256 blocks x 64 threads (covers all SMs) ----------------
__global__ void knnk(const float* __restrict__ p, const float* __restrict__ cntrd) {
    __shared__ float shp[Np*3];
    __shared__ float sp2[Np];
    __shared__ double s9[9];
    int t = threadIdx.x;
    int gc = blockIdx.x*64 + t;
    int b = blockIdx.x >> 3;               // 8 blocks per batch
    for (int i = t; i < Np*3; i += 64) shp[i] = p[b*Np*3 + i];
    if (t < 9) s9[t] = 0.0;
    __syncthreads();
    for (int n = t; n < Np; n += 64) {
        float x = shp[n*3], y = shp[n*3+1], z = shp[n*3+2];
        sp2[n] = __fadd_rn(__fadd_rn(__fmul_rn(x,x), __fmul_rn(y,y)), __fmul_rn(z,z));
    }
    __syncthreads();
    float cx = cntrd[gc*3+0], cy = cntrd[gc*3+1], cz = cntrd[gc*3+2];
    float c2 = __fadd_rn(__fadd_rn(__fmul_rn(cx,cx), __fmul_rn(cy,cy)), __fmul_rn(cz,cz));
    float hd[KN]; int hi[KN];
    #pragma unroll
    for (int k = 0; k < KN; k++) { hd[k] = 3.4e38f; hi[k] = 0; }
    for (int n = 0; n < Np; n++) {
        float dot = __fadd_rn(__fadd_rn(__fmul_rn(cx, shp[n*3]),
                                        __fmul_rn(cy, shp[n*3+1])),
                              __fmul_rn(cz, shp[n*3+2]));
        float d2 = __fadd_rn(__fadd_rn(c2, sp2[n]), -__fmul_rn(2.0f, dot));
        if (d2 < hd[KN-1]) {
            hd[KN-1] = d2; hi[KN-1] = n;
            #pragma unroll
            for (int j = KN-1; j > 0; --j) {
                bool sw = hd[j] < hd[j-1];
                float td = hd[j]; int ti = hi[j];
                float tdm = hd[j-1]; int tim = hi[j-1];
                hd[j]   = sw ? tdm : td;   hi[j]   = sw ? tim : ti;
                hd[j-1] = sw ? td  : tdm;  hi[j-1] = sw ? ti  : tim;
            }
        }
    }
    double sx=0, sy=0, sz=0, sxx=0, syy=0, szz=0, sxy=0, sxz=0, syz=0;
    #pragma unroll
    for (int k = 0; k < KN; k++) {
        int n = hi[k];
        float x = shp[n*3], y = shp[n*3+1], z = shp[n*3+2];
        g_grouped[(gc*KN + k)*3 + 0] = x;
        g_grouped[(gc*KN + k)*3 + 1] = y;
        g_grouped[(gc*KN + k)*3 + 2] = z;
        sx += x; sy += y; sz += z;
        sxx += (double)x*x; syy += (double)y*y; szz += (double)z*z;
        sxy += (double)x*y; sxz += (double)x*z; syz += (double)y*z;
    }
    atomicAdd(&s9[0], sx);  atomicAdd(&s9[1], sy);  atomicAdd(&s9[2], sz);
    atomicAdd(&s9[3], sxx); atomicAdd(&s9[4], syy); atomicAdd(&s9[5], szz);
    atomicAdd(&s9[6], sxy); atomicAdd(&s9[7], sxz); atomicAdd(&s9[8], syz);
    __syncthreads();
    if (t < 9) atomicAdd(&g_sum9[t], s9[t]);
}

// ---------------- BN1 affine from analytic moments ----------------
__global__ void bn1k(const float* __restrict__ b2, const float* __restrict__ g1,
                     const float* __restrict__ b1) {
    int o = threadIdx.x;
    if (o >= 256) return;
    double inv = 1.0 / (double)JJ;
    double Ex = g_sum9[0]*inv, Ey = g_sum9[1]*inv, Ez = g_sum9[2]*inv;
    double Mxx = g_sum9[3]*inv, Myy = g_sum9[4]*inv, Mzz = g_sum9[5]*inv;
    double Mxy = g_sum9[6]*inv, Mxz = g_sum9[7]*inv, Myz = g_sum9[8]*inv;
    double w0 = g_Weff2[o*3], w1v = g_Weff2[o*3+1], w2v = g_Weff2[o*3+2];
    double bo = b2[o];
    double wEg = w0*Ex + w1v*Ey + w2v*Ez;
    double m = wEg + bo;
    double Ex2 = w0*w0*Mxx + w1v*w1v*Myy + w2v*w2v*Mzz
               + 2.0*(w0*w1v*Mxy + w0*w2v*Mxz + w1v*w2v*Myz)
               + 2.0*bo*wEg + bo*bo;
    double var = Ex2 - m*m;
    double s = (double)g1[o] / sqrt(var + EPSf);
    g_A1[o*3+0] = (float)(s*w0);
    g_A1[o*3+1] = (float)(s*w1v);
    g_A1[o*3+2] = (float)(s*w2v);
    g_c1v[o] = (float)((double)b1[o] + s*(bo - m));
}

// ---------------- pooled: P[tile][c] = tf32(max_k relu(A1.xyz + c1)) ----------------
__global__ void pgenk() {
    __shared__ float gsh[48];
    int t = threadIdx.x;
    float a0 = g_A1[t*3], a1 = g_A1[t*3+1], a2 = g_A1[t*3+2], c1 = g_c1v[t];
    for (int it = 0; it < 8; it++) {
        int tile = blockIdx.x*8 + it;
        __syncthreads();
        if (t < 48) gsh[t] = g_grouped[tile*48 + t];
        __syncthreads();
        float mx = 0.0f;
        #pragma unroll
        for (int k = 0; k < KN; k++)
            mx = fmaxf(mx, fmaxf(0.0f, fmaf(a0, gsh[k*3], fmaf(a1, gsh[k*3+1], fmaf(a2, gsh[k*3+2], c1)))));
        g_P[(size_t)tile*256 + t] = tf(mx);
    }
}

// ================= GEMM1: Z[j][o] = sum_c w3[o][c]*Baug[j][c]; Z -> fp16 =================
// CTA 128o x 128j, K=512; 8 warps, warp tile 32x64; cp.async pipeline.
#define G1_SMEM 73216
__global__ __launch_bounds__(256, 2) void tcg1() {
    extern __shared__ __align__(16) float smf[];
    uint32_t sb = smem_u32(smf);
    int t = threadIdx.x, lane = t & 31, wid = t >> 5;
    int wm = wid & 3, wn = wid >> 2;
    int j0 = blockIdx.x * 128, o0 = blockIdx.y * 128;
    float* sXYZ = smf + 16896;
    float* sA0 = smf + 17280;
    float* sA1p = sA0 + 256; float* sA2p = sA0 + 512; float* sCp = sA0 + 768;

    for (int i = t; i < 384; i += 256) sXYZ[i] = g_grouped[(size_t)j0*3 + i];
    sA0[t] = g_A1[t*3]; sA1p[t] = g_A1[t*3+1]; sA2p[t] = g_A1[t*3+2]; sCp[t] = g_c1v[t];

    float acc[2][8][4];
    #pragma unroll
    for (int mf = 0; mf < 2; mf++)
        #pragma unroll
        for (int nf = 0; nf < 8; nf++)
            #pragma unroll
            for (int e = 0; e < 4; e++) acc[mf][nf][e] = 0.0f;

    int t0 = j0 >> 4;

    auto issue = [&](int buf, int kc) {
        int c0 = kc*32;
        uint32_t abb = sb + buf*16384;
        #pragma unroll
        for (int i = 0; i < 4; i++) {
            int slot = t + 256*i; int o = slot >> 3, chR = slot & 7;
            CPA(abb + o*128 + ((chR ^ (o & 7)) << 4),
                &g_w3r[(size_t)(o0+o)*512 + c0 + chR*4]);
        }
        if (kc < 8) {
            uint32_t bbb = sb + 32768 + buf*16384;
            #pragma unroll
            for (int i = 0; i < 4; i++) {
                int slot = t + 256*i; int j = slot >> 3, chR = slot & 7;
                CPA(bbb + j*128 + ((chR ^ (j & 7)) << 4),
                    &g_P[(size_t)(t0 + (j >> 4))*256 + c0 + chR*4]);
            }
        } else {
            float* Bp = smf + 8192 + buf*4096;
            int cb = c0 - 256;
            #pragma unroll
            for (int i = 0; i < 4; i++) {
                int slot = t + 256*i; int j = slot >> 3, chR = slot & 7;
                float x = sXYZ[j*3], y = sXYZ[j*3+1], z = sXYZ[j*3+2];
                int c = cb + chR*4;
                float4 v;
                v.x = tf(fmaxf(0.f, fmaf(sA0[c+0], x, fmaf(sA1p[c+0], y, fmaf(sA2p[c+0], z, sCp[c+0])))));
                v.y = tf(fmaxf(0.f, fmaf(sA0[c+1], x, fmaf(sA1p[c+1], y, fmaf(sA2p[c+1], z, sCp[c+1])))));
                v.z = tf(fmaxf(0.f, fmaf(sA0[c+2], x, fmaf(sA1p[c+2], y, fmaf(sA2p[c+2], z, sCp[c+2])))));
                v.w = tf(fmaxf(0.f, fmaf(sA0[c+3], x, fmaf(sA1p[c+3], y, fmaf(sA2p[c+3], z, sCp[c+3])))));
                *(float4*)&Bp[j*32 + ((chR ^ (j & 7)) << 2)] = v;
            }
        }
        CPA_COMMIT();
    };

    auto compute = [&](int buf) {
        uint32_t abase = sb + buf*16384;
        uint32_t bbase = sb + 32768 + buf*16384;
        int t7 = lane & 7, mi = lane >> 3;
        #pragma unroll
        for (int s = 0; s < 4; s++) {
            uint32_t a[2][4], b[8][2];
            #pragma unroll
            for (int mf = 0; mf < 2; mf++) {
                int row = wm*32 + mf*16 + ((mi & 1) << 3) + t7;
                int ch = 2*s + (mi >> 1);
                LDM4(a[mf][0], a[mf][1], a[mf][2], a[mf][3],
                     abase + row*128 + ((ch ^ (row & 7)) << 4));
            }
            #pragma unroll
            for (int np = 0; np < 4; np++) {
                int row = wn*64 + np*16 + ((mi >> 1) << 3) + t7;
                int ch = 2*s + (mi & 1);
                LDM4(b[2*np][0], b[2*np][1], b[2*np+1][0], b[2*np+1][1],
                     bbase + row*128 + ((ch ^ (row & 7)) << 4));
            }
            #pragma unroll
            for (int mf = 0; mf < 2; mf++)
                #pragma unroll
                for (int nf = 0; nf < 8; nf++)
                    MMA8(acc[mf][nf], a[mf], b[nf]);
        }
    };

    __syncthreads();                // sXYZ/params visible (H-gen reads them in issue)
    issue(0, 0);
    for (int kc = 0; kc < 16; kc++) {
        int cur = kc & 1;
        CPA_WAIT0();
        __syncthreads();
        if (kc < 15) issue(cur ^ 1, kc + 1);
        compute(cur);
    }
    __syncthreads();                // all compute done before T overwrites A/B buffers

    // stats via quad shuffles
    int t4 = lane & 3, gr = lane >> 2;
    #pragma unroll
    for (int mf = 0; mf < 2; mf++)
        #pragma unroll
        for (int rs = 0; rs < 2; rs++) {
            double s = 0.0, q = 0.0;
            #pragma unroll
            for (int nf = 0; nf < 8; nf++) {
                float v0 = acc[mf][nf][rs*2], v1 = acc[mf][nf][rs*2+1];
                s += (double)v0 + (double)v1;
                q += (double)v0*(double)v0 + (double)v1*(double)v1;
            }
            s += __shfl_xor_sync(0xffffffffu, s, 1); s += __shfl_xor_sync(0xffffffffu, s, 2);
            q += __shfl_xor_sync(0xffffffffu, q, 1); q += __shfl_xor_sync(0xffffffffu, q, 2);
            if (t4 == 0) {
                int o = o0 + wm*32 + mf*16 + rs*8 + gr;
                atomicAdd(&g_bn3sum[o], s); atomicAdd(&g_bn3sq[o], q);
            }
        }

    // transpose through smem (pad 132) then coalesced fp16 store
    float* T = smf;
    #pragma unroll
    for (int mf = 0; mf < 2; mf++)
        #pragma unroll
        for (int nf = 0; nf < 8; nf++) {
            int orw = wm*32 + mf*16 + gr;
            int jl = wn*64 + nf*8 + 2*t4;
            T[jl*132 + orw]       = acc[mf][nf][0];
            T[(jl+1)*132 + orw]   = acc[mf][nf][1];
            T[jl*132 + orw + 8]   = acc[mf][nf][2];
            T[(jl+1)*132 + orw+8] = acc[mf][nf][3];
        }
    __syncthreads();
    int cg16 = t & 15, rr = t >> 4;
    #pragma unroll
    for (int r = 0; r < 8; r++) {
        int row = rr + 16*r;
        float4 v0 = *(float4*)&T[row*132 + cg16*8];
        float4 v1 = *(float4*)&T[row*132 + cg16*8 + 4];
        __half h[8];
        h[0] = __float2half_rn(v0.x); h[1] = __float2half_rn(v0.y);
        h[2] = __float2half_rn(v0.z); h[3] = __float2half_rn(v0.w);
        h[4] = __float2half_rn(v1.x); h[5] = __float2half_rn(v1.y);
        h[6] = __float2half_rn(v1.z); h[7] = __float2half_rn(v1.w);
        *(uint4*)&g_Zh[(size_t)(j0+row)*512 + o0 + cg16*8] = *(uint4*)h;
    }
}

// ================= GEMM2: stats + max_k of w4 @ relu(bn3(Z)) =================
// CTA 256o x 128j, K=512; 8 warps, warp tile 64x64; cp.async A, reg-prefetch B.
#define G2_SMEM 102400
__global__ __launch_bounds__(256, 1) void tcg2() {
    extern __shared__ __align__(16) float smf[];
    uint32_t sb = smem_u32(smf);
    int t = threadIdx.x, lane = t & 31, wid = t >> 5;
    int wm = wid & 3, wn = wid >> 2;
    int j0 = blockIdx.x * 128;
    float* sa3 = smf + 24576;
    float* sd3 = sa3 + 512;
    for (int i = t; i < 512; i += 256) { sa3[i] = g_a3[i]; sd3[i] = g_d3[i]; }

    float acc[4][8][4];
    #pragma unroll
    for (int mf = 0; mf < 4; mf++)
        #pragma unroll
        for (int nf = 0; nf < 8; nf++)
            #pragma unroll
            for (int e = 0; e < 4; e++) acc[mf][nf][e] = 0.0f;

    auto issueA = [&](int buf, int kc) {
        int c0 = kc*32;
        uint32_t abb = sb + buf*32768;
        #pragma unroll
        for (int i = 0; i < 8; i++) {
            int slot = t + 256*i; int o = slot >> 3, chR = slot & 7;
            CPA(abb + o*128 + ((chR ^ (o & 7)) << 4),
                &g_w4r[(size_t)o*512 + c0 + chR*4]);
        }
        CPA_COMMIT();
    };
    auto loadB = [&](int kc, uint4* br) {
        #pragma unroll
        for (int i = 0; i < 2; i++) {
            int slot = t*2 + i;
            int j = slot >> 2, cg = slot & 3;
            br[i] = *(const uint4*)&g_Zh[(size_t)(j0+j)*512 + kc*32 + cg*8];
        }
    };
    auto storeB = [&](int buf, int kc, const uint4* br) {
        float* Bp = smf + 16384 + buf*4096;
        #pragma unroll
        for (int i = 0; i < 2; i++) {
            int slot = t*2 + i;
            int j = slot >> 2, cg = slot & 3;
            const __half* h = (const __half*)&br[i];
            int c = kc*32 + cg*8;
            float v[8];
            #pragma unroll
            for (int e = 0; e < 8; e++)
                v[e] = tf(fmaxf(0.f, fmaf(__half2float(h[e]), sa3[c+e], sd3[c+e])));
            int chR = cg*2;
            *(float4*)&Bp[j*32 + ((chR ^ (j&7)) << 2)]       = make_float4(v[0],v[1],v[2],v[3]);
            *(float4*)&Bp[j*32 + (((chR+1) ^ (j&7)) << 2)]   = make_float4(v[4],v[5],v[6],v[7]);
        }
    };
    auto compute = [&](int buf) {
        uint32_t abase = sb + buf*32768;
        uint32_t bbase = sb + 65536 + buf*16384;
        int t7 = lane & 7, mi = lane >> 3;
        #pragma unroll
        for (int s = 0; s < 4; s++) {
            uint32_t a[4][4], b[8][2];
            #pragma unroll
            for (int mf = 0; mf < 4; mf++) {
                int row = wm*64 + mf*16 + ((mi & 1) << 3) + t7;
                int ch = 2*s + (mi >> 1);
                LDM4(a[mf][0], a[mf][1], a[mf][2], a[mf][3],
                     abase + row*128 + ((ch ^ (row & 7)) << 4));
            }
            #pragma unroll
            for (int np = 0; np < 4; np++) {
                int row = wn*64 + np*16 + ((mi >> 1) << 3) + t7;
                int ch = 2*s + (mi & 1);
                LDM4(b[2*np][0], b[2*np][1], b[2*np+1][0], b[2*np+1][1],
                     bbase + row*128 + ((ch ^ (row & 7)) << 4));
            }
            #pragma unroll
            for (int mf = 0; mf < 4; mf++)
                #pragma unroll
                for (int nf = 0; nf < 8; nf++)
                    MMA8(acc[mf][nf], a[mf], b[nf]);
        }
    };

    __syncthreads();                // sa3/sd3 visible
    issueA(0, 0);
    {
        uint4 br0[2];
        loadB(0, br0);
        storeB(0, 0, br0);
    }
    uint4 br[2];
    for (int kc = 0; kc < 16; kc++) {
        int cur = kc & 1;
        CPA_WAIT0();
        __syncthreads();
        if (kc < 15) { issueA(cur ^ 1, kc + 1); loadB(kc + 1, br); }
        compute(cur);
        if (kc < 15) storeB(cur ^ 1, kc + 1, br);
    }

    int t4 = lane & 3, gr = lane >> 2;
    int jt0 = (j0 >> 4) + wn*4;
    #pragma unroll
    for (int mf = 0; mf < 4; mf++)
        #pragma unroll
        for (int rs = 0; rs < 2; rs++) {
            int o = wm*64 + mf*16 + rs*8 + gr;
            double s = 0.0, q = 0.0;
            #pragma unroll
            for (int nf = 0; nf < 8; nf++) {
                float v0 = acc[mf][nf][rs*2], v1 = acc[mf][nf][rs*2+1];
                s += (double)v0 + (double)v1;
                q += (double)v0*(double)v0 + (double)v1*(double)v1;
            }
            s += __shfl_xor_sync(0xffffffffu, s, 1); s += __shfl_xor_sync(0xffffffffu, s, 2);
            q += __shfl_xor_sync(0xffffffffu, q, 1); q += __shfl_xor_sync(0xffffffffu, q, 2);
            if (t4 == 0) { atomicAdd(&g_bn4sum[o], s); atomicAdd(&g_bn4sq[o], q); }
            #pragma unroll
            for (int tt = 0; tt < 4; tt++) {
                float m = fmaxf(fmaxf(acc[mf][2*tt][rs*2], acc[mf][2*tt][rs*2+1]),
                                fmaxf(acc[mf][2*tt+1][rs*2], acc[mf][2*tt+1][rs*2+1]));
                m = fmaxf(m, __shfl_xor_sync(0xffffffffu, m, 1));
                m = fmaxf(m, __shfl_xor_sync(0xffffffffu, m, 2));
                if (t4 == 0) g_M4[(size_t)(jt0 + tt)*256 + o] = m;
            }
        }
}

// ---------------- BN affine params ----------------
__global__ void bn3aff(const float* __restrict__ g, const float* __restrict__ b) {
    int c = threadIdx.x;
    if (c >= 512) return;
    double inv = 1.0 / (double)JJ;
    double m = g_bn3sum[c]*inv;
    double var = g_bn3sq[c]*inv - m*m;
    float a = (float)((double)g[c] / sqrt(var + EPSf));
    g_a3[c] = a;
    g_d3[c] = b[c] - (float)m * a;
}
__global__ void bn4aff(const float* __restrict__ g, const float* __restrict__ b) {
    int c = threadIdx.x;
    if (c >= 256) return;
    double inv = 1.0 / (double)JJ;
    double m = g_bn4sum[c]*inv;
    double var = g_bn4sq[c]*inv - m*m;
    float a = (float)((double)g[c] / sqrt(var + EPSf));
    g_a4[c] = a;
    g_d4[c] = b[c] - (float)m * a;
}

// ---------------- final: feat[b][o][ns] = relu(a4*M4 + d4)  (a4>0) ----------------
__global__ void finalk(float* __restrict__ out) {
    __shared__ float sm[32*257];
    int b = blockIdx.x >> 4, chunk = blockIdx.x & 15, t = threadIdx.x;
    int tile0 = b*512 + chunk*32;
    for (int i = t; i < 8192; i += 256) {
        int tl = i >> 8, o = i & 255;
        sm[tl*257 + o] = g_M4[(size_t)(tile0 + tl)*256 + o];
    }
    __syncthreads();
    int nsl = t & 31, og = t >> 5;
    for (int pass = 0; pass < 32; pass++) {
        int o = pass*8 + og;
        float a = g_a4[o], d = g_d4[o];
        float v = fmaxf(0.0f, fmaf(sm[nsl*257 + o], a, d));
        out[Bb*NSd*3 + b*131072 + o*512 + chunk*32 + nsl] = v;
    }
}

// ---------------- launch ----------------
extern "C" void kernel_launch(void* const* d_in, const int* in_sizes, int n_in,
                              void* d_out, int out_size) {
    const float* p    = (const float*)d_in[0];
    const float* w1   = (const float*)d_in[1];
    const float* w2   = (const float*)d_in[2];
    const float* b2   = (const float*)d_in[3];
    const float* bn1g = (const float*)d_in[4];
    const float* bn1b = (const float*)d_in[5];
    const float* w3   = (const float*)d_in[6];
    const float* bn3g = (const float*)d_in[7];
    const float* bn3b = (const float*)d_in[8];
    const float* w4   = (const float*)d_in[9];
    const float* bn4g = (const float*)d_in[10];
    const float* bn4b = (const float*)d_in[11];
    float* out = (float*)d_out;

    cudaFuncSetAttribute(tcg1, cudaFuncAttributeMaxDynamicSharedMemorySize, G1_SMEM);
    cudaFuncSetAttribute(tcg2, cudaFuncAttributeMaxDynamicSharedMemorySize, G2_SMEM);

    zerok<<<1, 512>>>();
    precompk<<<1, 256>>>(w1, w2);
    roundwk<<<512, 512>>>(w3, w4);
    fpsk<<<32, 512>>>(p, out);                 // centroids -> out[0:49152]
    knnk<<<256, 64>>>(p, out);
    bn1k<<<1, 256>>>(b2, bn1g, bn1b);
    pgenk<<<NT/8, 256>>>();
    tcg1<<<dim3(JJ/128, 4), 256, G1_SMEM>>>();
    bn3aff<<<1, 512>>>(bn3g, bn3b);
    tcg2<<<JJ/128, 256, G2_SMEM>>>();
    bn4aff<<<1, 256>>>(bn4g, bn4b);
    finalk<<<Bb*16, 256>>>(out);
}

// round 11
// speedup vs baseline: 2.5561x; 1.1147x over previous
#include <cuda_runtime.h>
#include <cuda_fp16.h>
#include <cstdint>

#define Bb 32
#define Np 2048
#define NSd 512
#define KN 16
#define NT (Bb*NSd)          // 16384 tiles
#define JJ (NT*KN)           // 262144 columns
#define EPSf 1e-5

// ---------------- scratch ----------------
__device__ float  g_grouped[NT*KN*3];
__device__ double g_sum9[9];
__device__ float  g_Weff2[256*3];
__device__ float  g_A1[256*3];
__device__ float  g_c1v[256];
__device__ __half g_Ph [NT*256];               // pooled [tile][c] fp16
__device__ __half g_w3h[512*512];              // fp16 w3
__device__ __half g_w4h[256*512];              // fp16 w4
__device__ __half g_Zh[(size_t)JJ*512];        // 268 MB  [j][c] fp16
__device__ float  g_M4[NT*256];                // max_k conv4-out [tile][o]
__device__ double g_bn3sum[512], g_bn3sq[512], g_bn4sum[256], g_bn4sq[256];
__device__ float  g_a3[512], g_d3[512], g_a4[256], g_d4[256];

// ---------------- helpers ----------------
__device__ __forceinline__ uint32_t smem_u32(const void* p) {
    uint32_t a;
    asm("{ .reg .u64 t; cvta.to.shared.u64 t, %1; cvt.u32.u64 %0, t; }" : "=r"(a) : "l"(p));
    return a;
}
#define LDM4(r0,r1,r2,r3,addr) \
    asm volatile("ldmatrix.sync.aligned.m8n8.x4.shared.b16 {%0,%1,%2,%3}, [%4];" \
        : "=r"(r0),"=r"(r1),"=r"(r2),"=r"(r3) : "r"(addr))
#define MMA16(c, a, b) \
    asm volatile("mma.sync.aligned.m16n8k16.row.col.f32.f16.f16.f32 " \
        "{%0,%1,%2,%3}, {%4,%5,%6,%7}, {%8,%9}, {%0,%1,%2,%3};" \
        : "+f"((c)[0]),"+f"((c)[1]),"+f"((c)[2]),"+f"((c)[3]) \
        : "r"((a)[0]),"r"((a)[1]),"r"((a)[2]),"r"((a)[3]), "r"((b)[0]),"r"((b)[1]))
#define CPA(dst, src) asm volatile("cp.async.cg.shared.global [%0], [%1], 16;" ::"r"(dst),"l"(src))
#define CPA_COMMIT()  asm volatile("cp.async.commit_group;" ::: "memory")
#define CPA_WAIT0()   asm volatile("cp.async.wait_group 0;" ::: "memory")

// ---------------- zero accumulators (graph replays!) ----------------
__global__ void zerok() {
    int t = threadIdx.x;
    if (t < 9) g_sum9[t] = 0.0;
    for (int i = t; i < 512; i += blockDim.x) { g_bn3sum[i] = 0.0; g_bn3sq[i] = 0.0; }
    for (int i = t; i < 256; i += blockDim.x) { g_bn4sum[i] = 0.0; g_bn4sq[i] = 0.0; }
}

__global__ void precompk(const float* __restrict__ w1, const float* __restrict__ w2) {
    int t = threadIdx.x;
    if (t < 256) {
        double s0 = 0.0, s1 = 0.0, s2 = 0.0;
        for (int i = 0; i < 256; i++) {
            double wi = (double)w2[t*256 + i];
            s0 += wi * ((double)w1[i*6+0] + (double)w1[i*6+3]);
            s1 += wi * ((double)w1[i*6+1] + (double)w1[i*6+4]);
            s2 += wi * ((double)w1[i*6+2] + (double)w1[i*6+5]);
        }
        g_Weff2[t*3+0] = (float)s0; g_Weff2[t*3+1] = (float)s1; g_Weff2[t*3+2] = (float)s2;
    }
}

// pre-round weights to fp16
__global__ void roundwk(const float* __restrict__ w3, const float* __restrict__ w4) {
    int i = blockIdx.x*512 + threadIdx.x;
    if (i < 512*512) g_w3h[i] = __float2half_rn(w3[i]);
    if (i < 256*512) g_w4h[i] = __float2half_rn(w4[i]);
}

// ---------------- FPS: 32 blocks x 128 threads, 16 pts/thread, 1 barrier/step ----------------
__global__ void fpsk(const float* __restrict__ p, float* __restrict__ outc) {
    __shared__ float sp[Np*3];
    __shared__ unsigned long long skey[2][4];
    int b = blockIdx.x, t = threadIdx.x;
    for (int i = t; i < Np*3; i += 128) sp[i] = p[b*Np*3 + i];
    __syncthreads();
    float px[16], py[16], pz[16], dist[16];
    #pragma unroll
    for (int i = 0; i < 16; i++) {
        int n = t + 128*i;
        px[i] = sp[n*3+0]; py[i] = sp[n*3+1]; pz[i] = sp[n*3+2];
        dist[i] = 1e10f;
    }
    int lane = t & 31, wid = t >> 5;
    int cs = 0;
    for (int s = 0; s < NSd; s++) {
        if (t == 0) {
            outc[(b*NSd + s)*3 + 0] = sp[cs*3+0];
            outc[(b*NSd + s)*3 + 1] = sp[cs*3+1];
            outc[(b*NSd + s)*3 + 2] = sp[cs*3+2];
        }
        float cx = sp[cs*3+0], cy = sp[cs*3+1], cz = sp[cs*3+2];
        unsigned long long best = 0ull;
        #pragma unroll
        for (int i = 0; i < 16; i++) {
            float dx = __fadd_rn(px[i], -cx);
            float dy = __fadd_rn(py[i], -cy);
            float dz = __fadd_rn(pz[i], -cz);
            float d = __fadd_rn(__fadd_rn(__fmul_rn(dx,dx), __fmul_rn(dy,dy)), __fmul_rn(dz,dz));
            dist[i] = fminf(dist[i], d);
            unsigned long long key = ((unsigned long long)__float_as_uint(dist[i]) << 32)
                                   | (unsigned)(Np - 1 - (t + 128*i));
            best = max(best, key);
        }
        #pragma unroll
        for (int off = 16; off; off >>= 1)
            best = max(best, __shfl_down_sync(0xffffffffu, best, off));
        if (lane == 0) skey[s & 1][wid] = best;
        __syncthreads();
        unsigned long long k2 = max(max(skey[s&1][0], skey[s&1][1]),
                                    max(skey[s&1][2], skey[s&1][3]));
        cs = Np - 1 - (int)(unsigned)(k2 & 0xffffffffull);
    }
}

// ---------------- kNN: 256 blocks x 64 threads ----------------
__global__ void knnk(const float* __restrict__ p, const float* __restrict__ cntrd) {
    __shared__ float shp[Np*3];
    __shared__ float sp2[Np];
    __shared__ double s9[9];
    int t = threadIdx.x;
    int gc = blockIdx.x*64 + t;
    int b = blockIdx.x >> 3;
    for (int i = t; i < Np*3; i += 64) shp[i] = p[b*Np*3 + i];
    if (t < 9) s9[t] = 0.0;
    __syncthreads();
    for (int n = t; n < Np; n += 64) {
        float x = shp[n*3], y = shp[n*3+1], z = shp[n*3+2];
        sp2[n] = __fadd_rn(__fadd_rn(__fmul_rn(x,x), __fmul_rn(y,y)), __fmul_rn(z,z));
    }
    __syncthreads();
    float cx = cntrd[gc*3+0], cy = cntrd[gc*3+1], cz = cntrd[gc*3+2];
    float c2 = __fadd_rn(__fadd_rn(__fmul_rn(cx,cx), __fmul_rn(cy,cy)), __fmul_rn(cz,cz));
    float hd[KN]; int hi[KN];
    #pragma unroll
    for (int k = 0; k < KN; k++) { hd[k] = 3.4e38f; hi[k] = 0; }
    for (int n = 0; n < Np; n++) {
        float dot = __fadd_rn(__fadd_rn(__fmul_rn(cx, shp[n*3]),
                                        __fmul_rn(cy, shp[n*3+1])),
                              __fmul_rn(cz, shp[n*3+2]));
        float d2 = __fadd_rn(__fadd_rn(c2, sp2[n]), -__fmul_rn(2.0f, dot));
        if (d2 < hd[KN-1]) {
            hd[KN-1] = d2; hi[KN-1] = n;
            #pragma unroll
            for (int j = KN-1; j > 0; --j) {
                bool sw = hd[j] < hd[j-1];
                float td = hd[j]; int ti = hi[j];
                float tdm = hd[j-1]; int tim = hi[j-1];
                hd[j]   = sw ? tdm : td;   hi[j]   = sw ? tim : ti;
                hd[j-1] = sw ? td  : tdm;  hi[j-1] = sw ? ti  : tim;
            }
        }
    }
    double sx=0, sy=0, sz=0, sxx=0, syy=0, szz=0, sxy=0, sxz=0, syz=0;
    #pragma unroll
    for (int k = 0; k < KN; k++) {
        int n = hi[k];
        float x = shp[n*3], y = shp[n*3+1], z = shp[n*3+2];
        g_grouped[(gc*KN + k)*3 + 0] = x;
        g_grouped[(gc*KN + k)*3 + 1] = y;
        g_grouped[(gc*KN + k)*3 + 2] = z;
        sx += x; sy += y; sz += z;
        sxx += (double)x*x; syy += (double)y*y; szz += (double)z*z;
        sxy += (double)x*y; sxz += (double)x*z; syz += (double)y*z;
    }
    atomicAdd(&s9[0], sx);  atomicAdd(&s9[1], sy);  atomicAdd(&s9[2], sz);
    atomicAdd(&s9[3], sxx); atomicAdd(&s9[4], syy); atomicAdd(&s9[5], szz);
    atomicAdd(&s9[6], sxy); atomicAdd(&s9[7], sxz); atomicAdd(&s9[8], syz);
    __syncthreads();
    if (t < 9) atomicAdd(&g_sum9[t], s9[t]);
}

// ---------------- BN1 affine from analytic moments ----------------
__global__ void bn1k(const float* __restrict__ b2, const float* __restrict__ g1,
                     const float* __restrict__ b1) {
    int o = threadIdx.x;
    if (o >= 256) return;
    double inv = 1.0 / (double)JJ;
    double Ex = g_sum9[0]*inv, Ey = g_sum9[1]*inv, Ez = g_sum9[2]*inv;
    double Mxx = g_sum9[3]*inv, Myy = g_sum9[4]*inv, Mzz = g_sum9[5]*inv;
    double Mxy = g_sum9[6]*inv, Mxz = g_sum9[7]*inv, Myz = g_sum9[8]*inv;
    double w0 = g_Weff2[o*3], w1v = g_Weff2[o*3+1], w2v = g_Weff2[o*3+2];
    double bo = b2[o];
    double wEg = w0*Ex + w1v*Ey + w2v*Ez;
    double m = wEg + bo;
    double Ex2 = w0*w0*Mxx + w1v*w1v*Myy + w2v*w2v*Mzz
               + 2.0*(w0*w1v*Mxy + w0*w2v*Mxz + w1v*w2v*Myz)
               + 2.0*bo*wEg + bo*bo;
    double var = Ex2 - m*m;
    double s = (double)g1[o] / sqrt(var + EPSf);
    g_A1[o*3+0] = (float)(s*w0);
    g_A1[o*3+1] = (float)(s*w1v);
    g_A1[o*3+2] = (float)(s*w2v);
    g_c1v[o] = (float)((double)b1[o] + s*(bo - m));
}

// ---------------- pooled: Ph[tile][c] = fp16(max_k relu(A1.xyz + c1)) ----------------
__global__ void pgenk() {
    __shared__ float gsh[48];
    int t = threadIdx.x;
    float a0 = g_A1[t*3], a1 = g_A1[t*3+1], a2 = g_A1[t*3+2], c1 = g_c1v[t];
    for (int it = 0; it < 8; it++) {
        int tile = blockIdx.x*8 + it;
        __syncthreads();
        if (t < 48) gsh[t] = g_grouped[tile*48 + t];
        __syncthreads();
        float mx = 0.0f;
        #pragma unroll
        for (int k = 0; k < KN; k++)
            mx = fmaxf(mx, fmaxf(0.0f, fmaf(a0, gsh[k*3], fmaf(a1, gsh[k*3+1], fmaf(a2, gsh[k*3+2], c1)))));
        g_Ph[(size_t)tile*256 + t] = __float2half_rn(mx);
    }
}

// ================= GEMM1 (fp16 m16n8k16): Z[j][o] = sum_c w3[o][c]*Baug[j][c] =================
// CTA 128o x 128j, K=512 in 8 chunks of 64; 8 warps, warp tile 32x64.
#define G1_SMEM 71168
__global__ __launch_bounds__(256, 2) void tcg1() {
    extern __shared__ __align__(16) char smc[];
    float* smf = (float*)smc;
    uint32_t sb = smem_u32(smc);
    int t = threadIdx.x, lane = t & 31, wid = t >> 5;
    int wm = wid & 3, wn = wid >> 2;
    int j0 = blockIdx.x * 128, o0 = blockIdx.y * 128;
    float* sXYZ = (float*)(smc + 65536);
    float* sA0 = (float*)(smc + 67072);
    float* sA1p = sA0 + 256; float* sA2p = sA0 + 512; float* sCp = sA0 + 768;

    for (int i = t; i < 384; i += 256) sXYZ[i] = g_grouped[(size_t)j0*3 + i];
    sA0[t] = g_A1[t*3]; sA1p[t] = g_A1[t*3+1]; sA2p[t] = g_A1[t*3+2]; sCp[t] = g_c1v[t];

    float acc[2][8][4];
    #pragma unroll
    for (int mf = 0; mf < 2; mf++)
        #pragma unroll
        for (int nf = 0; nf < 8; nf++)
            #pragma unroll
            for (int e = 0; e < 4; e++) acc[mf][nf][e] = 0.0f;

    int t0 = j0 >> 4;

    auto issue = [&](int buf, int kc) {
        uint32_t abb = sb + buf*16384;
        #pragma unroll
        for (int i = 0; i < 4; i++) {
            int slot = t + 256*i; int o = slot >> 3, chR = slot & 7;
            CPA(abb + o*128 + ((chR ^ (o & 7)) << 4),
                &g_w3h[(size_t)(o0+o)*512 + kc*64 + chR*8]);
        }
        if (kc < 4) {
            uint32_t bbb = sb + 32768 + buf*16384;
            #pragma unroll
            for (int i = 0; i < 4; i++) {
                int slot = t + 256*i; int j = slot >> 3, chR = slot & 7;
                CPA(bbb + j*128 + ((chR ^ (j & 7)) << 4),
                    &g_Ph[(size_t)(t0 + (j >> 4))*256 + kc*64 + chR*8]);
            }
        } else {
            char* Bp = smc + 32768 + buf*16384;
            int cb = (kc - 4)*64;
            #pragma unroll
            for (int i = 0; i < 4; i++) {
                int slot = t + 256*i; int j = slot >> 3, chR = slot & 7;
                float x = sXYZ[j*3], y = sXYZ[j*3+1], z = sXYZ[j*3+2];
                int c = cb + chR*8;
                __half h[8];
                #pragma unroll
                for (int e = 0; e < 8; e++)
                    h[e] = __float2half_rn(fmaxf(0.f,
                        fmaf(sA0[c+e], x, fmaf(sA1p[c+e], y, fmaf(sA2p[c+e], z, sCp[c+e])))));
                *(uint4*)(Bp + j*128 + ((chR ^ (j & 7)) << 4)) = *(uint4*)h;
            }
        }
        CPA_COMMIT();
    };

    auto compute = [&](int buf) {
        uint32_t abase = sb + buf*16384;
        uint32_t bbase = sb + 32768 + buf*16384;
        int t7 = lane & 7, mi = lane >> 3;
        #pragma unroll
        for (int s = 0; s < 4; s++) {
            uint32_t a[2][4], b[8][2];
            #pragma unroll
            for (int mf = 0; mf < 2; mf++) {
                int row = wm*32 + mf*16 + ((mi & 1) << 3) + t7;
                int ch = 2*s + (mi >> 1);
                LDM4(a[mf][0], a[mf][1], a[mf][2], a[mf][3],
                     abase + row*128 + ((ch ^ (row & 7)) << 4));
            }
            #pragma unroll
            for (int np = 0; np < 4; np++) {
                int row = wn*64 + np*16 + ((mi >> 1) << 3) + t7;
                int ch = 2*s + (mi & 1);
                LDM4(b[2*np][0], b[2*np][1], b[2*np+1][0], b[2*np+1][1],
                     bbase + row*128 + ((ch ^ (row & 7)) << 4));
            }
            #pragma unroll
            for (int mf = 0; mf < 2; mf++)
                #pragma unroll
                for (int nf = 0; nf < 8; nf++)
                    MMA16(acc[mf][nf], a[mf], b[nf]);
        }
    };

    __syncthreads();
    issue(0, 0);
    for (int kc = 0; kc < 8; kc++) {
        int cur = kc & 1;
        CPA_WAIT0();
        __syncthreads();
        if (kc < 7) issue(cur ^ 1, kc + 1);
        compute(cur);
    }
    __syncthreads();

    // stats via quad shuffles
    int t4 = lane & 3, gr = lane >> 2;
    #pragma unroll
    for (int mf = 0; mf < 2; mf++)
        #pragma unroll
        for (int rs = 0; rs < 2; rs++) {
            double s = 0.0, q = 0.0;
            #pragma unroll
            for (int nf = 0; nf < 8; nf++) {
                float v0 = acc[mf][nf][rs*2], v1 = acc[mf][nf][rs*2+1];
                s += (double)v0 + (double)v1;
                q += (double)v0*(double)v0 + (double)v1*(double)v1;
            }
            s += __shfl_xor_sync(0xffffffffu, s, 1); s += __shfl_xor_sync(0xffffffffu, s, 2);
            q += __shfl_xor_sync(0xffffffffu, q, 1); q += __shfl_xor_sync(0xffffffffu, q, 2);
            if (t4 == 0) {
                int o = o0 + wm*32 + mf*16 + rs*8 + gr;
                atomicAdd(&g_bn3sum[o], s); atomicAdd(&g_bn3sq[o], q);
            }
        }

    // transpose through smem (pad 132) then coalesced fp16 store
    float* T = smf;
    #pragma unroll
    for (int mf = 0; mf < 2; mf++)
        #pragma unroll
        for (int nf = 0; nf < 8; nf++) {
            int orw = wm*32 + mf*16 + gr;
            int jl = wn*64 + nf*8 + 2*t4;
            T[jl*132 + orw]       = acc[mf][nf][0];
            T[(jl+1)*132 + orw]   = acc[mf][nf][1];
            T[jl*132 + orw + 8]   = acc[mf][nf][2];
            T[(jl+1)*132 + orw+8] = acc[mf][nf][3];
        }
    __syncthreads();
    int cg16 = t & 15, rr = t >> 4;
    #pragma unroll
    for (int r = 0; r < 8; r++) {
        int row = rr + 16*r;
        float4 v0 = *(float4*)&T[row*132 + cg16*8];
        float4 v1 = *(float4*)&T[row*132 + cg16*8 + 4];
        __half h[8];
        h[0] = __float2half_rn(v0.x); h[1] = __float2half_rn(v0.y);
        h[2] = __float2half_rn(v0.z); h[3] = __float2half_rn(v0.w);
        h[4] = __float2half_rn(v1.x); h[5] = __float2half_rn(v1.y);
        h[6] = __float2half_rn(v1.z); h[7] = __float2half_rn(v1.w);
        *(uint4*)&g_Zh[(size_t)(j0+row)*512 + o0 + cg16*8] = *(uint4*)h;
    }
}

// ================= GEMM2 (fp16 m16n8k16): stats + max_k of w4 @ relu(bn3(Z)) =================
// CTA 256o x 128j, K=512 in 8 chunks of 64; 8 warps, warp tile 64x64.
#define G2_SMEM 102400
__global__ __launch_bounds__(256, 1) void tcg2() {
    extern __shared__ __align__(16) char smc[];
    uint32_t sb = smem_u32(smc);
    int t = threadIdx.x, lane = t & 31, wid = t >> 5;
    int wm = wid & 3, wn = wid >> 2;
    int j0 = blockIdx.x * 128;
    float* sa3 = (float*)(smc + 98304);
    float* sd3 = sa3 + 512;
    for (int i = t; i < 512; i += 256) { sa3[i] = g_a3[i]; sd3[i] = g_d3[i]; }

    float acc[4][8][4];
    #pragma unroll
    for (int mf = 0; mf < 4; mf++)
        #pragma unroll
        for (int nf = 0; nf < 8; nf++)
            #pragma unroll
            for (int e = 0; e < 4; e++) acc[mf][nf][e] = 0.0f;

    auto issueA = [&](int buf, int kc) {
        uint32_t abb = sb + buf*32768;
        #pragma unroll
        for (int i = 0; i < 8; i++) {
            int slot = t + 256*i; int o = slot >> 3, chR = slot & 7;
            CPA(abb + o*128 + ((chR ^ (o & 7)) << 4),
                &g_w4h[(size_t)o*512 + kc*64 + chR*8]);
        }
        CPA_COMMIT();
    };
    auto loadB = [&](int kc, uint4* br) {
        #pragma unroll
        for (int i = 0; i < 4; i++) {
            int slot = t + 256*i;
            int j = slot >> 3, chR = slot & 7;
            br[i] = *(const uint4*)&g_Zh[(size_t)(j0+j)*512 + kc*64 + chR*8];
        }
    };
    auto storeB = [&](int buf, int kc, const uint4* br) {
        char* Bp = smc + 65536 + buf*16384;
        #pragma unroll
        for (int i = 0; i < 4; i++) {
            int slot = t + 256*i;
            int j = slot >> 3, chR = slot & 7;
            const __half* h = (const __half*)&br[i];
            int c = kc*64 + chR*8;
            __half v[8];
            #pragma unroll
            for (int e = 0; e < 8; e++)
                v[e] = __float2half_rn(fmaxf(0.f, fmaf(__half2float(h[e]), sa3[c+e], sd3[c+e])));
            *(uint4*)(Bp + j*128 + ((chR ^ (j & 7)) << 4)) = *(uint4*)v;
        }
    };
    auto compute = [&](int buf) {
        uint32_t abase = sb + buf*32768;
        uint32_t bbase = sb + 65536 + buf*16384;
        int t7 = lane & 7, mi = lane >> 3;
        #pragma unroll
        for (int s = 0; s < 4; s++) {
            uint32_t a[4][4], b[8][2];
            #pragma unroll
            for (int mf = 0; mf < 4; mf++) {
                int row = wm*64 + mf*16 + ((mi & 1) << 3) + t7;
                int ch = 2*s + (mi >> 1);
                LDM4(a[mf][0], a[mf][1], a[mf][2], a[mf][3],
                     abase + row*128 + ((ch ^ (row & 7)) << 4));
            }
            #pragma unroll
            for (int np = 0; np < 4; np++) {
                int row = wn*64 + np*16 + ((mi >> 1) << 3) + t7;
                int ch = 2*s + (mi & 1);
                LDM4(b[2*np][0], b[2*np][1], b[2*np+1][0], b[2*np+1][1],
                     bbase + row*128 + ((ch ^ (row & 7)) << 4));
            }
            #pragma unroll
            for (int mf = 0; mf < 4; mf++)
                #pragma unroll
                for (int nf = 0; nf < 8; nf++)
                    MMA16(acc[mf][nf], a[mf], b[nf]);
        }
    };

    __syncthreads();
    issueA(0, 0);
    {
        uint4 br0[4];
        loadB(0, br0);
        storeB(0, 0, br0);
    }
    uint4 br[4];
    for (int kc = 0; kc < 8; kc++) {
        int cur = kc & 1;
        CPA_WAIT0();
        __syncthreads();
        if (kc < 7) { issueA(cur ^ 1, kc + 1); loadB(kc + 1, br); }
        compute(cur);
        if (kc < 7) storeB(cur ^ 1, kc + 1, br);
    }

    int t4 = lane & 3, gr = lane >> 2;
    int jt0 = (j0 >> 4) + wn*4;
    #pragma unroll
    for (int mf = 0; mf < 4; mf++)
        #pragma unroll
        for (int rs = 0; rs < 2; rs++) {
            int o = wm*64 + mf*16 + rs*8 + gr;
            double s = 0.0, q = 0.0;
            #pragma unroll
            for (int nf = 0; nf < 8; nf++) {
                float v0 = acc[mf][nf][rs*2], v1 = acc[mf][nf][rs*2+1];
                s += (double)v0 + (double)v1;
                q += (double)v0*(double)v0 + (double)v1*(double)v1;
            }
            s += __shfl_xor_sync(0xffffffffu, s, 1); s += __shfl_xor_sync(0xffffffffu, s, 2);
            q += __shfl_xor_sync(0xffffffffu, q, 1); q += __shfl_xor_sync(0xffffffffu, q, 2);
            if (t4 == 0) { atomicAdd(&g_bn4sum[o], s); atomicAdd(&g_bn4sq[o], q); }
            #pragma unroll
            for (int tt = 0; tt < 4; tt++) {
                float m = fmaxf(fmaxf(acc[mf][2*tt][rs*2], acc[mf][2*tt][rs*2+1]),
                                fmaxf(acc[mf][2*tt+1][rs*2], acc[mf][2*tt+1][rs*2+1]));
                m = fmaxf(m, __shfl_xor_sync(0xffffffffu, m, 1));
                m = fmaxf(m, __shfl_xor_sync(0xffffffffu, m, 2));
                if (t4 == 0) g_M4[(size_t)(jt0 + tt)*256 + o] = m;
            }
        }
}

// ---------------- BN affine params ----------------
__global__ void bn3aff(const float* __restrict__ g, const float* __restrict__ b) {
    int c = threadIdx.x;
    if (c >= 512) return;
    double inv = 1.0 / (double)JJ;
    double m = g_bn3sum[c]*inv;
    double var = g_bn3sq[c]*inv - m*m;
    float a = (float)((double)g[c] / sqrt(var + EPSf));
    g_a3[c] = a;
    g_d3[c] = b[c] - (float)m * a;
}
__global__ void bn4aff(const float* __restrict__ g, const float* __restrict__ b) {
    int c = threadIdx.x;
    if (c >= 256) return;
    double inv = 1.0 / (double)JJ;
    double m = g_bn4sum[c]*inv;
    double var = g_bn4sq[c]*inv - m*m;
    float a = (float)((double)g[c] / sqrt(var + EPSf));
    g_a4[c] = a;
    g_d4[c] = b[c] - (float)m * a;
}

// ---------------- final: feat[b][o][ns] = relu(a4*M4 + d4)  (a4>0) ----------------
__global__ void finalk(float* __restrict__ out) {
    __shared__ float sm[32*257];
    int b = blockIdx.x >> 4, chunk = blockIdx.x & 15, t = threadIdx.x;
    int tile0 = b*512 + chunk*32;
    for (int i = t; i < 8192; i += 256) {
        int tl = i >> 8, o = i & 255;
        sm[tl*257 + o] = g_M4[(size_t)(tile0 + tl)*256 + o];
    }
    __syncthreads();
    int nsl = t & 31, og = t >> 5;
    for (int pass = 0; pass < 32; pass++) {
        int o = pass*8 + og;
        float a = g_a4[o], d = g_d4[o];
        float v = fmaxf(0.0f, fmaf(sm[nsl*257 + o], a, d));
        out[Bb*NSd*3 + b*131072 + o*512 + chunk*32 + nsl] = v;
    }
}

// ---------------- launch ----------------
extern "C" void kernel_launch(void* const* d_in, const int* in_sizes, int n_in,
                              void* d_out, int out_size) {
    const float* p    = (const float*)d_in[0];
    const float* w1   = (const float*)d_in[1];
    const float* w2   = (const float*)d_in[2];
    const float* b2   = (const float*)d_in[3];
    const float* bn1g = (const float*)d_in[4];
    const float* bn1b = (const float*)d_in[5];
    const float* w3   = (const float*)d_in[6];
    const float* bn3g = (const float*)d_in[7];
    const float* bn3b = (const float*)d_in[8];
    const float* w4   = (const float*)d_in[9];
    const float* bn4g = (const float*)d_in[10];
    const float* bn4b = (const float*)d_in[11];
    float* out = (float*)d_out;

    cudaFuncSetAttribute(tcg1, cudaFuncAttributeMaxDynamicSharedMemorySize, G1_SMEM);
    cudaFuncSetAttribute(tcg2, cudaFuncAttributeMaxDynamicSharedMemorySize, G2_SMEM);

    zerok<<<1, 512>>>();
    precompk<<<1, 256>>>(w1, w2);
    roundwk<<<512, 512>>>(w3, w4);
    fpsk<<<32, 128>>>(p, out);                 // centroids -> out[0:49152]
    knnk<<<256, 64>>>(p, out);
    bn1k<<<1, 256>>>(b2, bn1g, bn1b);
    pgenk<<<NT/8, 256>>>();
    tcg1<<<dim3(JJ/128, 4), 256, G1_SMEM>>>();
    bn3aff<<<1, 512>>>(bn3g, bn3b);
    tcg2<<<JJ/128, 256, G2_SMEM>>>();
    bn4aff<<<1, 256>>>(bn4g, bn4b);
    finalk<<<Bb*16, 256>>>(out);
}

// round 12
// speedup vs baseline: 2.6083x; 1.0204x over previous
#include <cuda_runtime.h>
#include <cuda_fp16.h>
#include <cstdint>

#define Bb 32
#define Np 2048
#define NSd 512
#define KN 16
#define NT (Bb*NSd)          // 16384 tiles
#define JJ (NT*KN)           // 262144 columns
#define EPSf 1e-5

// ---------------- scratch ----------------
__device__ float  g_grouped[NT*KN*3];
__device__ double g_sum9[9];
__device__ float  g_Weff2[256*3];
__device__ float  g_A1[256*3];
__device__ float  g_c1v[256];
__device__ __half g_Ph [NT*256];               // pooled [tile][c] fp16
__device__ __half g_w3h[512*512];              // fp16 w3
__device__ __half g_w4h[256*512];              // fp16 w4
__device__ __half g_Zh[(size_t)JJ*512];        // 268 MB  [j][c] fp16
__device__ float  g_M4[NT*256];                // max_k conv4-out [tile][o]
__device__ double g_bn3sum[512], g_bn3sq[512], g_bn4sum[256], g_bn4sq[256];
__device__ float  g_a3[512], g_d3[512], g_a4[256], g_d4[256];

// ---------------- helpers ----------------
__device__ __forceinline__ uint32_t smem_u32(const void* p) {
    uint32_t a;
    asm("{ .reg .u64 t; cvta.to.shared.u64 t, %1; cvt.u32.u64 %0, t; }" : "=r"(a) : "l"(p));
    return a;
}
#define LDM4(r0,r1,r2,r3,addr) \
    asm volatile("ldmatrix.sync.aligned.m8n8.x4.shared.b16 {%0,%1,%2,%3}, [%4];" \
        : "=r"(r0),"=r"(r1),"=r"(r2),"=r"(r3) : "r"(addr))
#define MMA16(c, a, b) \
    asm volatile("mma.sync.aligned.m16n8k16.row.col.f32.f16.f16.f32 " \
        "{%0,%1,%2,%3}, {%4,%5,%6,%7}, {%8,%9}, {%0,%1,%2,%3};" \
        : "+f"((c)[0]),"+f"((c)[1]),"+f"((c)[2]),"+f"((c)[3]) \
        : "r"((a)[0]),"r"((a)[1]),"r"((a)[2]),"r"((a)[3]), "r"((b)[0]),"r"((b)[1]))
#define CPA(dst, src) asm volatile("cp.async.cg.shared.global [%0], [%1], 16;" ::"r"(dst),"l"(src))
#define CPA_COMMIT()  asm volatile("cp.async.commit_group;" ::: "memory")
#define CPA_WAIT0()   asm volatile("cp.async.wait_group 0;" ::: "memory")

// ---------------- zero accumulators (graph replays!) ----------------
__global__ void zerok() {
    int t = threadIdx.x;
    if (t < 9) g_sum9[t] = 0.0;
    for (int i = t; i < 512; i += blockDim.x) { g_bn3sum[i] = 0.0; g_bn3sq[i] = 0.0; }
    for (int i = t; i < 256; i += blockDim.x) { g_bn4sum[i] = 0.0; g_bn4sq[i] = 0.0; }
}

__global__ void precompk(const float* __restrict__ w1, const float* __restrict__ w2) {
    int t = threadIdx.x;
    if (t < 256) {
        double s0 = 0.0, s1 = 0.0, s2 = 0.0;
        for (int i = 0; i < 256; i++) {
            double wi = (double)w2[t*256 + i];
            s0 += wi * ((double)w1[i*6+0] + (double)w1[i*6+3]);
            s1 += wi * ((double)w1[i*6+1] + (double)w1[i*6+4]);
            s2 += wi * ((double)w1[i*6+2] + (double)w1[i*6+5]);
        }
        g_Weff2[t*3+0] = (float)s0; g_Weff2[t*3+1] = (float)s1; g_Weff2[t*3+2] = (float)s2;
    }
}

// pre-round weights to fp16
__global__ void roundwk(const float* __restrict__ w3, const float* __restrict__ w4) {
    int i = blockIdx.x*512 + threadIdx.x;
    if (i < 512*512) g_w3h[i] = __float2half_rn(w3[i]);
    if (i < 256*512) g_w4h[i] = __float2half_rn(w4[i]);
}

// ---------------- FPS: 32 blocks x 256 threads, 8 pts/thread, 1 barrier/step ----------------
__global__ void fpsk(const float* __restrict__ p, float* __restrict__ outc) {
    __shared__ float sp[Np*3];
    __shared__ unsigned long long skey[2][8];
    int b = blockIdx.x, t = threadIdx.x;
    for (int i = t; i < Np*3; i += 256) sp[i] = p[b*Np*3 + i];
    __syncthreads();
    float px[8], py[8], pz[8], dist[8];
    #pragma unroll
    for (int i = 0; i < 8; i++) {
        int n = t + 256*i;
        px[i] = sp[n*3+0]; py[i] = sp[n*3+1]; pz[i] = sp[n*3+2];
        dist[i] = 1e10f;
    }
    int lane = t & 31, wid = t >> 5;
    int cs = 0;
    for (int s = 0; s < NSd; s++) {
        if (t == 0) {
            outc[(b*NSd + s)*3 + 0] = sp[cs*3+0];
            outc[(b*NSd + s)*3 + 1] = sp[cs*3+1];
            outc[(b*NSd + s)*3 + 2] = sp[cs*3+2];
        }
        float cx = sp[cs*3+0], cy = sp[cs*3+1], cz = sp[cs*3+2];
        unsigned long long best = 0ull;
        #pragma unroll
        for (int i = 0; i < 8; i++) {
            float dx = __fadd_rn(px[i], -cx);
            float dy = __fadd_rn(py[i], -cy);
            float dz = __fadd_rn(pz[i], -cz);
            float d = __fadd_rn(__fadd_rn(__fmul_rn(dx,dx), __fmul_rn(dy,dy)), __fmul_rn(dz,dz));
            dist[i] = fminf(dist[i], d);
            unsigned long long key = ((unsigned long long)__float_as_uint(dist[i]) << 32)
                                   | (unsigned)(Np - 1 - (t + 256*i));
            best = max(best, key);
        }
        #pragma unroll
        for (int off = 16; off; off >>= 1)
            best = max(best, __shfl_down_sync(0xffffffffu, best, off));
        if (lane == 0) skey[s & 1][wid] = best;
        __syncthreads();
        const unsigned long long* sk = skey[s & 1];
        unsigned long long k2 = max(max(max(sk[0], sk[1]), max(sk[2], sk[3])),
                                    max(max(sk[4], sk[5]), max(sk[6], sk[7])));
        cs = Np - 1 - (int)(unsigned)(k2 & 0xffffffffull);
    }
}

// ---------------- kNN: 256 blocks x 64 threads, float4-packed smem ----------------
__global__ void knnk(const float* __restrict__ p, const float* __restrict__ cntrd) {
    __shared__ float4 shp4[Np];                // (x, y, z, |p|^2) — 32 KB
    __shared__ double s9[9];
    int t = threadIdx.x;
    int gc = blockIdx.x*64 + t;
    int b = blockIdx.x >> 3;
    for (int n = t; n < Np; n += 64) {
        float x = p[b*Np*3 + n*3 + 0];
        float y = p[b*Np*3 + n*3 + 1];
        float z = p[b*Np*3 + n*3 + 2];
        float p2 = __fadd_rn(__fadd_rn(__fmul_rn(x,x), __fmul_rn(y,y)), __fmul_rn(z,z));
        shp4[n] = make_float4(x, y, z, p2);
    }
    if (t < 9) s9[t] = 0.0;
    __syncthreads();
    float cx = cntrd[gc*3+0], cy = cntrd[gc*3+1], cz = cntrd[gc*3+2];
    float c2 = __fadd_rn(__fadd_rn(__fmul_rn(cx,cx), __fmul_rn(cy,cy)), __fmul_rn(cz,cz));
    float hd[KN]; int hi[KN];
    #pragma unroll
    for (int k = 0; k < KN; k++) { hd[k] = 3.4e38f; hi[k] = 0; }
    for (int n = 0; n < Np; n++) {
        float4 v = shp4[n];
        float dot = __fadd_rn(__fadd_rn(__fmul_rn(cx, v.x),
                                        __fmul_rn(cy, v.y)),
                              __fmul_rn(cz, v.z));
        float d2 = __fadd_rn(__fadd_rn(c2, v.w), -__fmul_rn(2.0f, dot));
        if (d2 < hd[KN-1]) {
            hd[KN-1] = d2; hi[KN-1] = n;
            #pragma unroll
            for (int j = KN-1; j > 0; --j) {
                bool sw = hd[j] < hd[j-1];
                float td = hd[j]; int ti = hi[j];
                float tdm = hd[j-1]; int tim = hi[j-1];
                hd[j]   = sw ? tdm : td;   hi[j]   = sw ? tim : ti;
                hd[j-1] = sw ? td  : tdm;  hi[j-1] = sw ? ti  : tim;
            }
        }
    }
    double sx=0, sy=0, sz=0, sxx=0, syy=0, szz=0, sxy=0, sxz=0, syz=0;
    #pragma unroll
    for (int k = 0; k < KN; k++) {
        int n = hi[k];
        float4 v = shp4[n];
        g_grouped[(gc*KN + k)*3 + 0] = v.x;
        g_grouped[(gc*KN + k)*3 + 1] = v.y;
        g_grouped[(gc*KN + k)*3 + 2] = v.z;
        sx += v.x; sy += v.y; sz += v.z;
        sxx += (double)v.x*v.x; syy += (double)v.y*v.y; szz += (double)v.z*v.z;
        sxy += (double)v.x*v.y; sxz += (double)v.x*v.z; syz += (double)v.y*v.z;
    }
    atomicAdd(&s9[0], sx);  atomicAdd(&s9[1], sy);  atomicAdd(&s9[2], sz);
    atomicAdd(&s9[3], sxx); atomicAdd(&s9[4], syy); atomicAdd(&s9[5], szz);
    atomicAdd(&s9[6], sxy); atomicAdd(&s9[7], sxz); atomicAdd(&s9[8], syz);
    __syncthreads();
    if (t < 9) atomicAdd(&g_sum9[t], s9[t]);
}

// ---------------- BN1 affine from analytic moments ----------------
__global__ void bn1k(const float* __restrict__ b2, const float* __restrict__ g1,
                     const float* __restrict__ b1) {
    int o = threadIdx.x;
    if (o >= 256) return;
    double inv = 1.0 / (double)JJ;
    double Ex = g_sum9[0]*inv, Ey = g_sum9[1]*inv, Ez = g_sum9[2]*inv;
    double Mxx = g_sum9[3]*inv, Myy = g_sum9[4]*inv, Mzz = g_sum9[5]*inv;
    double Mxy = g_sum9[6]*inv, Mxz = g_sum9[7]*inv, Myz = g_sum9[8]*inv;
    double w0 = g_Weff2[o*3], w1v = g_Weff2[o*3+1], w2v = g_Weff2[o*3+2];
    double bo = b2[o];
    double wEg = w0*Ex + w1v*Ey + w2v*Ez;
    double m = wEg + bo;
    double Ex2 = w0*w0*Mxx + w1v*w1v*Myy + w2v*w2v*Mzz
               + 2.0*(w0*w1v*Mxy + w0*w2v*Mxz + w1v*w2v*Myz)
               + 2.0*bo*wEg + bo*bo;
    double var = Ex2 - m*m;
    double s = (double)g1[o] / sqrt(var + EPSf);
    g_A1[o*3+0] = (float)(s*w0);
    g_A1[o*3+1] = (float)(s*w1v);
    g_A1[o*3+2] = (float)(s*w2v);
    g_c1v[o] = (float)((double)b1[o] + s*(bo - m));
}

// ---------------- pooled: Ph[tile][c] = fp16(max_k relu(A1.xyz + c1)) ----------------
__global__ void pgenk() {
    __shared__ float gsh[48];
    int t = threadIdx.x;
    float a0 = g_A1[t*3], a1 = g_A1[t*3+1], a2 = g_A1[t*3+2], c1 = g_c1v[t];
    for (int it = 0; it < 8; it++) {
        int tile = blockIdx.x*8 + it;
        __syncthreads();
        if (t < 48) gsh[t] = g_grouped[tile*48 + t];
        __syncthreads();
        float mx = 0.0f;
        #pragma unroll
        for (int k = 0; k < KN; k++)
            mx = fmaxf(mx, fmaxf(0.0f, fmaf(a0, gsh[k*3], fmaf(a1, gsh[k*3+1], fmaf(a2, gsh[k*3+2], c1)))));
        g_Ph[(size_t)tile*256 + t] = __float2half_rn(mx);
    }
}

// ================= GEMM1 (fp16 m16n8k16): Z[j][o] = sum_c w3[o][c]*Baug[j][c] =================
// CTA 128o x 128j, K=512 in 8 chunks of 64; 8 warps, warp tile 32x64.
#define G1_SMEM 71168
__global__ __launch_bounds__(256, 2) void tcg1() {
    extern __shared__ __align__(16) char smc[];
    float* smf = (float*)smc;
    uint32_t sb = smem_u32(smc);
    int t = threadIdx.x, lane = t & 31, wid = t >> 5;
    int wm = wid & 3, wn = wid >> 2;
    int j0 = blockIdx.x * 128, o0 = blockIdx.y * 128;
    float* sXYZ = (float*)(smc + 65536);
    float* sA0 = (float*)(smc + 67072);
    float* sA1p = sA0 + 256; float* sA2p = sA0 + 512; float* sCp = sA0 + 768;

    for (int i = t; i < 384; i += 256) sXYZ[i] = g_grouped[(size_t)j0*3 + i];
    sA0[t] = g_A1[t*3]; sA1p[t] = g_A1[t*3+1]; sA2p[t] = g_A1[t*3+2]; sCp[t] = g_c1v[t];

    float acc[2][8][4];
    #pragma unroll
    for (int mf = 0; mf < 2; mf++)
        #pragma unroll
        for (int nf = 0; nf < 8; nf++)
            #pragma unroll
            for (int e = 0; e < 4; e++) acc[mf][nf][e] = 0.0f;

    int t0 = j0 >> 4;

    auto issue = [&](int buf, int kc) {
        uint32_t abb = sb + buf*16384;
        #pragma unroll
        for (int i = 0; i < 4; i++) {
            int slot = t + 256*i; int o = slot >> 3, chR = slot & 7;
            CPA(abb + o*128 + ((chR ^ (o & 7)) << 4),
                &g_w3h[(size_t)(o0+o)*512 + kc*64 + chR*8]);
        }
        if (kc < 4) {
            uint32_t bbb = sb + 32768 + buf*16384;
            #pragma unroll
            for (int i = 0; i < 4; i++) {
                int slot = t + 256*i; int j = slot >> 3, chR = slot & 7;
                CPA(bbb + j*128 + ((chR ^ (j & 7)) << 4),
                    &g_Ph[(size_t)(t0 + (j >> 4))*256 + kc*64 + chR*8]);
            }
        } else {
            char* Bp = smc + 32768 + buf*16384;
            int cb = (kc - 4)*64;
            #pragma unroll
            for (int i = 0; i < 4; i++) {
                int slot = t + 256*i; int j = slot >> 3, chR = slot & 7;
                float x = sXYZ[j*3], y = sXYZ[j*3+1], z = sXYZ[j*3+2];
                int c = cb + chR*8;
                __half h[8];
                #pragma unroll
                for (int e = 0; e < 8; e++)
                    h[e] = __float2half_rn(fmaxf(0.f,
                        fmaf(sA0[c+e], x, fmaf(sA1p[c+e], y, fmaf(sA2p[c+e], z, sCp[c+e])))));
                *(uint4*)(Bp + j*128 + ((chR ^ (j & 7)) << 4)) = *(uint4*)h;
            }
        }
        CPA_COMMIT();
    };

    auto compute = [&](int buf) {
        uint32_t abase = sb + buf*16384;
        uint32_t bbase = sb + 32768 + buf*16384;
        int t7 = lane & 7, mi = lane >> 3;
        #pragma unroll
        for (int s = 0; s < 4; s++) {
            uint32_t a[2][4], b[8][2];
            #pragma unroll
            for (int mf = 0; mf < 2; mf++) {
                int row = wm*32 + mf*16 + ((mi & 1) << 3) + t7;
                int ch = 2*s + (mi >> 1);
                LDM4(a[mf][0], a[mf][1], a[mf][2], a[mf][3],
                     abase + row*128 + ((ch ^ (row & 7)) << 4));
            }
            #pragma unroll
            for (int np = 0; np < 4; np++) {
                int row = wn*64 + np*16 + ((mi >> 1) << 3) + t7;
                int ch = 2*s + (mi & 1);
                LDM4(b[2*np][0], b[2*np][1], b[2*np+1][0], b[2*np+1][1],
                     bbase + row*128 + ((ch ^ (row & 7)) << 4));
            }
            #pragma unroll
            for (int mf = 0; mf < 2; mf++)
                #pragma unroll
                for (int nf = 0; nf < 8; nf++)
                    MMA16(acc[mf][nf], a[mf], b[nf]);
        }
    };

    __syncthreads();
    issue(0, 0);
    for (int kc = 0; kc < 8; kc++) {
        int cur = kc & 1;
        CPA_WAIT0();
        __syncthreads();
        if (kc < 7) issue(cur ^ 1, kc + 1);
        compute(cur);
    }
    __syncthreads();

    // stats via quad shuffles
    int t4 = lane & 3, gr = lane >> 2;
    #pragma unroll
    for (int mf = 0; mf < 2; mf++)
        #pragma unroll
        for (int rs = 0; rs < 2; rs++) {
            double s = 0.0, q = 0.0;
            #pragma unroll
            for (int nf = 0; nf < 8; nf++) {
                float v0 = acc[mf][nf][rs*2], v1 = acc[mf][nf][rs*2+1];
                s += (double)v0 + (double)v1;
                q += (double)v0*(double)v0 + (double)v1*(double)v1;
            }
            s += __shfl_xor_sync(0xffffffffu, s, 1); s += __shfl_xor_sync(0xffffffffu, s, 2);
            q += __shfl_xor_sync(0xffffffffu, q, 1); q += __shfl_xor_sync(0xffffffffu, q, 2);
            if (t4 == 0) {
                int o = o0 + wm*32 + mf*16 + rs*8 + gr;
                atomicAdd(&g_bn3sum[o], s); atomicAdd(&g_bn3sq[o], q);
            }
        }

    // transpose through smem (pad 132) then coalesced fp16 store
    float* T = smf;
    #pragma unroll
    for (int mf = 0; mf < 2; mf++)
        #pragma unroll
        for (int nf = 0; nf < 8; nf++) {
            int orw = wm*32 + mf*16 + gr;
            int jl = wn*64 + nf*8 + 2*t4;
            T[jl*132 + orw]       = acc[mf][nf][0];
            T[(jl+1)*132 + orw]   = acc[mf][nf][1];
            T[jl*132 + orw + 8]   = acc[mf][nf][2];
            T[(jl+1)*132 + orw+8] = acc[mf][nf][3];
        }
    __syncthreads();
    int cg16 = t & 15, rr = t >> 4;
    #pragma unroll
    for (int r = 0; r < 8; r++) {
        int row = rr + 16*r;
        float4 v0 = *(float4*)&T[row*132 + cg16*8];
        float4 v1 = *(float4*)&T[row*132 + cg16*8 + 4];
        __half h[8];
        h[0] = __float2half_rn(v0.x); h[1] = __float2half_rn(v0.y);
        h[2] = __float2half_rn(v0.z); h[3] = __float2half_rn(v0.w);
        h[4] = __float2half_rn(v1.x); h[5] = __float2half_rn(v1.y);
        h[6] = __float2half_rn(v1.z); h[7] = __float2half_rn(v1.w);
        *(uint4*)&g_Zh[(size_t)(j0+row)*512 + o0 + cg16*8] = *(uint4*)h;
    }
}

// ================= GEMM2 (fp16 m16n8k16): stats + max_k of w4 @ relu(bn3(Z)) =================
// CTA 256o x 128j, K=512 in 8 chunks of 64; 8 warps, warp tile 64x64.
#define G2_SMEM 102400
__global__ __launch_bounds__(256, 1) void tcg2() {
    extern __shared__ __align__(16) char smc[];
    uint32_t sb = smem_u32(smc);
    int t = threadIdx.x, lane = t & 31, wid = t >> 5;
    int wm = wid & 3, wn = wid >> 2;
    int j0 = blockIdx.x * 128;
    float* sa3 = (float*)(smc + 98304);
    float* sd3 = sa3 + 512;
    for (int i = t; i < 512; i += 256) { sa3[i] = g_a3[i]; sd3[i] = g_d3[i]; }

    float acc[4][8][4];
    #pragma unroll
    for (int mf = 0; mf < 4; mf++)
        #pragma unroll
        for (int nf = 0; nf < 8; nf++)
            #pragma unroll
            for (int e = 0; e < 4; e++) acc[mf][nf][e] = 0.0f;

    auto issueA = [&](int buf, int kc) {
        uint32_t abb = sb + buf*32768;
        #pragma unroll
        for (int i = 0; i < 8; i++) {
            int slot = t + 256*i; int o = slot >> 3, chR = slot & 7;
            CPA(abb + o*128 + ((chR ^ (o & 7)) << 4),
                &g_w4h[(size_t)o*512 + kc*64 + chR*8]);
        }
        CPA_COMMIT();
    };
    auto loadB = [&](int kc, uint4* br) {
        #pragma unroll
        for (int i = 0; i < 4; i++) {
            int slot = t + 256*i;
            int j = slot >> 3, chR = slot & 7;
            br[i] = *(const uint4*)&g_Zh[(size_t)(j0+j)*512 + kc*64 + chR*8];
        }
    };
    auto storeB = [&](int buf, int kc, const uint4* br) {
        char* Bp = smc + 65536 + buf*16384;
        #pragma unroll
        for (int i = 0; i < 4; i++) {
            int slot = t + 256*i;
            int j = slot >> 3, chR = slot & 7;
            const __half* h = (const __half*)&br[i];
            int c = kc*64 + chR*8;
            __half v[8];
            #pragma unroll
            for (int e = 0; e < 8; e++)
                v[e] = __float2half_rn(fmaxf(0.f, fmaf(__half2float(h[e]), sa3[c+e], sd3[c+e])));
            *(uint4*)(Bp + j*128 + ((chR ^ (j & 7)) << 4)) = *(uint4*)v;
        }
    };
    auto compute = [&](int buf) {
        uint32_t abase = sb + buf*32768;
        uint32_t bbase = sb + 65536 + buf*16384;
        int t7 = lane & 7, mi = lane >> 3;
        #pragma unroll
        for (int s = 0; s < 4; s++) {
            uint32_t a[4][4], b[8][2];
            #pragma unroll
            for (int mf = 0; mf < 4; mf++) {
                int row = wm*64 + mf*16 + ((mi & 1) << 3) + t7;
                int ch = 2*s + (mi >> 1);
                LDM4(a[mf][0], a[mf][1], a[mf][2], a[mf][3],
                     abase + row*128 + ((ch ^ (row & 7)) << 4));
            }
            #pragma unroll
            for (int np = 0; np < 4; np++) {
                int row = wn*64 + np*16 + ((mi >> 1) << 3) + t7;
                int ch = 2*s + (mi & 1);
                LDM4(b[2*np][0], b[2*np][1], b[2*np+1][0], b[2*np+1][1],
                     bbase + row*128 + ((ch ^ (row & 7)) << 4));
            }
            #pragma unroll
            for (int mf = 0; mf < 4; mf++)
                #pragma unroll
                for (int nf = 0; nf < 8; nf++)
                    MMA16(acc[mf][nf], a[mf], b[nf]);
        }
    };

    __syncthreads();
    issueA(0, 0);
    {
        uint4 br0[4];
        loadB(0, br0);
        storeB(0, 0, br0);
    }
    uint4 br[4];
    for (int kc = 0; kc < 8; kc++) {
        int cur = kc & 1;
        CPA_WAIT0();
        __syncthreads();
        if (kc < 7) { issueA(cur ^ 1, kc + 1); loadB(kc + 1, br); }
        compute(cur);
        if (kc < 7) storeB(cur ^ 1, kc + 1, br);
    }

    int t4 = lane & 3, gr = lane >> 2;
    int jt0 = (j0 >> 4) + wn*4;
    #pragma unroll
    for (int mf = 0; mf < 4; mf++)
        #pragma unroll
        for (int rs = 0; rs < 2; rs++) {
            int o = wm*64 + mf*16 + rs*8 + gr;
            double s = 0.0, q = 0.0;
            #pragma unroll
            for (int nf = 0; nf < 8; nf++) {
                float v0 = acc[mf][nf][rs*2], v1 = acc[mf][nf][rs*2+1];
                s += (double)v0 + (double)v1;
                q += (double)v0*(double)v0 + (double)v1*(double)v1;
            }
            s += __shfl_xor_sync(0xffffffffu, s, 1); s += __shfl_xor_sync(0xffffffffu, s, 2);
            q += __shfl_xor_sync(0xffffffffu, q, 1); q += __shfl_xor_sync(0xffffffffu, q, 2);
            if (t4 == 0) { atomicAdd(&g_bn4sum[o], s); atomicAdd(&g_bn4sq[o], q); }
            #pragma unroll
            for (int tt = 0; tt < 4; tt++) {
                float m = fmaxf(fmaxf(acc[mf][2*tt][rs*2], acc[mf][2*tt][rs*2+1]),
                                fmaxf(acc[mf][2*tt+1][rs*2], acc[mf][2*tt+1][rs*2+1]));
                m = fmaxf(m, __shfl_xor_sync(0xffffffffu, m, 1));
                m = fmaxf(m, __shfl_xor_sync(0xffffffffu, m, 2));
                if (t4 == 0) g_M4[(size_t)(jt0 + tt)*256 + o] = m;
            }
        }
}

// ---------------- BN affine params ----------------
__global__ void bn3aff(const float* __restrict__ g, const float* __restrict__ b) {
    int c = threadIdx.x;
    if (c >= 512) return;
    double inv = 1.0 / (double)JJ;
    double m = g_bn3sum[c]*inv;
    double var = g_bn3sq[c]*inv - m*m;
    float a = (float)((double)g[c] / sqrt(var + EPSf));
    g_a3[c] = a;
    g_d3[c] = b[c] - (float)m * a;
}
__global__ void bn4aff(const float* __restrict__ g, const float* __restrict__ b) {
    int c = threadIdx.x;
    if (c >= 256) return;
    double inv = 1.0 / (double)JJ;
    double m = g_bn4sum[c]*inv;
    double var = g_bn4sq[c]*inv - m*m;
    float a = (float)((double)g[c] / sqrt(var + EPSf));
    g_a4[c] = a;
    g_d4[c] = b[c] - (float)m * a;
}

// ---------------- final: feat[b][o][ns] = relu(a4*M4 + d4)  (a4>0) ----------------
__global__ void finalk(float* __restrict__ out) {
    __shared__ float sm[32*257];
    int b = blockIdx.x >> 4, chunk = blockIdx.x & 15, t = threadIdx.x;
    int tile0 = b*512 + chunk*32;
    for (int i = t; i < 8192; i += 256) {
        int tl = i >> 8, o = i & 255;
        sm[tl*257 + o] = g_M4[(size_t)(tile0 + tl)*256 + o];
    }
    __syncthreads();
    int nsl = t & 31, og = t >> 5;
    for (int pass = 0; pass < 32; pass++) {
        int o = pass*8 + og;
        float a = g_a4[o], d = g_d4[o];
        float v = fmaxf(0.0f, fmaf(sm[nsl*257 + o], a, d));
        out[Bb*NSd*3 + b*131072 + o*512 + chunk*32 + nsl] = v;
    }
}

// ---------------- launch ----------------
extern "C" void kernel_launch(void* const* d_in, const int* in_sizes, int n_in,
                              void* d_out, int out_size) {
    const float* p    = (const float*)d_in[0];
    const float* w1   = (const float*)d_in[1];
    const float* w2   = (const float*)d_in[2];
    const float* b2   = (const float*)d_in[3];
    const float* bn1g = (const float*)d_in[4];
    const float* bn1b = (const float*)d_in[5];
    const float* w3   = (const float*)d_in[6];
    const float* bn3g = (const float*)d_in[7];
    const float* bn3b = (const float*)d_in[8];
    const float* w4   = (const float*)d_in[9];
    const float* bn4g = (const float*)d_in[10];
    const float* bn4b = (const float*)d_in[11];
    float* out = (float*)d_out;

    cudaFuncSetAttribute(tcg1, cudaFuncAttributeMaxDynamicSharedMemorySize, G1_SMEM);
    cudaFuncSetAttribute(tcg2, cudaFuncAttributeMaxDynamicSharedMemorySize, G2_SMEM);

    zerok<<<1, 512>>>();
    precompk<<<1, 256>>>(w1, w2);
    roundwk<<<512, 512>>>(w3, w4);
    fpsk<<<32, 256>>>(p, out);                 // centroids -> out[0:49152]
    knnk<<<256, 64>>>(p, out);
    bn1k<<<1, 256>>>(b2, bn1g, bn1b);
    pgenk<<<NT/8, 256>>>();
    tcg1<<<dim3(JJ/128, 4), 256, G1_SMEM>>>();
    bn3aff<<<1, 512>>>(bn3g, bn3b);
    tcg2<<<JJ/128, 256, G2_SMEM>>>();
    bn4aff<<<1, 256>>>(bn4g, bn4b);
    finalk<<<Bb*16, 256>>>(out);
}

// round 13
// speedup vs baseline: 2.6181x; 1.0037x over previous
#include <cuda_runtime.h>
#include <cuda_fp16.h>
#include <cstdint>

#define Bb 32
#define Np 2048
#define NSd 512
#define KN 16
#define NT (Bb*NSd)          // 16384 tiles
#define JJ (NT*KN)           // 262144 columns
#define EPSf 1e-5

// ---------------- scratch ----------------
__device__ float  g_grouped[NT*KN*3];
__device__ double g_sum9[9];
__device__ float  g_Weff2[256*3];
__device__ float  g_A1[256*3];
__device__ float  g_c1v[256];
__device__ __half g_Ph [NT*256];               // pooled [tile][c] fp16
__device__ __half g_w3h[512*512];              // fp16 w3
__device__ __half g_w4h[256*512];              // fp16 w4
__device__ float  g_Zp[(size_t)NT*512];        // 32 MB  Zp[t][o] = w3a @ pooled
__device__ __half g_Zh[(size_t)JJ*512];        // 268 MB  [j][c] fp16
__device__ float  g_M4[NT*256];                // max_k conv4-out [tile][o]
__device__ double g_bn3sum[512], g_bn3sq[512], g_bn4sum[256], g_bn4sq[256];
__device__ float  g_a3[512], g_d3[512], g_a4[256], g_d4[256];

// ---------------- helpers ----------------
__device__ __forceinline__ uint32_t smem_u32(const void* p) {
    uint32_t a;
    asm("{ .reg .u64 t; cvta.to.shared.u64 t, %1; cvt.u32.u64 %0, t; }" : "=r"(a) : "l"(p));
    return a;
}
#define LDM4(r0,r1,r2,r3,addr) \
    asm volatile("ldmatrix.sync.aligned.m8n8.x4.shared.b16 {%0,%1,%2,%3}, [%4];" \
        : "=r"(r0),"=r"(r1),"=r"(r2),"=r"(r3) : "r"(addr))
#define MMA16(c, a, b) \
    asm volatile("mma.sync.aligned.m16n8k16.row.col.f32.f16.f16.f32 " \
        "{%0,%1,%2,%3}, {%4,%5,%6,%7}, {%8,%9}, {%0,%1,%2,%3};" \
        : "+f"((c)[0]),"+f"((c)[1]),"+f"((c)[2]),"+f"((c)[3]) \
        : "r"((a)[0]),"r"((a)[1]),"r"((a)[2]),"r"((a)[3]), "r"((b)[0]),"r"((b)[1]))
#define CPA(dst, src) asm volatile("cp.async.cg.shared.global [%0], [%1], 16;" ::"r"(dst),"l"(src))
#define CPA_COMMIT()  asm volatile("cp.async.commit_group;" ::: "memory")
#define CPA_WAIT0()   asm volatile("cp.async.wait_group 0;" ::: "memory")

// ---------------- zero accumulators (graph replays!) ----------------
__global__ void zerok() {
    int t = threadIdx.x;
    if (t < 9) g_sum9[t] = 0.0;
    for (int i = t; i < 512; i += blockDim.x) { g_bn3sum[i] = 0.0; g_bn3sq[i] = 0.0; }
    for (int i = t; i < 256; i += blockDim.x) { g_bn4sum[i] = 0.0; g_bn4sq[i] = 0.0; }
}

__global__ void precompk(const float* __restrict__ w1, const float* __restrict__ w2) {
    int t = threadIdx.x;
    if (t < 256) {
        double s0 = 0.0, s1 = 0.0, s2 = 0.0;
        for (int i = 0; i < 256; i++) {
            double wi = (double)w2[t*256 + i];
            s0 += wi * ((double)w1[i*6+0] + (double)w1[i*6+3]);
            s1 += wi * ((double)w1[i*6+1] + (double)w1[i*6+4]);
            s2 += wi * ((double)w1[i*6+2] + (double)w1[i*6+5]);
        }
        g_Weff2[t*3+0] = (float)s0; g_Weff2[t*3+1] = (float)s1; g_Weff2[t*3+2] = (float)s2;
    }
}

// pre-round weights to fp16
__global__ void roundwk(const float* __restrict__ w3, const float* __restrict__ w4) {
    int i = blockIdx.x*512 + threadIdx.x;
    if (i < 512*512) g_w3h[i] = __float2half_rn(w3[i]);
    if (i < 256*512) g_w4h[i] = __float2half_rn(w4[i]);
}

// ---------------- FPS: 32 blocks x 256 threads, 8 pts/thread, 1 barrier/step ----------------
__global__ void fpsk(const float* __restrict__ p, float* __restrict__ outc) {
    __shared__ float sp[Np*3];
    __shared__ unsigned long long skey[2][8];
    int b = blockIdx.x, t = threadIdx.x;
    for (int i = t; i < Np*3; i += 256) sp[i] = p[b*Np*3 + i];
    __syncthreads();
    float px[8], py[8], pz[8], dist[8];
    #pragma unroll
    for (int i = 0; i < 8; i++) {
        int n = t + 256*i;
        px[i] = sp[n*3+0]; py[i] = sp[n*3+1]; pz[i] = sp[n*3+2];
        dist[i] = 1e10f;
    }
    int lane = t & 31, wid = t >> 5;
    int cs = 0;
    for (int s = 0; s < NSd; s++) {
        if (t == 0) {
            outc[(b*NSd + s)*3 + 0] = sp[cs*3+0];
            outc[(b*NSd + s)*3 + 1] = sp[cs*3+1];
            outc[(b*NSd + s)*3 + 2] = sp[cs*3+2];
        }
        float cx = sp[cs*3+0], cy = sp[cs*3+1], cz = sp[cs*3+2];
        unsigned long long best = 0ull;
        #pragma unroll
        for (int i = 0; i < 8; i++) {
            float dx = __fadd_rn(px[i], -cx);
            float dy = __fadd_rn(py[i], -cy);
            float dz = __fadd_rn(pz[i], -cz);
            float d = __fadd_rn(__fadd_rn(__fmul_rn(dx,dx), __fmul_rn(dy,dy)), __fmul_rn(dz,dz));
            dist[i] = fminf(dist[i], d);
            unsigned long long key = ((unsigned long long)__float_as_uint(dist[i]) << 32)
                                   | (unsigned)(Np - 1 - (t + 256*i));
            best = max(best, key);
        }
        #pragma unroll
        for (int off = 16; off; off >>= 1)
            best = max(best, __shfl_down_sync(0xffffffffu, best, off));
        if (lane == 0) skey[s & 1][wid] = best;
        __syncthreads();
        const unsigned long long* sk = skey[s & 1];
        unsigned long long k2 = max(max(max(sk[0], sk[1]), max(sk[2], sk[3])),
                                    max(max(sk[4], sk[5]), max(sk[6], sk[7])));
        cs = Np - 1 - (int)(unsigned)(k2 & 0xffffffffull);
    }
}

// ---------------- kNN: 256 blocks x 64 threads, float4-packed smem ----------------
__global__ void knnk(const float* __restrict__ p, const float* __restrict__ cntrd) {
    __shared__ float4 shp4[Np];                // (x, y, z, |p|^2) — 32 KB
    __shared__ double s9[9];
    int t = threadIdx.x;
    int gc = blockIdx.x*64 + t;
    int b = blockIdx.x >> 3;
    for (int n = t; n < Np; n += 64) {
        float x = p[b*Np*3 + n*3 + 0];
        float y = p[b*Np*3 + n*3 + 1];
        float z = p[b*Np*3 + n*3 + 2];
        float p2 = __fadd_rn(__fadd_rn(__fmul_rn(x,x), __fmul_rn(y,y)), __fmul_rn(z,z));
        shp4[n] = make_float4(x, y, z, p2);
    }
    if (t < 9) s9[t] = 0.0;
    __syncthreads();
    float cx = cntrd[gc*3+0], cy = cntrd[gc*3+1], cz = cntrd[gc*3+2];
    float c2 = __fadd_rn(__fadd_rn(__fmul_rn(cx,cx), __fmul_rn(cy,cy)), __fmul_rn(cz,cz));
    float hd[KN]; int hi[KN];
    #pragma unroll
    for (int k = 0; k < KN; k++) { hd[k] = 3.4e38f; hi[k] = 0; }
    for (int n = 0; n < Np; n++) {
        float4 v = shp4[n];
        float dot = __fadd_rn(__fadd_rn(__fmul_rn(cx, v.x),
                                        __fmul_rn(cy, v.y)),
                              __fmul_rn(cz, v.z));
        float d2 = __fadd_rn(__fadd_rn(c2, v.w), -__fmul_rn(2.0f, dot));
        if (d2 < hd[KN-1]) {
            hd[KN-1] = d2; hi[KN-1] = n;
            #pragma unroll
            for (int j = KN-1; j > 0; --j) {
                bool sw = hd[j] < hd[j-1];
                float td = hd[j]; int ti = hi[j];
                float tdm = hd[j-1]; int tim = hi[j-1];
                hd[j]   = sw ? tdm : td;   hi[j]   = sw ? tim : ti;
                hd[j-1] = sw ? td  : tdm;  hi[j-1] = sw ? ti  : tim;
            }
        }
    }
    double sx=0, sy=0, sz=0, sxx=0, syy=0, szz=0, sxy=0, sxz=0, syz=0;
    #pragma unroll
    for (int k = 0; k < KN; k++) {
        int n = hi[k];
        float4 v = shp4[n];
        g_grouped[(gc*KN + k)*3 + 0] = v.x;
        g_grouped[(gc*KN + k)*3 + 1] = v.y;
        g_grouped[(gc*KN + k)*3 + 2] = v.z;
        sx += v.x; sy += v.y; sz += v.z;
        sxx += (double)v.x*v.x; syy += (double)v.y*v.y; szz += (double)v.z*v.z;
        sxy += (double)v.x*v.y; sxz += (double)v.x*v.z; syz += (double)v.y*v.z;
    }
    atomicAdd(&s9[0], sx);  atomicAdd(&s9[1], sy);  atomicAdd(&s9[2], sz);
    atomicAdd(&s9[3], sxx); atomicAdd(&s9[4], syy); atomicAdd(&s9[5], szz);
    atomicAdd(&s9[6], sxy); atomicAdd(&s9[7], sxz); atomicAdd(&s9[8], syz);
    __syncthreads();
    if (t < 9) atomicAdd(&g_sum9[t], s9[t]);
}

// ---------------- BN1 affine from analytic moments ----------------
__global__ void bn1k(const float* __restrict__ b2, const float* __restrict__ g1,
                     const float* __restrict__ b1) {
    int o = threadIdx.x;
    if (o >= 256) return;
    double inv = 1.0 / (double)JJ;
    double Ex = g_sum9[0]*inv, Ey = g_sum9[1]*inv, Ez = g_sum9[2]*inv;
    double Mxx = g_sum9[3]*inv, Myy = g_sum9[4]*inv, Mzz = g_sum9[5]*inv;
    double Mxy = g_sum9[6]*inv, Mxz = g_sum9[7]*inv, Myz = g_sum9[8]*inv;
    double w0 = g_Weff2[o*3], w1v = g_Weff2[o*3+1], w2v = g_Weff2[o*3+2];
    double bo = b2[o];
    double wEg = w0*Ex + w1v*Ey + w2v*Ez;
    double m = wEg + bo;
    double Ex2 = w0*w0*Mxx + w1v*w1v*Myy + w2v*w2v*Mzz
               + 2.0*(w0*w1v*Mxy + w0*w2v*Mxz + w1v*w2v*Myz)
               + 2.0*bo*wEg + bo*bo;
    double var = Ex2 - m*m;
    double s = (double)g1[o] / sqrt(var + EPSf);
    g_A1[o*3+0] = (float)(s*w0);
    g_A1[o*3+1] = (float)(s*w1v);
    g_A1[o*3+2] = (float)(s*w2v);
    g_c1v[o] = (float)((double)b1[o] + s*(bo - m));
}

// ---------------- pooled: Ph[tile][c] = fp16(max_k relu(A1.xyz + c1)) ----------------
__global__ void pgenk() {
    __shared__ float gsh[48];
    int t = threadIdx.x;
    float a0 = g_A1[t*3], a1 = g_A1[t*3+1], a2 = g_A1[t*3+2], c1 = g_c1v[t];
    for (int it = 0; it < 8; it++) {
        int tile = blockIdx.x*8 + it;
        __syncthreads();
        if (t < 48) gsh[t] = g_grouped[tile*48 + t];
        __syncthreads();
        float mx = 0.0f;
        #pragma unroll
        for (int k = 0; k < KN; k++)
            mx = fmaxf(mx, fmaxf(0.0f, fmaf(a0, gsh[k*3], fmaf(a1, gsh[k*3+1], fmaf(a2, gsh[k*3+2], c1)))));
        g_Ph[(size_t)tile*256 + t] = __float2half_rn(mx);
    }
}

// ================= GEMM0 (fp16): Zp[t][o] = sum_{c<256} w3[o][c]*pooled[t][c] =================
// CTA 128o x 128t, K=256 in 4 chunks of 64; 8 warps, warp tile 32x64.
#define G0_SMEM 69120
__global__ __launch_bounds__(256, 2) void tcg0() {
    extern __shared__ __align__(16) char smc[];
    float* smf = (float*)smc;
    uint32_t sb = smem_u32(smc);
    int t = threadIdx.x, lane = t & 31, wid = t >> 5;
    int wm = wid & 3, wn = wid >> 2;
    int t0 = blockIdx.x * 128, o0 = blockIdx.y * 128;

    float acc[2][8][4];
    #pragma unroll
    for (int mf = 0; mf < 2; mf++)
        #pragma unroll
        for (int nf = 0; nf < 8; nf++)
            #pragma unroll
            for (int e = 0; e < 4; e++) acc[mf][nf][e] = 0.0f;

    auto issue = [&](int buf, int kc) {
        uint32_t abb = sb + buf*16384;
        uint32_t bbb = sb + 32768 + buf*16384;
        #pragma unroll
        for (int i = 0; i < 4; i++) {
            int slot = t + 256*i; int o = slot >> 3, chR = slot & 7;
            CPA(abb + o*128 + ((chR ^ (o & 7)) << 4),
                &g_w3h[(size_t)(o0+o)*512 + kc*64 + chR*8]);
        }
        #pragma unroll
        for (int i = 0; i < 4; i++) {
            int slot = t + 256*i; int j = slot >> 3, chR = slot & 7;
            CPA(bbb + j*128 + ((chR ^ (j & 7)) << 4),
                &g_Ph[(size_t)(t0 + j)*256 + kc*64 + chR*8]);
        }
        CPA_COMMIT();
    };

    auto compute = [&](int buf) {
        uint32_t abase = sb + buf*16384;
        uint32_t bbase = sb + 32768 + buf*16384;
        int t7 = lane & 7, mi = lane >> 3;
        #pragma unroll
        for (int s = 0; s < 4; s++) {
            uint32_t a[2][4], b[8][2];
            #pragma unroll
            for (int mf = 0; mf < 2; mf++) {
                int row = wm*32 + mf*16 + ((mi & 1) << 3) + t7;
                int ch = 2*s + (mi >> 1);
                LDM4(a[mf][0], a[mf][1], a[mf][2], a[mf][3],
                     abase + row*128 + ((ch ^ (row & 7)) << 4));
            }
            #pragma unroll
            for (int np = 0; np < 4; np++) {
                int row = wn*64 + np*16 + ((mi >> 1) << 3) + t7;
                int ch = 2*s + (mi & 1);
                LDM4(b[2*np][0], b[2*np][1], b[2*np+1][0], b[2*np+1][1],
                     bbase + row*128 + ((ch ^ (row & 7)) << 4));
            }
            #pragma unroll
            for (int mf = 0; mf < 2; mf++)
                #pragma unroll
                for (int nf = 0; nf < 8; nf++)
                    MMA16(acc[mf][nf], a[mf], b[nf]);
        }
    };

    issue(0, 0);
    for (int kc = 0; kc < 4; kc++) {
        int cur = kc & 1;
        CPA_WAIT0();
        __syncthreads();
        if (kc < 3) issue(cur ^ 1, kc + 1);
        compute(cur);
    }
    __syncthreads();

    // transpose through smem (pad 132) then coalesced fp32 store
    int t4 = lane & 3, gr = lane >> 2;
    float* T = smf;
    #pragma unroll
    for (int mf = 0; mf < 2; mf++)
        #pragma unroll
        for (int nf = 0; nf < 8; nf++) {
            int orw = wm*32 + mf*16 + gr;
            int jl = wn*64 + nf*8 + 2*t4;
            T[jl*132 + orw]       = acc[mf][nf][0];
            T[(jl+1)*132 + orw]   = acc[mf][nf][1];
            T[jl*132 + orw + 8]   = acc[mf][nf][2];
            T[(jl+1)*132 + orw+8] = acc[mf][nf][3];
        }
    __syncthreads();
    int col4 = t & 31, wrow = t >> 5;
    #pragma unroll
    for (int r = 0; r < 16; r++) {
        int row = wrow + 8*r;
        float4 v = *(float4*)&T[row*132 + col4*4];
        *(float4*)&g_Zp[(size_t)(t0+row)*512 + o0 + col4*4] = v;
    }
}

// ================= GEMM1 (fp16): Z[j][o] = Zp[t(j)][o] + sum_c w3b[o][c]*H[j][c] =================
// CTA 128o x 128j, K=256 in 4 chunks of 64; 8 warps, warp tile 32x64.
#define G1_SMEM 75264
__global__ __launch_bounds__(256, 2) void tcg1() {
    extern __shared__ __align__(16) char smc[];
    float* smf = (float*)smc;
    uint32_t sb = smem_u32(smc);
    int t = threadIdx.x, lane = t & 31, wid = t >> 5;
    int wm = wid & 3, wn = wid >> 2;
    int j0 = blockIdx.x * 128, o0 = blockIdx.y * 128;
    float* sXYZ = (float*)(smc + 65536);       // 1536 B
    float* sA0 = (float*)(smc + 67072);        // 4096 B
    float* sA1p = sA0 + 256; float* sA2p = sA0 + 512; float* sCp = sA0 + 768;
    float* zpS = (float*)(smc + 71168);        // 4096 B : zp[tile_local][o_local]

    for (int i = t; i < 384; i += 256) sXYZ[i] = g_grouped[(size_t)j0*3 + i];
    sA0[t] = g_A1[t*3]; sA1p[t] = g_A1[t*3+1]; sA2p[t] = g_A1[t*3+2]; sCp[t] = g_c1v[t];

    float acc[2][8][4];
    #pragma unroll
    for (int mf = 0; mf < 2; mf++)
        #pragma unroll
        for (int nf = 0; nf < 8; nf++)
            #pragma unroll
            for (int e = 0; e < 4; e++) acc[mf][nf][e] = 0.0f;

    auto issue = [&](int buf, int kc) {
        uint32_t abb = sb + buf*16384;
        #pragma unroll
        for (int i = 0; i < 4; i++) {
            int slot = t + 256*i; int o = slot >> 3, chR = slot & 7;
            CPA(abb + o*128 + ((chR ^ (o & 7)) << 4),
                &g_w3h[(size_t)(o0+o)*512 + 256 + kc*64 + chR*8]);
        }
        char* Bp = smc + 32768 + buf*16384;
        int cb = kc*64;
        #pragma unroll
        for (int i = 0; i < 4; i++) {
            int slot = t + 256*i; int j = slot >> 3, chR = slot & 7;
            float x = sXYZ[j*3], y = sXYZ[j*3+1], z = sXYZ[j*3+2];
            int c = cb + chR*8;
            __half h[8];
            #pragma unroll
            for (int e = 0; e < 8; e++)
                h[e] = __float2half_rn(fmaxf(0.f,
                    fmaf(sA0[c+e], x, fmaf(sA1p[c+e], y, fmaf(sA2p[c+e], z, sCp[c+e])))));
            *(uint4*)(Bp + j*128 + ((chR ^ (j & 7)) << 4)) = *(uint4*)h;
        }
        CPA_COMMIT();
    };

    auto compute = [&](int buf) {
        uint32_t abase = sb + buf*16384;
        uint32_t bbase = sb + 32768 + buf*16384;
        int t7 = lane & 7, mi = lane >> 3;
        #pragma unroll
        for (int s = 0; s < 4; s++) {
            uint32_t a[2][4], b[8][2];
            #pragma unroll
            for (int mf = 0; mf < 2; mf++) {
                int row = wm*32 + mf*16 + ((mi & 1) << 3) + t7;
                int ch = 2*s + (mi >> 1);
                LDM4(a[mf][0], a[mf][1], a[mf][2], a[mf][3],
                     abase + row*128 + ((ch ^ (row & 7)) << 4));
            }
            #pragma unroll
            for (int np = 0; np < 4; np++) {
                int row = wn*64 + np*16 + ((mi >> 1) << 3) + t7;
                int ch = 2*s + (mi & 1);
                LDM4(b[2*np][0], b[2*np][1], b[2*np+1][0], b[2*np+1][1],
                     bbase + row*128 + ((ch ^ (row & 7)) << 4));
            }
            #pragma unroll
            for (int mf = 0; mf < 2; mf++)
                #pragma unroll
                for (int nf = 0; nf < 8; nf++)
                    MMA16(acc[mf][nf], a[mf], b[nf]);
        }
    };

    __syncthreads();                // sXYZ/params visible
    issue(0, 0);
    for (int kc = 0; kc < 4; kc++) {
        int cur = kc & 1;
        CPA_WAIT0();
        __syncthreads();
        if (kc < 3) issue(cur ^ 1, kc + 1);
        compute(cur);
    }
    __syncthreads();

    // load Zp slice: 8 tiles x 128 o = 1024 floats
    {
        int tb = j0 >> 4;
        int tl = t >> 5, ol = (t & 31) * 4;
        float4 v = *(const float4*)&g_Zp[(size_t)(tb + tl)*512 + o0 + ol];
        *(float4*)&zpS[tl*128 + ol] = v;
    }
    __syncthreads();

    int t4 = lane & 3, gr = lane >> 2;
    // add pooled contribution into accumulators
    #pragma unroll
    for (int mf = 0; mf < 2; mf++) {
        int orw = wm*32 + mf*16 + gr;
        #pragma unroll
        for (int nf = 0; nf < 8; nf++) {
            int tl = wn*4 + (nf >> 1);
            float zp0 = zpS[tl*128 + orw];
            float zp1 = zpS[tl*128 + orw + 8];
            acc[mf][nf][0] += zp0; acc[mf][nf][1] += zp0;
            acc[mf][nf][2] += zp1; acc[mf][nf][3] += zp1;
        }
    }

    // stats via quad shuffles
    #pragma unroll
    for (int mf = 0; mf < 2; mf++)
        #pragma unroll
        for (int rs = 0; rs < 2; rs++) {
            double s = 0.0, q = 0.0;
            #pragma unroll
            for (int nf = 0; nf < 8; nf++) {
                float v0 = acc[mf][nf][rs*2], v1 = acc[mf][nf][rs*2+1];
                s += (double)v0 + (double)v1;
                q += (double)v0*(double)v0 + (double)v1*(double)v1;
            }
            s += __shfl_xor_sync(0xffffffffu, s, 1); s += __shfl_xor_sync(0xffffffffu, s, 2);
            q += __shfl_xor_sync(0xffffffffu, q, 1); q += __shfl_xor_sync(0xffffffffu, q, 2);
            if (t4 == 0) {
                int o = o0 + wm*32 + mf*16 + rs*8 + gr;
                atomicAdd(&g_bn3sum[o], s); atomicAdd(&g_bn3sq[o], q);
            }
        }

    // transpose through smem (pad 132) then coalesced fp16 store
    float* T = smf;
    #pragma unroll
    for (int mf = 0; mf < 2; mf++)
        #pragma unroll
        for (int nf = 0; nf < 8; nf++) {
            int orw = wm*32 + mf*16 + gr;
            int jl = wn*64 + nf*8 + 2*t4;
            T[jl*132 + orw]       = acc[mf][nf][0];
            T[(jl+1)*132 + orw]   = acc[mf][nf][1];
            T[jl*132 + orw + 8]   = acc[mf][nf][2];
            T[(jl+1)*132 + orw+8] = acc[mf][nf][3];
        }
    __syncthreads();
    int cg16 = t & 15, rr = t >> 4;
    #pragma unroll
    for (int r = 0; r < 8; r++) {
        int row = rr + 16*r;
        float4 v0 = *(float4*)&T[row*132 + cg16*8];
        float4 v1 = *(float4*)&T[row*132 + cg16*8 + 4];
        __half h[8];
        h[0] = __float2half_rn(v0.x); h[1] = __float2half_rn(v0.y);
        h[2] = __float2half_rn(v0.z); h[3] = __float2half_rn(v0.w);
        h[4] = __float2half_rn(v1.x); h[5] = __float2half_rn(v1.y);
        h[6] = __float2half_rn(v1.z); h[7] = __float2half_rn(v1.w);
        *(uint4*)&g_Zh[(size_t)(j0+row)*512 + o0 + cg16*8] = *(uint4*)h;
    }
}

// ================= GEMM2 (fp16 m16n8k16): stats + max_k of w4 @ relu(bn3(Z)) =================
// CTA 256o x 128j, K=512 in 8 chunks of 64; 8 warps, warp tile 64x64.
#define G2_SMEM 102400
__global__ __launch_bounds__(256, 1) void tcg2() {
    extern __shared__ __align__(16) char smc[];
    uint32_t sb = smem_u32(smc);
    int t = threadIdx.x, lane = t & 31, wid = t >> 5;
    int wm = wid & 3, wn = wid >> 2;
    int j0 = blockIdx.x * 128;
    float* sa3 = (float*)(smc + 98304);
    float* sd3 = sa3 + 512;
    for (int i = t; i < 512; i += 256) { sa3[i] = g_a3[i]; sd3[i] = g_d3[i]; }

    float acc[4][8][4];
    #pragma unroll
    for (int mf = 0; mf < 4; mf++)
        #pragma unroll
        for (int nf = 0; nf < 8; nf++)
            #pragma unroll
            for (int e = 0; e < 4; e++) acc[mf][nf][e] = 0.0f;

    auto issueA = [&](int buf, int kc) {
        uint32_t abb = sb + buf*32768;
        #pragma unroll
        for (int i = 0; i < 8; i++) {
            int slot = t + 256*i; int o = slot >> 3, chR = slot & 7;
            CPA(abb + o*128 + ((chR ^ (o & 7)) << 4),
                &g_w4h[(size_t)o*512 + kc*64 + chR*8]);
        }
        CPA_COMMIT();
    };
    auto loadB = [&](int kc, uint4* br) {
        #pragma unroll
        for (int i = 0; i < 4; i++) {
            int slot = t + 256*i;
            int j = slot >> 3, chR = slot & 7;
            br[i] = *(const uint4*)&g_Zh[(size_t)(j0+j)*512 + kc*64 + chR*8];
        }
    };
    auto storeB = [&](int buf, int kc, const uint4* br) {
        char* Bp = smc + 65536 + buf*16384;
        #pragma unroll
        for (int i = 0; i < 4; i++) {
            int slot = t + 256*i;
            int j = slot >> 3, chR = slot & 7;
            const __half* h = (const __half*)&br[i];
            int c = kc*64 + chR*8;
            __half v[8];
            #pragma unroll
            for (int e = 0; e < 8; e++)
                v[e] = __float2half_rn(fmaxf(0.f, fmaf(__half2float(h[e]), sa3[c+e], sd3[c+e])));
            *(uint4*)(Bp + j*128 + ((chR ^ (j & 7)) << 4)) = *(uint4*)v;
        }
    };
    auto compute = [&](int buf) {
        uint32_t abase = sb + buf*32768;
        uint32_t bbase = sb + 65536 + buf*16384;
        int t7 = lane & 7, mi = lane >> 3;
        #pragma unroll
        for (int s = 0; s < 4; s++) {
            uint32_t a[4][4], b[8][2];
            #pragma unroll
            for (int mf = 0; mf < 4; mf++) {
                int row = wm*64 + mf*16 + ((mi & 1) << 3) + t7;
                int ch = 2*s + (mi >> 1);
                LDM4(a[mf][0], a[mf][1], a[mf][2], a[mf][3],
                     abase + row*128 + ((ch ^ (row & 7)) << 4));
            }
            #pragma unroll
            for (int np = 0; np < 4; np++) {
                int row = wn*64 + np*16 + ((mi >> 1) << 3) + t7;
                int ch = 2*s + (mi & 1);
                LDM4(b[2*np][0], b[2*np][1], b[2*np+1][0], b[2*np+1][1],
                     bbase + row*128 + ((ch ^ (row & 7)) << 4));
            }
            #pragma unroll
            for (int mf = 0; mf < 4; mf++)
                #pragma unroll
                for (int nf = 0; nf < 8; nf++)
                    MMA16(acc[mf][nf], a[mf], b[nf]);
        }
    };

    __syncthreads();
    issueA(0, 0);
    {
        uint4 br0[4];
        loadB(0, br0);
        storeB(0, 0, br0);
    }
    uint4 br[4];
    for (int kc = 0; kc < 8; kc++) {
        int cur = kc & 1;
        CPA_WAIT0();
        __syncthreads();
        if (kc < 7) { issueA(cur ^ 1, kc + 1); loadB(kc + 1, br); }
        compute(cur);
        if (kc < 7) storeB(cur ^ 1, kc + 1, br);
    }

    int t4 = lane & 3, gr = lane >> 2;
    int jt0 = (j0 >> 4) + wn*4;
    #pragma unroll
    for (int mf = 0; mf < 4; mf++)
        #pragma unroll
        for (int rs = 0; rs < 2; rs++) {
            int o = wm*64 + mf*16 + rs*8 + gr;
            double s = 0.0, q = 0.0;
            #pragma unroll
            for (int nf = 0; nf < 8; nf++) {
                float v0 = acc[mf][nf][rs*2], v1 = acc[mf][nf][rs*2+1];
                s += (double)v0 + (double)v1;
                q += (double)v0*(double)v0 + (double)v1*(double)v1;
            }
            s += __shfl_xor_sync(0xffffffffu, s, 1); s += __shfl_xor_sync(0xffffffffu, s, 2);
            q += __shfl_xor_sync(0xffffffffu, q, 1); q += __shfl_xor_sync(0xffffffffu, q, 2);
            if (t4 == 0) { atomicAdd(&g_bn4sum[o], s); atomicAdd(&g_bn4sq[o], q); }
            #pragma unroll
            for (int tt = 0; tt < 4; tt++) {
                float m = fmaxf(fmaxf(acc[mf][2*tt][rs*2], acc[mf][2*tt][rs*2+1]),
                                fmaxf(acc[mf][2*tt+1][rs*2], acc[mf][2*tt+1][rs*2+1]));
                m = fmaxf(m, __shfl_xor_sync(0xffffffffu, m, 1));
                m = fmaxf(m, __shfl_xor_sync(0xffffffffu, m, 2));
                if (t4 == 0) g_M4[(size_t)(jt0 + tt)*256 + o] = m;
            }
        }
}

// ---------------- BN affine params ----------------
__global__ void bn3aff(const float* __restrict__ g, const float* __restrict__ b) {
    int c = threadIdx.x;
    if (c >= 512) return;
    double inv = 1.0 / (double)JJ;
    double m = g_bn3sum[c]*inv;
    double var = g_bn3sq[c]*inv - m*m;
    float a = (float)((double)g[c] / sqrt(var + EPSf));
    g_a3[c] = a;
    g_d3[c] = b[c] - (float)m * a;
}
__global__ void bn4aff(const float* __restrict__ g, const float* __restrict__ b) {
    int c = threadIdx.x;
    if (c >= 256) return;
    double inv = 1.0 / (double)JJ;
    double m = g_bn4sum[c]*inv;
    double var = g_bn4sq[c]*inv - m*m;
    float a = (float)((double)g[c] / sqrt(var + EPSf));
    g_a4[c] = a;
    g_d4[c] = b[c] - (float)m * a;
}

// ---------------- final: feat[b][o][ns] = relu(a4*M4 + d4)  (a4>0) ----------------
__global__ void finalk(float* __restrict__ out) {
    __shared__ float sm[32*257];
    int b = blockIdx.x >> 4, chunk = blockIdx.x & 15, t = threadIdx.x;
    int tile0 = b*512 + chunk*32;
    for (int i = t; i < 8192; i += 256) {
        int tl = i >> 8, o = i & 255;
        sm[tl*257 + o] = g_M4[(size_t)(tile0 + tl)*256 + o];
    }
    __syncthreads();
    int nsl = t & 31, og = t >> 5;
    for (int pass = 0; pass < 32; pass++) {
        int o = pass*8 + og;
        float a = g_a4[o], d = g_d4[o];
        float v = fmaxf(0.0f, fmaf(sm[nsl*257 + o], a, d));
        out[Bb*NSd*3 + b*131072 + o*512 + chunk*32 + nsl] = v;
    }
}

// ---------------- launch ----------------
extern "C" void kernel_launch(void* const* d_in, const int* in_sizes, int n_in,
                              void* d_out, int out_size) {
    const float* p    = (const float*)d_in[0];
    const float* w1   = (const float*)d_in[1];
    const float* w2   = (const float*)d_in[2];
    const float* b2   = (const float*)d_in[3];
    const float* bn1g = (const float*)d_in[4];
    const float* bn1b = (const float*)d_in[5];
    const float* w3   = (const float*)d_in[6];
    const float* bn3g = (const float*)d_in[7];
    const float* bn3b = (const float*)d_in[8];
    const float* w4   = (const float*)d_in[9];
    const float* bn4g = (const float*)d_in[10];
    const float* bn4b = (const float*)d_in[11];
    float* out = (float*)d_out;

    cudaFuncSetAttribute(tcg0, cudaFuncAttributeMaxDynamicSharedMemorySize, G0_SMEM);
    cudaFuncSetAttribute(tcg1, cudaFuncAttributeMaxDynamicSharedMemorySize, G1_SMEM);
    cudaFuncSetAttribute(tcg2, cudaFuncAttributeMaxDynamicSharedMemorySize, G2_SMEM);

    zerok<<<1, 512>>>();
    precompk<<<1, 256>>>(w1, w2);
    roundwk<<<512, 512>>>(w3, w4);
    fpsk<<<32, 256>>>(p, out);                 // centroids -> out[0:49152]
    knnk<<<256, 64>>>(p, out);
    bn1k<<<1, 256>>>(b2, bn1g, bn1b);
    pgenk<<<NT/8, 256>>>();
    tcg0<<<dim3(NT/128, 4), 256, G0_SMEM>>>();
    tcg1<<<dim3(JJ/128, 4), 256, G1_SMEM>>>();
    bn3aff<<<1, 512>>>(bn3g, bn3b);
    tcg2<<<JJ/128, 256, G2_SMEM>>>();
    bn4aff<<<1, 256>>>(bn4g, bn4b);
    finalk<<<Bb*16, 256>>>(out);
}

// round 14
// speedup vs baseline: 2.7028x; 1.0324x over previous
#include <cuda_runtime.h>
#include <cuda_fp16.h>
#include <cstdint>

#define Bb 32
#define Np 2048
#define NSd 512
#define KN 16
#define NT (Bb*NSd)          // 16384 tiles
#define JJ (NT*KN)           // 262144 columns
#define EPSf 1e-5

// ---------------- scratch ----------------
__device__ float  g_grouped[NT*KN*3];
__device__ double g_sum9[9];
__device__ float  g_Weff2[256*3];
__device__ float  g_A1[256*3];
__device__ float  g_c1v[256];
__device__ __half g_Ph [NT*256];               // pooled [tile][c] fp16
__device__ __half g_w3h[512*512];              // fp16 w3
__device__ __half g_w4h[256*512];              // fp16 w4
__device__ float  g_Zp[(size_t)NT*512];        // 32 MB  Zp[t][o] = w3a @ pooled
__device__ __half g_Zh[(size_t)JJ*512];        // 268 MB  [j][c] fp16
__device__ float  g_M4[NT*256];                // max_k conv4-out [tile][o]
__device__ double g_bn3sum[512], g_bn3sq[512], g_bn4sum[256], g_bn4sq[256];
__device__ float  g_a3[512], g_d3[512], g_a4[256], g_d4[256];

// ---------------- helpers ----------------
__device__ __forceinline__ uint32_t smem_u32(const void* p) {
    uint32_t a;
    asm("{ .reg .u64 t; cvta.to.shared.u64 t, %1; cvt.u32.u64 %0, t; }" : "=r"(a) : "l"(p));
    return a;
}
#define LDM4(r0,r1,r2,r3,addr) \
    asm volatile("ldmatrix.sync.aligned.m8n8.x4.shared.b16 {%0,%1,%2,%3}, [%4];" \
        : "=r"(r0),"=r"(r1),"=r"(r2),"=r"(r3) : "r"(addr))
#define MMA16(c, a, b) \
    asm volatile("mma.sync.aligned.m16n8k16.row.col.f32.f16.f16.f32 " \
        "{%0,%1,%2,%3}, {%4,%5,%6,%7}, {%8,%9}, {%0,%1,%2,%3};" \
        : "+f"((c)[0]),"+f"((c)[1]),"+f"((c)[2]),"+f"((c)[3]) \
        : "r"((a)[0]),"r"((a)[1]),"r"((a)[2]),"r"((a)[3]), "r"((b)[0]),"r"((b)[1]))
#define CPA(dst, src) asm volatile("cp.async.cg.shared.global [%0], [%1], 16;" ::"r"(dst),"l"(src))
#define CPA_COMMIT()  asm volatile("cp.async.commit_group;" ::: "memory")
#define CPA_WAIT0()   asm volatile("cp.async.wait_group 0;" ::: "memory")

// ---------------- zero accumulators (graph replays!) ----------------
__global__ void zerok() {
    int t = threadIdx.x;
    if (t < 9) g_sum9[t] = 0.0;
    for (int i = t; i < 512; i += blockDim.x) { g_bn3sum[i] = 0.0; g_bn3sq[i] = 0.0; }
    for (int i = t; i < 256; i += blockDim.x) { g_bn4sum[i] = 0.0; g_bn4sq[i] = 0.0; }
}

__global__ void precompk(const float* __restrict__ w1, const float* __restrict__ w2) {
    int t = threadIdx.x;
    if (t < 256) {
        double s0 = 0.0, s1 = 0.0, s2 = 0.0;
        for (int i = 0; i < 256; i++) {
            double wi = (double)w2[t*256 + i];
            s0 += wi * ((double)w1[i*6+0] + (double)w1[i*6+3]);
            s1 += wi * ((double)w1[i*6+1] + (double)w1[i*6+4]);
            s2 += wi * ((double)w1[i*6+2] + (double)w1[i*6+5]);
        }
        g_Weff2[t*3+0] = (float)s0; g_Weff2[t*3+1] = (float)s1; g_Weff2[t*3+2] = (float)s2;
    }
}

// pre-round weights to fp16
__global__ void roundwk(const float* __restrict__ w3, const float* __restrict__ w4) {
    int i = blockIdx.x*512 + threadIdx.x;
    if (i < 512*512) g_w3h[i] = __float2half_rn(w3[i]);
    if (i < 256*512) g_w4h[i] = __float2half_rn(w4[i]);
}

// ---------------- FPS: 32 blocks x 256 threads, 8 pts/thread, 1 barrier/step ----------------
__global__ void fpsk(const float* __restrict__ p, float* __restrict__ outc) {
    __shared__ float sp[Np*3];
    __shared__ unsigned long long skey[2][8];
    int b = blockIdx.x, t = threadIdx.x;
    for (int i = t; i < Np*3; i += 256) sp[i] = p[b*Np*3 + i];
    __syncthreads();
    float px[8], py[8], pz[8], dist[8];
    #pragma unroll
    for (int i = 0; i < 8; i++) {
        int n = t + 256*i;
        px[i] = sp[n*3+0]; py[i] = sp[n*3+1]; pz[i] = sp[n*3+2];
        dist[i] = 1e10f;
    }
    int lane = t & 31, wid = t >> 5;
    int cs = 0;
    for (int s = 0; s < NSd; s++) {
        if (t == 0) {
            outc[(b*NSd + s)*3 + 0] = sp[cs*3+0];
            outc[(b*NSd + s)*3 + 1] = sp[cs*3+1];
            outc[(b*NSd + s)*3 + 2] = sp[cs*3+2];
        }
        float cx = sp[cs*3+0], cy = sp[cs*3+1], cz = sp[cs*3+2];
        unsigned long long best = 0ull;
        #pragma unroll
        for (int i = 0; i < 8; i++) {
            float dx = __fadd_rn(px[i], -cx);
            float dy = __fadd_rn(py[i], -cy);
            float dz = __fadd_rn(pz[i], -cz);
            float d = __fadd_rn(__fadd_rn(__fmul_rn(dx,dx), __fmul_rn(dy,dy)), __fmul_rn(dz,dz));
            dist[i] = fminf(dist[i], d);
            unsigned long long key = ((unsigned long long)__float_as_uint(dist[i]) << 32)
                                   | (unsigned)(Np - 1 - (t + 256*i));
            best = max(best, key);
        }
        #pragma unroll
        for (int off = 16; off; off >>= 1)
            best = max(best, __shfl_down_sync(0xffffffffu, best, off));
        if (lane == 0) skey[s & 1][wid] = best;
        __syncthreads();
        const unsigned long long* sk = skey[s & 1];
        unsigned long long k2 = max(max(max(sk[0], sk[1]), max(sk[2], sk[3])),
                                    max(max(sk[4], sk[5]), max(sk[6], sk[7])));
        cs = Np - 1 - (int)(unsigned)(k2 & 0xffffffffull);
    }
}

// ---------------- kNN: 256 blocks x 64 threads, float4-packed smem ----------------
__global__ void knnk(const float* __restrict__ p, const float* __restrict__ cntrd) {
    __shared__ float4 shp4[Np];                // (x, y, z, |p|^2) — 32 KB
    __shared__ double s9[9];
    int t = threadIdx.x;
    int gc = blockIdx.x*64 + t;
    int b = blockIdx.x >> 3;
    for (int n = t; n < Np; n += 64) {
        float x = p[b*Np*3 + n*3 + 0];
        float y = p[b*Np*3 + n*3 + 1];
        float z = p[b*Np*3 + n*3 + 2];
        float p2 = __fadd_rn(__fadd_rn(__fmul_rn(x,x), __fmul_rn(y,y)), __fmul_rn(z,z));
        shp4[n] = make_float4(x, y, z, p2);
    }
    if (t < 9) s9[t] = 0.0;
    __syncthreads();
    float cx = cntrd[gc*3+0], cy = cntrd[gc*3+1], cz = cntrd[gc*3+2];
    float c2 = __fadd_rn(__fadd_rn(__fmul_rn(cx,cx), __fmul_rn(cy,cy)), __fmul_rn(cz,cz));
    float hd[KN]; int hi[KN];
    #pragma unroll
    for (int k = 0; k < KN; k++) { hd[k] = 3.4e38f; hi[k] = 0; }
    for (int n = 0; n < Np; n++) {
        float4 v = shp4[n];
        float dot = __fadd_rn(__fadd_rn(__fmul_rn(cx, v.x),
                                        __fmul_rn(cy, v.y)),
                              __fmul_rn(cz, v.z));
        float d2 = __fadd_rn(__fadd_rn(c2, v.w), -__fmul_rn(2.0f, dot));
        if (d2 < hd[KN-1]) {
            hd[KN-1] = d2; hi[KN-1] = n;
            #pragma unroll
            for (int j = KN-1; j > 0; --j) {
                bool sw = hd[j] < hd[j-1];
                float td = hd[j]; int ti = hi[j];
                float tdm = hd[j-1]; int tim = hi[j-1];
                hd[j]   = sw ? tdm : td;   hi[j]   = sw ? tim : ti;
                hd[j-1] = sw ? td  : tdm;  hi[j-1] = sw ? ti  : tim;
            }
        }
    }
    double sx=0, sy=0, sz=0, sxx=0, syy=0, szz=0, sxy=0, sxz=0, syz=0;
    #pragma unroll
    for (int k = 0; k < KN; k++) {
        int n = hi[k];
        float4 v = shp4[n];
        g_grouped[(gc*KN + k)*3 + 0] = v.x;
        g_grouped[(gc*KN + k)*3 + 1] = v.y;
        g_grouped[(gc*KN + k)*3 + 2] = v.z;
        sx += v.x; sy += v.y; sz += v.z;
        sxx += (double)v.x*v.x; syy += (double)v.y*v.y; szz += (double)v.z*v.z;
        sxy += (double)v.x*v.y; sxz += (double)v.x*v.z; syz += (double)v.y*v.z;
    }
    atomicAdd(&s9[0], sx);  atomicAdd(&s9[1], sy);  atomicAdd(&s9[2], sz);
    atomicAdd(&s9[3], sxx); atomicAdd(&s9[4], syy); atomicAdd(&s9[5], szz);
    atomicAdd(&s9[6], sxy); atomicAdd(&s9[7], sxz); atomicAdd(&s9[8], syz);
    __syncthreads();
    if (t < 9) atomicAdd(&g_sum9[t], s9[t]);
}

// ---------------- BN1 affine from analytic moments ----------------
__global__ void bn1k(const float* __restrict__ b2, const float* __restrict__ g1,
                     const float* __restrict__ b1) {
    int o = threadIdx.x;
    if (o >= 256) return;
    double inv = 1.0 / (double)JJ;
    double Ex = g_sum9[0]*inv, Ey = g_sum9[1]*inv, Ez = g_sum9[2]*inv;
    double Mxx = g_sum9[3]*inv, Myy = g_sum9[4]*inv, Mzz = g_sum9[5]*inv;
    double Mxy = g_sum9[6]*inv, Mxz = g_sum9[7]*inv, Myz = g_sum9[8]*inv;
    double w0 = g_Weff2[o*3], w1v = g_Weff2[o*3+1], w2v = g_Weff2[o*3+2];
    double bo = b2[o];
    double wEg = w0*Ex + w1v*Ey + w2v*Ez;
    double m = wEg + bo;
    double Ex2 = w0*w0*Mxx + w1v*w1v*Myy + w2v*w2v*Mzz
               + 2.0*(w0*w1v*Mxy + w0*w2v*Mxz + w1v*w2v*Myz)
               + 2.0*bo*wEg + bo*bo;
    double var = Ex2 - m*m;
    double s = (double)g1[o] / sqrt(var + EPSf);
    g_A1[o*3+0] = (float)(s*w0);
    g_A1[o*3+1] = (float)(s*w1v);
    g_A1[o*3+2] = (float)(s*w2v);
    g_c1v[o] = (float)((double)b1[o] + s*(bo - m));
}

// ---------------- pooled: Ph[tile][c] = fp16(max_k relu(A1.xyz + c1)) ----------------
__global__ void pgenk() {
    __shared__ float gsh[48];
    int t = threadIdx.x;
    float a0 = g_A1[t*3], a1 = g_A1[t*3+1], a2 = g_A1[t*3+2], c1 = g_c1v[t];
    for (int it = 0; it < 8; it++) {
        int tile = blockIdx.x*8 + it;
        __syncthreads();
        if (t < 48) gsh[t] = g_grouped[tile*48 + t];
        __syncthreads();
        float mx = 0.0f;
        #pragma unroll
        for (int k = 0; k < KN; k++)
            mx = fmaxf(mx, fmaxf(0.0f, fmaf(a0, gsh[k*3], fmaf(a1, gsh[k*3+1], fmaf(a2, gsh[k*3+2], c1)))));
        g_Ph[(size_t)tile*256 + t] = __float2half_rn(mx);
    }
}

// ================= GEMM0 (fp16): Zp[t][o] = sum_{c<256} w3[o][c]*pooled[t][c] =================
#define G0_SMEM 69120
__global__ __launch_bounds__(256, 2) void tcg0() {
    extern __shared__ __align__(16) char smc[];
    float* smf = (float*)smc;
    uint32_t sb = smem_u32(smc);
    int t = threadIdx.x, lane = t & 31, wid = t >> 5;
    int wm = wid & 3, wn = wid >> 2;
    int t0 = blockIdx.x * 128, o0 = blockIdx.y * 128;

    float acc[2][8][4];
    #pragma unroll
    for (int mf = 0; mf < 2; mf++)
        #pragma unroll
        for (int nf = 0; nf < 8; nf++)
            #pragma unroll
            for (int e = 0; e < 4; e++) acc[mf][nf][e] = 0.0f;

    auto issue = [&](int buf, int kc) {
        uint32_t abb = sb + buf*16384;
        uint32_t bbb = sb + 32768 + buf*16384;
        #pragma unroll
        for (int i = 0; i < 4; i++) {
            int slot = t + 256*i; int o = slot >> 3, chR = slot & 7;
            CPA(abb + o*128 + ((chR ^ (o & 7)) << 4),
                &g_w3h[(size_t)(o0+o)*512 + kc*64 + chR*8]);
        }
        #pragma unroll
        for (int i = 0; i < 4; i++) {
            int slot = t + 256*i; int j = slot >> 3, chR = slot & 7;
            CPA(bbb + j*128 + ((chR ^ (j & 7)) << 4),
                &g_Ph[(size_t)(t0 + j)*256 + kc*64 + chR*8]);
        }
        CPA_COMMIT();
    };

    auto compute = [&](int buf) {
        uint32_t abase = sb + buf*16384;
        uint32_t bbase = sb + 32768 + buf*16384;
        int t7 = lane & 7, mi = lane >> 3;
        #pragma unroll
        for (int s = 0; s < 4; s++) {
            uint32_t a[2][4], b[8][2];
            #pragma unroll
            for (int mf = 0; mf < 2; mf++) {
                int row = wm*32 + mf*16 + ((mi & 1) << 3) + t7;
                int ch = 2*s + (mi >> 1);
                LDM4(a[mf][0], a[mf][1], a[mf][2], a[mf][3],
                     abase + row*128 + ((ch ^ (row & 7)) << 4));
            }
            #pragma unroll
            for (int np = 0; np < 4; np++) {
                int row = wn*64 + np*16 + ((mi >> 1) << 3) + t7;
                int ch = 2*s + (mi & 1);
                LDM4(b[2*np][0], b[2*np][1], b[2*np+1][0], b[2*np+1][1],
                     bbase + row*128 + ((ch ^ (row & 7)) << 4));
            }
            #pragma unroll
            for (int mf = 0; mf < 2; mf++)
                #pragma unroll
                for (int nf = 0; nf < 8; nf++)
                    MMA16(acc[mf][nf], a[mf], b[nf]);
        }
    };

    issue(0, 0);
    for (int kc = 0; kc < 4; kc++) {
        int cur = kc & 1;
        CPA_WAIT0();
        __syncthreads();
        if (kc < 3) issue(cur ^ 1, kc + 1);
        compute(cur);
    }
    __syncthreads();

    int t4 = lane & 3, gr = lane >> 2;
    float* T = smf;
    #pragma unroll
    for (int mf = 0; mf < 2; mf++)
        #pragma unroll
        for (int nf = 0; nf < 8; nf++) {
            int orw = wm*32 + mf*16 + gr;
            int jl = wn*64 + nf*8 + 2*t4;
            T[jl*132 + orw]       = acc[mf][nf][0];
            T[(jl+1)*132 + orw]   = acc[mf][nf][1];
            T[jl*132 + orw + 8]   = acc[mf][nf][2];
            T[(jl+1)*132 + orw+8] = acc[mf][nf][3];
        }
    __syncthreads();
    int col4 = t & 31, wrow = t >> 5;
    #pragma unroll
    for (int r = 0; r < 16; r++) {
        int row = wrow + 8*r;
        float4 v = *(float4*)&T[row*132 + col4*4];
        *(float4*)&g_Zp[(size_t)(t0+row)*512 + o0 + col4*4] = v;
    }
}

// ================= GEMM1 (fp16): Z[j][o] = Zp[t(j)][o] + sum_c w3b[o][c]*H[j][c] =================
#define G1_SMEM 75264
__global__ __launch_bounds__(256, 2) void tcg1() {
    extern __shared__ __align__(16) char smc[];
    float* smf = (float*)smc;
    uint32_t sb = smem_u32(smc);
    int t = threadIdx.x, lane = t & 31, wid = t >> 5;
    int wm = wid & 3, wn = wid >> 2;
    int j0 = blockIdx.x * 128, o0 = blockIdx.y * 128;
    float* sXYZ = (float*)(smc + 65536);
    float* sA0 = (float*)(smc + 67072);
    float* sA1p = sA0 + 256; float* sA2p = sA0 + 512; float* sCp = sA0 + 768;
    float* zpS = (float*)(smc + 71168);

    for (int i = t; i < 384; i += 256) sXYZ[i] = g_grouped[(size_t)j0*3 + i];
    sA0[t] = g_A1[t*3]; sA1p[t] = g_A1[t*3+1]; sA2p[t] = g_A1[t*3+2]; sCp[t] = g_c1v[t];

    float acc[2][8][4];
    #pragma unroll
    for (int mf = 0; mf < 2; mf++)
        #pragma unroll
        for (int nf = 0; nf < 8; nf++)
            #pragma unroll
            for (int e = 0; e < 4; e++) acc[mf][nf][e] = 0.0f;

    auto issue = [&](int buf, int kc) {
        uint32_t abb = sb + buf*16384;
        #pragma unroll
        for (int i = 0; i < 4; i++) {
            int slot = t + 256*i; int o = slot >> 3, chR = slot & 7;
            CPA(abb + o*128 + ((chR ^ (o & 7)) << 4),
                &g_w3h[(size_t)(o0+o)*512 + 256 + kc*64 + chR*8]);
        }
        char* Bp = smc + 32768 + buf*16384;
        int cb = kc*64;
        #pragma unroll
        for (int i = 0; i < 4; i++) {
            int slot = t + 256*i; int j = slot >> 3, chR = slot & 7;
            float x = sXYZ[j*3], y = sXYZ[j*3+1], z = sXYZ[j*3+2];
            int c = cb + chR*8;
            __half h[8];
            #pragma unroll
            for (int e = 0; e < 8; e++)
                h[e] = __float2half_rn(fmaxf(0.f,
                    fmaf(sA0[c+e], x, fmaf(sA1p[c+e], y, fmaf(sA2p[c+e], z, sCp[c+e])))));
            *(uint4*)(Bp + j*128 + ((chR ^ (j & 7)) << 4)) = *(uint4*)h;
        }
        CPA_COMMIT();
    };

    auto compute = [&](int buf) {
        uint32_t abase = sb + buf*16384;
        uint32_t bbase = sb + 32768 + buf*16384;
        int t7 = lane & 7, mi = lane >> 3;
        #pragma unroll
        for (int s = 0; s < 4; s++) {
            uint32_t a[2][4], b[8][2];
            #pragma unroll
            for (int mf = 0; mf < 2; mf++) {
                int row = wm*32 + mf*16 + ((mi & 1) << 3) + t7;
                int ch = 2*s + (mi >> 1);
                LDM4(a[mf][0], a[mf][1], a[mf][2], a[mf][3],
                     abase + row*128 + ((ch ^ (row & 7)) << 4));
            }
            #pragma unroll
            for (int np = 0; np < 4; np++) {
                int row = wn*64 + np*16 + ((mi >> 1) << 3) + t7;
                int ch = 2*s + (mi & 1);
                LDM4(b[2*np][0], b[2*np][1], b[2*np+1][0], b[2*np+1][1],
                     bbase + row*128 + ((ch ^ (row & 7)) << 4));
            }
            #pragma unroll
            for (int mf = 0; mf < 2; mf++)
                #pragma unroll
                for (int nf = 0; nf < 8; nf++)
                    MMA16(acc[mf][nf], a[mf], b[nf]);
        }
    };

    __syncthreads();
    issue(0, 0);
    for (int kc = 0; kc < 4; kc++) {
        int cur = kc & 1;
        CPA_WAIT0();
        __syncthreads();
        if (kc < 3) issue(cur ^ 1, kc + 1);
        compute(cur);
    }
    __syncthreads();

    {
        int tb = j0 >> 4;
        int tl = t >> 5, ol = (t & 31) * 4;
        float4 v = *(const float4*)&g_Zp[(size_t)(tb + tl)*512 + o0 + ol];
        *(float4*)&zpS[tl*128 + ol] = v;
    }
    __syncthreads();

    int t4 = lane & 3, gr = lane >> 2;
    #pragma unroll
    for (int mf = 0; mf < 2; mf++) {
        int orw = wm*32 + mf*16 + gr;
        #pragma unroll
        for (int nf = 0; nf < 8; nf++) {
            int tl = wn*4 + (nf >> 1);
            float zp0 = zpS[tl*128 + orw];
            float zp1 = zpS[tl*128 + orw + 8];
            acc[mf][nf][0] += zp0; acc[mf][nf][1] += zp0;
            acc[mf][nf][2] += zp1; acc[mf][nf][3] += zp1;
        }
    }

    #pragma unroll
    for (int mf = 0; mf < 2; mf++)
        #pragma unroll
        for (int rs = 0; rs < 2; rs++) {
            double s = 0.0, q = 0.0;
            #pragma unroll
            for (int nf = 0; nf < 8; nf++) {
                float v0 = acc[mf][nf][rs*2], v1 = acc[mf][nf][rs*2+1];
                s += (double)v0 + (double)v1;
                q += (double)v0*(double)v0 + (double)v1*(double)v1;
            }
            s += __shfl_xor_sync(0xffffffffu, s, 1); s += __shfl_xor_sync(0xffffffffu, s, 2);
            q += __shfl_xor_sync(0xffffffffu, q, 1); q += __shfl_xor_sync(0xffffffffu, q, 2);
            if (t4 == 0) {
                int o = o0 + wm*32 + mf*16 + rs*8 + gr;
                atomicAdd(&g_bn3sum[o], s); atomicAdd(&g_bn3sq[o], q);
            }
        }

    float* T = smf;
    #pragma unroll
    for (int mf = 0; mf < 2; mf++)
        #pragma unroll
        for (int nf = 0; nf < 8; nf++) {
            int orw = wm*32 + mf*16 + gr;
            int jl = wn*64 + nf*8 + 2*t4;
            T[jl*132 + orw]       = acc[mf][nf][0];
            T[(jl+1)*132 + orw]   = acc[mf][nf][1];
            T[jl*132 + orw + 8]   = acc[mf][nf][2];
            T[(jl+1)*132 + orw+8] = acc[mf][nf][3];
        }
    __syncthreads();
    int cg16 = t & 15, rr = t >> 4;
    #pragma unroll
    for (int r = 0; r < 8; r++) {
        int row = rr + 16*r;
        float4 v0 = *(float4*)&T[row*132 + cg16*8];
        float4 v1 = *(float4*)&T[row*132 + cg16*8 + 4];
        __half h[8];
        h[0] = __float2half_rn(v0.x); h[1] = __float2half_rn(v0.y);
        h[2] = __float2half_rn(v0.z); h[3] = __float2half_rn(v0.w);
        h[4] = __float2half_rn(v1.x); h[5] = __float2half_rn(v1.y);
        h[6] = __float2half_rn(v1.z); h[7] = __float2half_rn(v1.w);
        *(uint4*)&g_Zh[(size_t)(j0+row)*512 + o0 + cg16*8] = *(uint4*)h;
    }
}

// ================= GEMM2 (fp16): stats + max_k of w4 @ relu(bn3(Z)) =================
// CTA 256o x 64j (occ 2), K=512 in 8 chunks of 64; 8 warps, warp tile 64x32.
#define G2_SMEM 86016
__global__ __launch_bounds__(256, 2) void tcg2() {
    extern __shared__ __align__(16) char smc[];
    uint32_t sb = smem_u32(smc);
    int t = threadIdx.x, lane = t & 31, wid = t >> 5;
    int wm = wid & 3, wn = wid >> 2;
    int j0 = blockIdx.x * 64;
    float* sa3 = (float*)(smc + 81920);
    float* sd3 = sa3 + 512;
    for (int i = t; i < 512; i += 256) { sa3[i] = g_a3[i]; sd3[i] = g_d3[i]; }

    float acc[4][4][4];
    #pragma unroll
    for (int mf = 0; mf < 4; mf++)
        #pragma unroll
        for (int nf = 0; nf < 4; nf++)
            #pragma unroll
            for (int e = 0; e < 4; e++) acc[mf][nf][e] = 0.0f;

    auto issueA = [&](int buf, int kc) {
        uint32_t abb = sb + buf*32768;
        #pragma unroll
        for (int i = 0; i < 8; i++) {
            int slot = t + 256*i; int o = slot >> 3, chR = slot & 7;
            CPA(abb + o*128 + ((chR ^ (o & 7)) << 4),
                &g_w4h[(size_t)o*512 + kc*64 + chR*8]);
        }
        CPA_COMMIT();
    };
    auto loadB = [&](int kc, uint4* br) {
        #pragma unroll
        for (int i = 0; i < 2; i++) {
            int slot = t + 256*i;
            int j = slot >> 3, chR = slot & 7;
            br[i] = *(const uint4*)&g_Zh[(size_t)(j0+j)*512 + kc*64 + chR*8];
        }
    };
    auto storeB = [&](int buf, int kc, const uint4* br) {
        char* Bp = smc + 65536 + buf*8192;
        #pragma unroll
        for (int i = 0; i < 2; i++) {
            int slot = t + 256*i;
            int j = slot >> 3, chR = slot & 7;
            const __half* h = (const __half*)&br[i];
            int c = kc*64 + chR*8;
            __half v[8];
            #pragma unroll
            for (int e = 0; e < 8; e++)
                v[e] = __float2half_rn(fmaxf(0.f, fmaf(__half2float(h[e]), sa3[c+e], sd3[c+e])));
            *(uint4*)(Bp + j*128 + ((chR ^ (j & 7)) << 4)) = *(uint4*)v;
        }
    };
    auto compute = [&](int buf) {
        uint32_t abase = sb + buf*32768;
        uint32_t bbase = sb + 65536 + buf*8192;
        int t7 = lane & 7, mi = lane >> 3;
        #pragma unroll
        for (int s = 0; s < 4; s++) {
            uint32_t a[4][4], b[4][2];
            #pragma unroll
            for (int mf = 0; mf < 4; mf++) {
                int row = wm*64 + mf*16 + ((mi & 1) << 3) + t7;
                int ch = 2*s + (mi >> 1);
                LDM4(a[mf][0], a[mf][1], a[mf][2], a[mf][3],
                     abase + row*128 + ((ch ^ (row & 7)) << 4));
            }
            #pragma unroll
            for (int np = 0; np < 2; np++) {
                int row = wn*32 + np*16 + ((mi >> 1) << 3) + t7;
                int ch = 2*s + (mi & 1);
                LDM4(b[2*np][0], b[2*np][1], b[2*np+1][0], b[2*np+1][1],
                     bbase + row*128 + ((ch ^ (row & 7)) << 4));
            }
            #pragma unroll
            for (int mf = 0; mf < 4; mf++)
                #pragma unroll
                for (int nf = 0; nf < 4; nf++)
                    MMA16(acc[mf][nf], a[mf], b[nf]);
        }
    };

    __syncthreads();
    issueA(0, 0);
    {
        uint4 br0[2];
        loadB(0, br0);
        storeB(0, 0, br0);
    }
    uint4 br[2];
    for (int kc = 0; kc < 8; kc++) {
        int cur = kc & 1;
        CPA_WAIT0();
        __syncthreads();
        if (kc < 7) { issueA(cur ^ 1, kc + 1); loadB(kc + 1, br); }
        compute(cur);
        if (kc < 7) storeB(cur ^ 1, kc + 1, br);
    }

    int t4 = lane & 3, gr = lane >> 2;
    int jt0 = (j0 >> 4) + wn*2;
    #pragma unroll
    for (int mf = 0; mf < 4; mf++)
        #pragma unroll
        for (int rs = 0; rs < 2; rs++) {
            int o = wm*64 + mf*16 + rs*8 + gr;
            double s = 0.0, q = 0.0;
            #pragma unroll
            for (int nf = 0; nf < 4; nf++) {
                float v0 = acc[mf][nf][rs*2], v1 = acc[mf][nf][rs*2+1];
                s += (double)v0 + (double)v1;
                q += (double)v0*(double)v0 + (double)v1*(double)v1;
            }
            s += __shfl_xor_sync(0xffffffffu, s, 1); s += __shfl_xor_sync(0xffffffffu, s, 2);
            q += __shfl_xor_sync(0xffffffffu, q, 1); q += __shfl_xor_sync(0xffffffffu, q, 2);
            if (t4 == 0) { atomicAdd(&g_bn4sum[o], s); atomicAdd(&g_bn4sq[o], q); }
            #pragma unroll
            for (int tt = 0; tt < 2; tt++) {
                float m = fmaxf(fmaxf(acc[mf][2*tt][rs*2], acc[mf][2*tt][rs*2+1]),
                                fmaxf(acc[mf][2*tt+1][rs*2], acc[mf][2*tt+1][rs*2+1]));
                m = fmaxf(m, __shfl_xor_sync(0xffffffffu, m, 1));
                m = fmaxf(m, __shfl_xor_sync(0xffffffffu, m, 2));
                if (t4 == 0) g_M4[(size_t)(jt0 + tt)*256 + o] = m;
            }
        }
}

// ---------------- BN affine params ----------------
__global__ void bn3aff(const float* __restrict__ g, const float* __restrict__ b) {
    int c = threadIdx.x;
    if (c >= 512) return;
    double inv = 1.0 / (double)JJ;
    double m = g_bn3sum[c]*inv;
    double var = g_bn3sq[c]*inv - m*m;
    float a = (float)((double)g[c] / sqrt(var + EPSf));
    g_a3[c] = a;
    g_d3[c] = b[c] - (float)m * a;
}
__global__ void bn4aff(const float* __restrict__ g, const float* __restrict__ b) {
    int c = threadIdx.x;
    if (c >= 256) return;
    double inv = 1.0 / (double)JJ;
    double m = g_bn4sum[c]*inv;
    double var = g_bn4sq[c]*inv - m*m;
    float a = (float)((double)g[c] / sqrt(var + EPSf));
    g_a4[c] = a;
    g_d4[c] = b[c] - (float)m * a;
}

// ---------------- final: feat[b][o][ns] = relu(a4*M4 + d4)  (a4>0) ----------------
__global__ void finalk(float* __restrict__ out) {
    __shared__ float sm[32*257];
    int b = blockIdx.x >> 4, chunk = blockIdx.x & 15, t = threadIdx.x;
    int tile0 = b*512 + chunk*32;
    for (int i = t; i < 8192; i += 256) {
        int tl = i >> 8, o = i & 255;
        sm[tl*257 + o] = g_M4[(size_t)(tile0 + tl)*256 + o];
    }
    __syncthreads();
    int nsl = t & 31, og = t >> 5;
    for (int pass = 0; pass < 32; pass++) {
        int o = pass*8 + og;
        float a = g_a4[o], d = g_d4[o];
        float v = fmaxf(0.0f, fmaf(sm[nsl*257 + o], a, d));
        out[Bb*NSd*3 + b*131072 + o*512 + chunk*32 + nsl] = v;
    }
}

// ---------------- launch ----------------
extern "C" void kernel_launch(void* const* d_in, const int* in_sizes, int n_in,
                              void* d_out, int out_size) {
    const float* p    = (const float*)d_in[0];
    const float* w1   = (const float*)d_in[1];
    const float* w2   = (const float*)d_in[2];
    const float* b2   = (const float*)d_in[3];
    const float* bn1g = (const float*)d_in[4];
    const float* bn1b = (const float*)d_in[5];
    const float* w3   = (const float*)d_in[6];
    const float* bn3g = (const float*)d_in[7];
    const float* bn3b = (const float*)d_in[8];
    const float* w4   = (const float*)d_in[9];
    const float* bn4g = (const float*)d_in[10];
    const float* bn4b = (const float*)d_in[11];
    float* out = (float*)d_out;

    cudaFuncSetAttribute(tcg0, cudaFuncAttributeMaxDynamicSharedMemorySize, G0_SMEM);
    cudaFuncSetAttribute(tcg1, cudaFuncAttributeMaxDynamicSharedMemorySize, G1_SMEM);
    cudaFuncSetAttribute(tcg2, cudaFuncAttributeMaxDynamicSharedMemorySize, G2_SMEM);

    zerok<<<1, 512>>>();
    precompk<<<1, 256>>>(w1, w2);
    fpsk<<<32, 256>>>(p, out);                 // centroids -> out[0:49152]
    knnk<<<256, 64>>>(p, out);                 // 4th launch -> profiled next round
    roundwk<<<512, 512>>>(w3, w4);
    bn1k<<<1, 256>>>(b2, bn1g, bn1b);
    pgenk<<<NT/8, 256>>>();
    tcg0<<<dim3(NT/128, 4), 256, G0_SMEM>>>();
    tcg1<<<dim3(JJ/128, 4), 256, G1_SMEM>>>();
    bn3aff<<<1, 512>>>(bn3g, bn3b);
    tcg2<<<JJ/64, 256, G2_SMEM>>>();
    bn4aff<<<1, 256>>>(bn4g, bn4b);
    finalk<<<Bb*16, 256>>>(out);
}

// round 15
// speedup vs baseline: 2.8566x; 1.0569x over previous
#include <cuda_runtime.h>
#include <cuda_fp16.h>
#include <cstdint>

#define Bb 32
#define Np 2048
#define NSd 512
#define KN 16
#define NT (Bb*NSd)          // 16384 tiles
#define JJ (NT*KN)           // 262144 columns
#define EPSf 1e-5

// ---------------- scratch ----------------
__device__ float  g_grouped[NT*KN*3];
__device__ double g_sum9[9];
__device__ float  g_Weff2[256*3];
__device__ float  g_A1[256*3];
__device__ float  g_c1v[256];
__device__ __half g_Ph [NT*256];               // pooled [tile][c] fp16
__device__ __half g_w3h[512*512];              // fp16 w3
__device__ __half g_w4h[256*512];              // fp16 w4
__device__ float  g_Zp[(size_t)NT*512];        // 32 MB  Zp[t][o] = w3a @ pooled
__device__ __half g_Zh[(size_t)JJ*512];        // 268 MB  [j][c] fp16
__device__ float  g_M4[NT*256];                // max_k conv4-out [tile][o]
__device__ double g_bn3sum[512], g_bn3sq[512], g_bn4sum[256], g_bn4sq[256];
__device__ float  g_a3[512], g_d3[512], g_a4[256], g_d4[256];

// ---------------- helpers ----------------
__device__ __forceinline__ uint32_t smem_u32(const void* p) {
    uint32_t a;
    asm("{ .reg .u64 t; cvta.to.shared.u64 t, %1; cvt.u32.u64 %0, t; }" : "=r"(a) : "l"(p));
    return a;
}
#define LDM4(r0,r1,r2,r3,addr) \
    asm volatile("ldmatrix.sync.aligned.m8n8.x4.shared.b16 {%0,%1,%2,%3}, [%4];" \
        : "=r"(r0),"=r"(r1),"=r"(r2),"=r"(r3) : "r"(addr))
#define MMA16(c, a, b) \
    asm volatile("mma.sync.aligned.m16n8k16.row.col.f32.f16.f16.f32 " \
        "{%0,%1,%2,%3}, {%4,%5,%6,%7}, {%8,%9}, {%0,%1,%2,%3};" \
        : "+f"((c)[0]),"+f"((c)[1]),"+f"((c)[2]),"+f"((c)[3]) \
        : "r"((a)[0]),"r"((a)[1]),"r"((a)[2]),"r"((a)[3]), "r"((b)[0]),"r"((b)[1]))
#define CPA(dst, src) asm volatile("cp.async.cg.shared.global [%0], [%1], 16;" ::"r"(dst),"l"(src))
#define CPA_COMMIT()  asm volatile("cp.async.commit_group;" ::: "memory")
#define CPA_WAIT0()   asm volatile("cp.async.wait_group 0;" ::: "memory")

// ---------------- zero accumulators (graph replays!) ----------------
__global__ void zerok() {
    int t = threadIdx.x;
    if (t < 9) g_sum9[t] = 0.0;
    for (int i = t; i < 512; i += blockDim.x) { g_bn3sum[i] = 0.0; g_bn3sq[i] = 0.0; }
    for (int i = t; i < 256; i += blockDim.x) { g_bn4sum[i] = 0.0; g_bn4sq[i] = 0.0; }
}

__global__ void precompk(const float* __restrict__ w1, const float* __restrict__ w2) {
    int t = threadIdx.x;
    if (t < 256) {
        double s0 = 0.0, s1 = 0.0, s2 = 0.0;
        for (int i = 0; i < 256; i++) {
            double wi = (double)w2[t*256 + i];
            s0 += wi * ((double)w1[i*6+0] + (double)w1[i*6+3]);
            s1 += wi * ((double)w1[i*6+1] + (double)w1[i*6+4]);
            s2 += wi * ((double)w1[i*6+2] + (double)w1[i*6+5]);
        }
        g_Weff2[t*3+0] = (float)s0; g_Weff2[t*3+1] = (float)s1; g_Weff2[t*3+2] = (float)s2;
    }
}

// pre-round weights to fp16
__global__ void roundwk(const float* __restrict__ w3, const float* __restrict__ w4) {
    int i = blockIdx.x*512 + threadIdx.x;
    if (i < 512*512) g_w3h[i] = __float2half_rn(w3[i]);
    if (i < 256*512) g_w4h[i] = __float2half_rn(w4[i]);
}

// ---------------- FPS: 32 blocks x 256 threads, 8 pts/thread, 1 barrier/step ----------------
__global__ void fpsk(const float* __restrict__ p, float* __restrict__ outc) {
    __shared__ float sp[Np*3];
    __shared__ unsigned long long skey[2][8];
    int b = blockIdx.x, t = threadIdx.x;
    for (int i = t; i < Np*3; i += 256) sp[i] = p[b*Np*3 + i];
    __syncthreads();
    float px[8], py[8], pz[8], dist[8];
    #pragma unroll
    for (int i = 0; i < 8; i++) {
        int n = t + 256*i;
        px[i] = sp[n*3+0]; py[i] = sp[n*3+1]; pz[i] = sp[n*3+2];
        dist[i] = 1e10f;
    }
    int lane = t & 31, wid = t >> 5;
    int cs = 0;
    for (int s = 0; s < NSd; s++) {
        if (t == 0) {
            outc[(b*NSd + s)*3 + 0] = sp[cs*3+0];
            outc[(b*NSd + s)*3 + 1] = sp[cs*3+1];
            outc[(b*NSd + s)*3 + 2] = sp[cs*3+2];
        }
        float cx = sp[cs*3+0], cy = sp[cs*3+1], cz = sp[cs*3+2];
        unsigned long long best = 0ull;
        #pragma unroll
        for (int i = 0; i < 8; i++) {
            float dx = __fadd_rn(px[i], -cx);
            float dy = __fadd_rn(py[i], -cy);
            float dz = __fadd_rn(pz[i], -cz);
            float d = __fadd_rn(__fadd_rn(__fmul_rn(dx,dx), __fmul_rn(dy,dy)), __fmul_rn(dz,dz));
            dist[i] = fminf(dist[i], d);
            unsigned long long key = ((unsigned long long)__float_as_uint(dist[i]) << 32)
                                   | (unsigned)(Np - 1 - (t + 256*i));
            best = max(best, key);
        }
        #pragma unroll
        for (int off = 16; off; off >>= 1)
            best = max(best, __shfl_down_sync(0xffffffffu, best, off));
        if (lane == 0) skey[s & 1][wid] = best;
        __syncthreads();
        const unsigned long long* sk = skey[s & 1];
        unsigned long long k2 = max(max(max(sk[0], sk[1]), max(sk[2], sk[3])),
                                    max(max(sk[4], sk[5]), max(sk[6], sk[7])));
        cs = Np - 1 - (int)(unsigned)(k2 & 0xffffffffull);
    }
}

// ---------------- kNN: 256 blocks x 256 threads; 4 threads per centroid, split scan + merge ----------------
// dyn smem: shp4 (32768) + md (16384) + mi (16384) = 65536
#define KNN_SMEM 65536
__global__ void knnk(const float* __restrict__ p, const float* __restrict__ cntrd) {
    extern __shared__ __align__(16) char ksm[];
    float4* shp4 = (float4*)ksm;                   // 2048 x float4
    float*  md   = (float*)(ksm + 32768);          // [cl][q][16]
    int*    mi   = (int*)(ksm + 49152);            // [cl][q][16]
    __shared__ double s9[9];
    int t = threadIdx.x;
    int cl = t >> 2, q = t & 3;
    int gc = blockIdx.x*64 + cl;
    int b = blockIdx.x >> 3;                        // 8 blocks per batch
    for (int n = t; n < Np; n += 256) {
        float x = p[b*Np*3 + n*3 + 0];
        float y = p[b*Np*3 + n*3 + 1];
        float z = p[b*Np*3 + n*3 + 2];
        float p2 = __fadd_rn(__fadd_rn(__fmul_rn(x,x), __fmul_rn(y,y)), __fmul_rn(z,z));
        shp4[n] = make_float4(x, y, z, p2);
    }
    if (t < 9) s9[t] = 0.0;
    __syncthreads();
    float cx = cntrd[gc*3+0], cy = cntrd[gc*3+1], cz = cntrd[gc*3+2];
    float c2 = __fadd_rn(__fadd_rn(__fmul_rn(cx,cx), __fmul_rn(cy,cy)), __fmul_rn(cz,cz));
    float hd[KN]; int hi[KN];
    #pragma unroll
    for (int k = 0; k < KN; k++) { hd[k] = 3.4e38f; hi[k] = 0; }
    int n0 = q*512;
    for (int i = 0; i < 512; i++) {
        int n = n0 + i;
        float4 v = shp4[n];
        float dot = __fadd_rn(__fadd_rn(__fmul_rn(cx, v.x),
                                        __fmul_rn(cy, v.y)),
                              __fmul_rn(cz, v.z));
        float d2 = __fadd_rn(__fadd_rn(c2, v.w), -__fmul_rn(2.0f, dot));
        if (d2 < hd[KN-1]) {
            hd[KN-1] = d2; hi[KN-1] = n;
            #pragma unroll
            for (int j = KN-1; j > 0; --j) {
                bool sw = hd[j] < hd[j-1];
                float td = hd[j]; int ti = hi[j];
                float tdm = hd[j-1]; int tim = hi[j-1];
                hd[j]   = sw ? tdm : td;   hi[j]   = sw ? tim : ti;
                hd[j-1] = sw ? td  : tdm;  hi[j-1] = sw ? ti  : tim;
            }
        }
    }
    int base = (cl*4 + q)*16;
    #pragma unroll
    for (int k = 0; k < KN; k++) { md[base + k] = hd[k]; mi[base + k] = hi[k]; }
    __syncthreads();

    if (q == 0) {
        int lb = cl*64;                // this centroid's 4 lists start here
        int ptr0 = 0, ptr1 = 0, ptr2 = 0, ptr3 = 0;
        double sx=0, sy=0, sz=0, sxx=0, syy=0, szz=0, sxy=0, sxz=0, syz=0;
        #pragma unroll 1
        for (int k = 0; k < KN; k++) {
            float d0 = (ptr0 < 16) ? md[lb + ptr0]      : 3.4e38f;
            float d1 = (ptr1 < 16) ? md[lb + 16 + ptr1] : 3.4e38f;
            float d2v= (ptr2 < 16) ? md[lb + 32 + ptr2] : 3.4e38f;
            float d3 = (ptr3 < 16) ? md[lb + 48 + ptr3] : 3.4e38f;
            int bq = 0; float bd = d0;
            if (d1 < bd) { bd = d1; bq = 1; }
            if (d2v < bd) { bd = d2v; bq = 2; }
            if (d3 < bd) { bd = d3; bq = 3; }
            int n;
            if (bq == 0) { n = mi[lb + ptr0]; ptr0++; }
            else if (bq == 1) { n = mi[lb + 16 + ptr1]; ptr1++; }
            else if (bq == 2) { n = mi[lb + 32 + ptr2]; ptr2++; }
            else { n = mi[lb + 48 + ptr3]; ptr3++; }
            float4 v = shp4[n];
            g_grouped[(gc*KN + k)*3 + 0] = v.x;
            g_grouped[(gc*KN + k)*3 + 1] = v.y;
            g_grouped[(gc*KN + k)*3 + 2] = v.z;
            sx += v.x; sy += v.y; sz += v.z;
            sxx += (double)v.x*v.x; syy += (double)v.y*v.y; szz += (double)v.z*v.z;
            sxy += (double)v.x*v.y; sxz += (double)v.x*v.z; syz += (double)v.y*v.z;
        }
        atomicAdd(&s9[0], sx);  atomicAdd(&s9[1], sy);  atomicAdd(&s9[2], sz);
        atomicAdd(&s9[3], sxx); atomicAdd(&s9[4], syy); atomicAdd(&s9[5], szz);
        atomicAdd(&s9[6], sxy); atomicAdd(&s9[7], sxz); atomicAdd(&s9[8], syz);
    }
    __syncthreads();
    if (t < 9) atomicAdd(&g_sum9[t], s9[t]);
}

// ---------------- BN1 affine from analytic moments ----------------
__global__ void bn1k(const float* __restrict__ b2, const float* __restrict__ g1,
                     const float* __restrict__ b1) {
    int o = threadIdx.x;
    if (o >= 256) return;
    double inv = 1.0 / (double)JJ;
    double Ex = g_sum9[0]*inv, Ey = g_sum9[1]*inv, Ez = g_sum9[2]*inv;
    double Mxx = g_sum9[3]*inv, Myy = g_sum9[4]*inv, Mzz = g_sum9[5]*inv;
    double Mxy = g_sum9[6]*inv, Mxz = g_sum9[7]*inv, Myz = g_sum9[8]*inv;
    double w0 = g_Weff2[o*3], w1v = g_Weff2[o*3+1], w2v = g_Weff2[o*3+2];
    double bo = b2[o];
    double wEg = w0*Ex + w1v*Ey + w2v*Ez;
    double m = wEg + bo;
    double Ex2 = w0*w0*Mxx + w1v*w1v*Myy + w2v*w2v*Mzz
               + 2.0*(w0*w1v*Mxy + w0*w2v*Mxz + w1v*w2v*Myz)
               + 2.0*bo*wEg + bo*bo;
    double var = Ex2 - m*m;
    double s = (double)g1[o] / sqrt(var + EPSf);
    g_A1[o*3+0] = (float)(s*w0);
    g_A1[o*3+1] = (float)(s*w1v);
    g_A1[o*3+2] = (float)(s*w2v);
    g_c1v[o] = (float)((double)b1[o] + s*(bo - m));
}

// ---------------- pooled: Ph[tile][c] = fp16(max_k relu(A1.xyz + c1)) ----------------
__global__ void pgenk() {
    __shared__ float gsh[48];
    int t = threadIdx.x;
    float a0 = g_A1[t*3], a1 = g_A1[t*3+1], a2 = g_A1[t*3+2], c1 = g_c1v[t];
    for (int it = 0; it < 8; it++) {
        int tile = blockIdx.x*8 + it;
        __syncthreads();
        if (t < 48) gsh[t] = g_grouped[tile*48 + t];
        __syncthreads();
        float mx = 0.0f;
        #pragma unroll
        for (int k = 0; k < KN; k++)
            mx = fmaxf(mx, fmaxf(0.0f, fmaf(a0, gsh[k*3], fmaf(a1, gsh[k*3+1], fmaf(a2, gsh[k*3+2], c1)))));
        g_Ph[(size_t)tile*256 + t] = __float2half_rn(mx);
    }
}

// ================= GEMM0 (fp16): Zp[t][o] = sum_{c<256} w3[o][c]*pooled[t][c] =================
#define G0_SMEM 69120
__global__ __launch_bounds__(256, 2) void tcg0() {
    extern __shared__ __align__(16) char smc[];
    float* smf = (float*)smc;
    uint32_t sb = smem_u32(smc);
    int t = threadIdx.x, lane = t & 31, wid = t >> 5;
    int wm = wid & 3, wn = wid >> 2;
    int t0 = blockIdx.x * 128, o0 = blockIdx.y * 128;

    float acc[2][8][4];
    #pragma unroll
    for (int mf = 0; mf < 2; mf++)
        #pragma unroll
        for (int nf = 0; nf < 8; nf++)
            #pragma unroll
            for (int e = 0; e < 4; e++) acc[mf][nf][e] = 0.0f;

    auto issue = [&](int buf, int kc) {
        uint32_t abb = sb + buf*16384;
        uint32_t bbb = sb + 32768 + buf*16384;
        #pragma unroll
        for (int i = 0; i < 4; i++) {
            int slot = t + 256*i; int o = slot >> 3, chR = slot & 7;
            CPA(abb + o*128 + ((chR ^ (o & 7)) << 4),
                &g_w3h[(size_t)(o0+o)*512 + kc*64 + chR*8]);
        }
        #pragma unroll
        for (int i = 0; i < 4; i++) {
            int slot = t + 256*i; int j = slot >> 3, chR = slot & 7;
            CPA(bbb + j*128 + ((chR ^ (j & 7)) << 4),
                &g_Ph[(size_t)(t0 + j)*256 + kc*64 + chR*8]);
        }
        CPA_COMMIT();
    };

    auto compute = [&](int buf) {
        uint32_t abase = sb + buf*16384;
        uint32_t bbase = sb + 32768 + buf*16384;
        int t7 = lane & 7, mi = lane >> 3;
        #pragma unroll
        for (int s = 0; s < 4; s++) {
            uint32_t a[2][4], b[8][2];
            #pragma unroll
            for (int mf = 0; mf < 2; mf++) {
                int row = wm*32 + mf*16 + ((mi & 1) << 3) + t7;
                int ch = 2*s + (mi >> 1);
                LDM4(a[mf][0], a[mf][1], a[mf][2], a[mf][3],
                     abase + row*128 + ((ch ^ (row & 7)) << 4));
            }
            #pragma unroll
            for (int np = 0; np < 4; np++) {
                int row = wn*64 + np*16 + ((mi >> 1) << 3) + t7;
                int ch = 2*s + (mi & 1);
                LDM4(b[2*np][0], b[2*np][1], b[2*np+1][0], b[2*np+1][1],
                     bbase + row*128 + ((ch ^ (row & 7)) << 4));
            }
            #pragma unroll
            for (int mf = 0; mf < 2; mf++)
                #pragma unroll
                for (int nf = 0; nf < 8; nf++)
                    MMA16(acc[mf][nf], a[mf], b[nf]);
        }
    };

    issue(0, 0);
    for (int kc = 0; kc < 4; kc++) {
        int cur = kc & 1;
        CPA_WAIT0();
        __syncthreads();
        if (kc < 3) issue(cur ^ 1, kc + 1);
        compute(cur);
    }
    __syncthreads();

    int t4 = lane & 3, gr = lane >> 2;
    float* T = smf;
    #pragma unroll
    for (int mf = 0; mf < 2; mf++)
        #pragma unroll
        for (int nf = 0; nf < 8; nf++) {
            int orw = wm*32 + mf*16 + gr;
            int jl = wn*64 + nf*8 + 2*t4;
            T[jl*132 + orw]       = acc[mf][nf][0];
            T[(jl+1)*132 + orw]   = acc[mf][nf][1];
            T[jl*132 + orw + 8]   = acc[mf][nf][2];
            T[(jl+1)*132 + orw+8] = acc[mf][nf][3];
        }
    __syncthreads();
    int col4 = t & 31, wrow = t >> 5;
    #pragma unroll
    for (int r = 0; r < 16; r++) {
        int row = wrow + 8*r;
        float4 v = *(float4*)&T[row*132 + col4*4];
        *(float4*)&g_Zp[(size_t)(t0+row)*512 + o0 + col4*4] = v;
    }
}

// ================= GEMM1 (fp16): Z[j][o] = Zp[t(j)][o] + sum_c w3b[o][c]*H[j][c] =================
#define G1_SMEM 75264
__global__ __launch_bounds__(256, 2) void tcg1() {
    extern __shared__ __align__(16) char smc[];
    float* smf = (float*)smc;
    uint32_t sb = smem_u32(smc);
    int t = threadIdx.x, lane = t & 31, wid = t >> 5;
    int wm = wid & 3, wn = wid >> 2;
    int j0 = blockIdx.x * 128, o0 = blockIdx.y * 128;
    float* sXYZ = (float*)(smc + 65536);
    float* sA0 = (float*)(smc + 67072);
    float* sA1p = sA0 + 256; float* sA2p = sA0 + 512; float* sCp = sA0 + 768;
    float* zpS = (float*)(smc + 71168);

    for (int i = t; i < 384; i += 256) sXYZ[i] = g_grouped[(size_t)j0*3 + i];
    sA0[t] = g_A1[t*3]; sA1p[t] = g_A1[t*3+1]; sA2p[t] = g_A1[t*3+2]; sCp[t] = g_c1v[t];

    float acc[2][8][4];
    #pragma unroll
    for (int mf = 0; mf < 2; mf++)
        #pragma unroll
        for (int nf = 0; nf < 8; nf++)
            #pragma unroll
            for (int e = 0; e < 4; e++) acc[mf][nf][e] = 0.0f;

    auto issue = [&](int buf, int kc) {
        uint32_t abb = sb + buf*16384;
        #pragma unroll
        for (int i = 0; i < 4; i++) {
            int slot = t + 256*i; int o = slot >> 3, chR = slot & 7;
            CPA(abb + o*128 + ((chR ^ (o & 7)) << 4),
                &g_w3h[(size_t)(o0+o)*512 + 256 + kc*64 + chR*8]);
        }
        char* Bp = smc + 32768 + buf*16384;
        int cb = kc*64;
        #pragma unroll
        for (int i = 0; i < 4; i++) {
            int slot = t + 256*i; int j = slot >> 3, chR = slot & 7;
            float x = sXYZ[j*3], y = sXYZ[j*3+1], z = sXYZ[j*3+2];
            int c = cb + chR*8;
            __half h[8];
            #pragma unroll
            for (int e = 0; e < 8; e++)
                h[e] = __float2half_rn(fmaxf(0.f,
                    fmaf(sA0[c+e], x, fmaf(sA1p[c+e], y, fmaf(sA2p[c+e], z, sCp[c+e])))));
            *(uint4*)(Bp + j*128 + ((chR ^ (j & 7)) << 4)) = *(uint4*)h;
        }
        CPA_COMMIT();
    };

    auto compute = [&](int buf) {
        uint32_t abase = sb + buf*16384;
        uint32_t bbase = sb + 32768 + buf*16384;
        int t7 = lane & 7, mi = lane >> 3;
        #pragma unroll
        for (int s = 0; s < 4; s++) {
            uint32_t a[2][4], b[8][2];
            #pragma unroll
            for (int mf = 0; mf < 2; mf++) {
                int row = wm*32 + mf*16 + ((mi & 1) << 3) + t7;
                int ch = 2*s + (mi >> 1);
                LDM4(a[mf][0], a[mf][1], a[mf][2], a[mf][3],
                     abase + row*128 + ((ch ^ (row & 7)) << 4));
            }
            #pragma unroll
            for (int np = 0; np < 4; np++) {
                int row = wn*64 + np*16 + ((mi >> 1) << 3) + t7;
                int ch = 2*s + (mi & 1);
                LDM4(b[2*np][0], b[2*np][1], b[2*np+1][0], b[2*np+1][1],
                     bbase + row*128 + ((ch ^ (row & 7)) << 4));
            }
            #pragma unroll
            for (int mf = 0; mf < 2; mf++)
                #pragma unroll
                for (int nf = 0; nf < 8; nf++)
                    MMA16(acc[mf][nf], a[mf], b[nf]);
        }
    };

    __syncthreads();
    issue(0, 0);
    for (int kc = 0; kc < 4; kc++) {
        int cur = kc & 1;
        CPA_WAIT0();
        __syncthreads();
        if (kc < 3) issue(cur ^ 1, kc + 1);
        compute(cur);
    }
    __syncthreads();

    {
        int tb = j0 >> 4;
        int tl = t >> 5, ol = (t & 31) * 4;
        float4 v = *(const float4*)&g_Zp[(size_t)(tb + tl)*512 + o0 + ol];
        *(float4*)&zpS[tl*128 + ol] = v;
    }
    __syncthreads();

    int t4 = lane & 3, gr = lane >> 2;
    #pragma unroll
    for (int mf = 0; mf < 2; mf++) {
        int orw = wm*32 + mf*16 + gr;
        #pragma unroll
        for (int nf = 0; nf < 8; nf++) {
            int tl = wn*4 + (nf >> 1);
            float zp0 = zpS[tl*128 + orw];
            float zp1 = zpS[tl*128 + orw + 8];
            acc[mf][nf][0] += zp0; acc[mf][nf][1] += zp0;
            acc[mf][nf][2] += zp1; acc[mf][nf][3] += zp1;
        }
    }

    #pragma unroll
    for (int mf = 0; mf < 2; mf++)
        #pragma unroll
        for (int rs = 0; rs < 2; rs++) {
            double s = 0.0, q = 0.0;
            #pragma unroll
            for (int nf = 0; nf < 8; nf++) {
                float v0 = acc[mf][nf][rs*2], v1 = acc[mf][nf][rs*2+1];
                s += (double)v0 + (double)v1;
                q += (double)v0*(double)v0 + (double)v1*(double)v1;
            }
            s += __shfl_xor_sync(0xffffffffu, s, 1); s += __shfl_xor_sync(0xffffffffu, s, 2);
            q += __shfl_xor_sync(0xffffffffu, q, 1); q += __shfl_xor_sync(0xffffffffu, q, 2);
            if (t4 == 0) {
                int o = o0 + wm*32 + mf*16 + rs*8 + gr;
                atomicAdd(&g_bn3sum[o], s); atomicAdd(&g_bn3sq[o], q);
            }
        }

    float* T = smf;
    #pragma unroll
    for (int mf = 0; mf < 2; mf++)
        #pragma unroll
        for (int nf = 0; nf < 8; nf++) {
            int orw = wm*32 + mf*16 + gr;
            int jl = wn*64 + nf*8 + 2*t4;
            T[jl*132 + orw]       = acc[mf][nf][0];
            T[(jl+1)*132 + orw]   = acc[mf][nf][1];
            T[jl*132 + orw + 8]   = acc[mf][nf][2];
            T[(jl+1)*132 + orw+8] = acc[mf][nf][3];
        }
    __syncthreads();
    int cg16 = t & 15, rr = t >> 4;
    #pragma unroll
    for (int r = 0; r < 8; r++) {
        int row = rr + 16*r;
        float4 v0 = *(float4*)&T[row*132 + cg16*8];
        float4 v1 = *(float4*)&T[row*132 + cg16*8 + 4];
        __half h[8];
        h[0] = __float2half_rn(v0.x); h[1] = __float2half_rn(v0.y);
        h[2] = __float2half_rn(v0.z); h[3] = __float2half_rn(v0.w);
        h[4] = __float2half_rn(v1.x); h[5] = __float2half_rn(v1.y);
        h[6] = __float2half_rn(v1.z); h[7] = __float2half_rn(v1.w);
        *(uint4*)&g_Zh[(size_t)(j0+row)*512 + o0 + cg16*8] = *(uint4*)h;
    }
}

// ================= GEMM2 (fp16): stats + max_k of w4 @ relu(bn3(Z)) =================
// CTA 256o x 64j (occ 2), K=512 in 8 chunks of 64; 8 warps, warp tile 64x32.
#define G2_SMEM 86016
__global__ __launch_bounds__(256, 2) void tcg2() {
    extern __shared__ __align__(16) char smc[];
    uint32_t sb = smem_u32(smc);
    int t = threadIdx.x, lane = t & 31, wid = t >> 5;
    int wm = wid & 3, wn = wid >> 2;
    int j0 = blockIdx.x * 64;
    float* sa3 = (float*)(smc + 81920);
    float* sd3 = sa3 + 512;
    for (int i = t; i < 512; i += 256) { sa3[i] = g_a3[i]; sd3[i] = g_d3[i]; }

    float acc[4][4][4];
    #pragma unroll
    for (int mf = 0; mf < 4; mf++)
        #pragma unroll
        for (int nf = 0; nf < 4; nf++)
            #pragma unroll
            for (int e = 0; e < 4; e++) acc[mf][nf][e] = 0.0f;

    auto issueA = [&](int buf, int kc) {
        uint32_t abb = sb + buf*32768;
        #pragma unroll
        for (int i = 0; i < 8; i++) {
            int slot = t + 256*i; int o = slot >> 3, chR = slot & 7;
            CPA(abb + o*128 + ((chR ^ (o & 7)) << 4),
                &g_w4h[(size_t)o*512 + kc*64 + chR*8]);
        }
        CPA_COMMIT();
    };
    auto loadB = [&](int kc, uint4* br) {
        #pragma unroll
        for (int i = 0; i < 2; i++) {
            int slot = t + 256*i;
            int j = slot >> 3, chR = slot & 7;
            br[i] = *(const uint4*)&g_Zh[(size_t)(j0+j)*512 + kc*64 + chR*8];
        }
    };
    auto storeB = [&](int buf, int kc, const uint4* br) {
        char* Bp = smc + 65536 + buf*8192;
        #pragma unroll
        for (int i = 0; i < 2; i++) {
            int slot = t + 256*i;
            int j = slot >> 3, chR = slot & 7;
            const __half* h = (const __half*)&br[i];
            int c = kc*64 + chR*8;
            __half v[8];
            #pragma unroll
            for (int e = 0; e < 8; e++)
                v[e] = __float2half_rn(fmaxf(0.f, fmaf(__half2float(h[e]), sa3[c+e], sd3[c+e])));
            *(uint4*)(Bp + j*128 + ((chR ^ (j & 7)) << 4)) = *(uint4*)v;
        }
    };
    auto compute = [&](int buf) {
        uint32_t abase = sb + buf*32768;
        uint32_t bbase = sb + 65536 + buf*8192;
        int t7 = lane & 7, mi = lane >> 3;
        #pragma unroll
        for (int s = 0; s < 4; s++) {
            uint32_t a[4][4], b[4][2];
            #pragma unroll
            for (int mf = 0; mf < 4; mf++) {
                int row = wm*64 + mf*16 + ((mi & 1) << 3) + t7;
                int ch = 2*s + (mi >> 1);
                LDM4(a[mf][0], a[mf][1], a[mf][2], a[mf][3],
                     abase + row*128 + ((ch ^ (row & 7)) << 4));
            }
            #pragma unroll
            for (int np = 0; np < 2; np++) {
                int row = wn*32 + np*16 + ((mi >> 1) << 3) + t7;
                int ch = 2*s + (mi & 1);
                LDM4(b[2*np][0], b[2*np][1], b[2*np+1][0], b[2*np+1][1],
                     bbase + row*128 + ((ch ^ (row & 7)) << 4));
            }
            #pragma unroll
            for (int mf = 0; mf < 4; mf++)
                #pragma unroll
                for (int nf = 0; nf < 4; nf++)
                    MMA16(acc[mf][nf], a[mf], b[nf]);
        }
    };

    __syncthreads();
    issueA(0, 0);
    {
        uint4 br0[2];
        loadB(0, br0);
        storeB(0, 0, br0);
    }
    uint4 br[2];
    for (int kc = 0; kc < 8; kc++) {
        int cur = kc & 1;
        CPA_WAIT0();
        __syncthreads();
        if (kc < 7) { issueA(cur ^ 1, kc + 1); loadB(kc + 1, br); }
        compute(cur);
        if (kc < 7) storeB(cur ^ 1, kc + 1, br);
    }

    int t4 = lane & 3, gr = lane >> 2;
    int jt0 = (j0 >> 4) + wn*2;
    #pragma unroll
    for (int mf = 0; mf < 4; mf++)
        #pragma unroll
        for (int rs = 0; rs < 2; rs++) {
            int o = wm*64 + mf*16 + rs*8 + gr;
            double s = 0.0, q = 0.0;
            #pragma unroll
            for (int nf = 0; nf < 4; nf++) {
                float v0 = acc[mf][nf][rs*2], v1 = acc[mf][nf][rs*2+1];
                s += (double)v0 + (double)v1;
                q += (double)v0*(double)v0 + (double)v1*(double)v1;
            }
            s += __shfl_xor_sync(0xffffffffu, s, 1); s += __shfl_xor_sync(0xffffffffu, s, 2);
            q += __shfl_xor_sync(0xffffffffu, q, 1); q += __shfl_xor_sync(0xffffffffu, q, 2);
            if (t4 == 0) { atomicAdd(&g_bn4sum[o], s); atomicAdd(&g_bn4sq[o], q); }
            #pragma unroll
            for (int tt = 0; tt < 2; tt++) {
                float m = fmaxf(fmaxf(acc[mf][2*tt][rs*2], acc[mf][2*tt][rs*2+1]),
                                fmaxf(acc[mf][2*tt+1][rs*2], acc[mf][2*tt+1][rs*2+1]));
                m = fmaxf(m, __shfl_xor_sync(0xffffffffu, m, 1));
                m = fmaxf(m, __shfl_xor_sync(0xffffffffu, m, 2));
                if (t4 == 0) g_M4[(size_t)(jt0 + tt)*256 + o] = m;
            }
        }
}

// ---------------- BN affine params ----------------
__global__ void bn3aff(const float* __restrict__ g, const float* __restrict__ b) {
    int c = threadIdx.x;
    if (c >= 512) return;
    double inv = 1.0 / (double)JJ;
    double m = g_bn3sum[c]*inv;
    double var = g_bn3sq[c]*inv - m*m;
    float a = (float)((double)g[c] / sqrt(var + EPSf));
    g_a3[c] = a;
    g_d3[c] = b[c] - (float)m * a;
}
__global__ void bn4aff(const float* __restrict__ g, const float* __restrict__ b) {
    int c = threadIdx.x;
    if (c >= 256) return;
    double inv = 1.0 / (double)JJ;
    double m = g_bn4sum[c]*inv;
    double var = g_bn4sq[c]*inv - m*m;
    float a = (float)((double)g[c] / sqrt(var + EPSf));
    g_a4[c] = a;
    g_d4[c] = b[c] - (float)m * a;
}

// ---------------- final: feat[b][o][ns] = relu(a4*M4 + d4)  (a4>0) ----------------
__global__ void finalk(float* __restrict__ out) {
    __shared__ float sm[32*257];
    int b = blockIdx.x >> 4, chunk = blockIdx.x & 15, t = threadIdx.x;
    int tile0 = b*512 + chunk*32;
    for (int i = t; i < 8192; i += 256) {
        int tl = i >> 8, o = i & 255;
        sm[tl*257 + o] = g_M4[(size_t)(tile0 + tl)*256 + o];
    }
    __syncthreads();
    int nsl = t & 31, og = t >> 5;
    for (int pass = 0; pass < 32; pass++) {
        int o = pass*8 + og;
        float a = g_a4[o], d = g_d4[o];
        float v = fmaxf(0.0f, fmaf(sm[nsl*257 + o], a, d));
        out[Bb*NSd*3 + b*131072 + o*512 + chunk*32 + nsl] = v;
    }
}

// ---------------- launch ----------------
extern "C" void kernel_launch(void* const* d_in, const int* in_sizes, int n_in,
                              void* d_out, int out_size) {
    const float* p    = (const float*)d_in[0];
    const float* w1   = (const float*)d_in[1];
    const float* w2   = (const float*)d_in[2];
    const float* b2   = (const float*)d_in[3];
    const float* bn1g = (const float*)d_in[4];
    const float* bn1b = (const float*)d_in[5];
    const float* w3   = (const float*)d_in[6];
    const float* bn3g = (const float*)d_in[7];
    const float* bn3b = (const float*)d_in[8];
    const float* w4   = (const float*)d_in[9];
    const float* bn4g = (const float*)d_in[10];
    const float* bn4b = (const float*)d_in[11];
    float* out = (float*)d_out;

    cudaFuncSetAttribute(knnk, cudaFuncAttributeMaxDynamicSharedMemorySize, KNN_SMEM);
    cudaFuncSetAttribute(tcg0, cudaFuncAttributeMaxDynamicSharedMemorySize, G0_SMEM);
    cudaFuncSetAttribute(tcg1, cudaFuncAttributeMaxDynamicSharedMemorySize, G1_SMEM);
    cudaFuncSetAttribute(tcg2, cudaFuncAttributeMaxDynamicSharedMemorySize, G2_SMEM);

    zerok<<<1, 512>>>();
    precompk<<<1, 256>>>(w1, w2);
    fpsk<<<32, 256>>>(p, out);                 // centroids -> out[0:49152]
    knnk<<<256, 256, KNN_SMEM>>>(p, out);
    roundwk<<<512, 512>>>(w3, w4);
    bn1k<<<1, 256>>>(b2, bn1g, bn1b);
    pgenk<<<NT/8, 256>>>();
    tcg0<<<dim3(NT/128, 4), 256, G0_SMEM>>>();
    tcg1<<<dim3(JJ/128, 4), 256, G1_SMEM>>>();
    bn3aff<<<1, 512>>>(bn3g, bn3b);
    tcg2<<<JJ/64, 256, G2_SMEM>>>();
    bn4aff<<<1, 256>>>(bn4g, bn4b);
    finalk<<<Bb*16, 256>>>(out);
}

// round 16
// speedup vs baseline: 2.8654x; 1.0031x over previous
#include <cuda_runtime.h>
#include <cuda_fp16.h>
#include <cstdint>

#define Bb 32
#define Np 2048
#define NSd 512
#define KN 16
#define NT (Bb*NSd)          // 16384 tiles
#define JJ (NT*KN)           // 262144 columns
#define EPSf 1e-5

// ---------------- scratch ----------------
__device__ float  g_grouped[NT*KN*3];
__device__ double g_sum9[9];
__device__ float  g_Weff2[256*3];
__device__ float  g_A1[256*3];
__device__ float  g_c1v[256];
__device__ __half g_Ph [NT*256];               // pooled [tile][c] fp16
__device__ __half g_w3h[512*512];              // fp16 w3
__device__ __half g_w4h[256*512];              // fp16 w4
__device__ float  g_Zp[(size_t)NT*512];        // 32 MB  Zp[t][o] = w3a @ pooled
__device__ __half g_Zh[(size_t)JJ*512];        // 268 MB  [j][c] fp16
__device__ float  g_M4[NT*256];                // max_k conv4-out [tile][o]
__device__ double g_bn3sum[512], g_bn3sq[512], g_bn4sum[256], g_bn4sq[256];
__device__ float  g_a3[512], g_d3[512], g_a4[256], g_d4[256];

// ---------------- helpers ----------------
__device__ __forceinline__ uint32_t smem_u32(const void* p) {
    uint32_t a;
    asm("{ .reg .u64 t; cvta.to.shared.u64 t, %1; cvt.u32.u64 %0, t; }" : "=r"(a) : "l"(p));
    return a;
}
#define LDM4(r0,r1,r2,r3,addr) \
    asm volatile("ldmatrix.sync.aligned.m8n8.x4.shared.b16 {%0,%1,%2,%3}, [%4];" \
        : "=r"(r0),"=r"(r1),"=r"(r2),"=r"(r3) : "r"(addr))
#define MMA16(c, a, b) \
    asm volatile("mma.sync.aligned.m16n8k16.row.col.f32.f16.f16.f32 " \
        "{%0,%1,%2,%3}, {%4,%5,%6,%7}, {%8,%9}, {%0,%1,%2,%3};" \
        : "+f"((c)[0]),"+f"((c)[1]),"+f"((c)[2]),"+f"((c)[3]) \
        : "r"((a)[0]),"r"((a)[1]),"r"((a)[2]),"r"((a)[3]), "r"((b)[0]),"r"((b)[1]))
#define CPA(dst, src) asm volatile("cp.async.cg.shared.global [%0], [%1], 16;" ::"r"(dst),"l"(src))
#define CPA_COMMIT()  asm volatile("cp.async.commit_group;" ::: "memory")
#define CPA_WAIT0()   asm volatile("cp.async.wait_group 0;" ::: "memory")

// ---------------- zero accumulators (graph replays!) ----------------
__global__ void zerok() {
    int t = threadIdx.x;
    if (t < 9) g_sum9[t] = 0.0;
    for (int i = t; i < 512; i += blockDim.x) { g_bn3sum[i] = 0.0; g_bn3sq[i] = 0.0; }
    for (int i = t; i < 256; i += blockDim.x) { g_bn4sum[i] = 0.0; g_bn4sq[i] = 0.0; }
}

__global__ void precompk(const float* __restrict__ w1, const float* __restrict__ w2) {
    int t = threadIdx.x;
    if (t < 256) {
        double s0 = 0.0, s1 = 0.0, s2 = 0.0;
        for (int i = 0; i < 256; i++) {
            double wi = (double)w2[t*256 + i];
            s0 += wi * ((double)w1[i*6+0] + (double)w1[i*6+3]);
            s1 += wi * ((double)w1[i*6+1] + (double)w1[i*6+4]);
            s2 += wi * ((double)w1[i*6+2] + (double)w1[i*6+5]);
        }
        g_Weff2[t*3+0] = (float)s0; g_Weff2[t*3+1] = (float)s1; g_Weff2[t*3+2] = (float)s2;
    }
}

// pre-round weights to fp16
__global__ void roundwk(const float* __restrict__ w3, const float* __restrict__ w4) {
    int i = blockIdx.x*512 + threadIdx.x;
    if (i < 512*512) g_w3h[i] = __float2half_rn(w3[i]);
    if (i < 256*512) g_w4h[i] = __float2half_rn(w4[i]);
}

// ---------------- FPS: 32 blocks x 256 threads, 8 pts/thread, 1 barrier/step ----------------
__global__ void fpsk(const float* __restrict__ p, float* __restrict__ outc) {
    __shared__ float sp[Np*3];
    __shared__ unsigned long long skey[2][8];
    __shared__ int scs[NSd];
    int b = blockIdx.x, t = threadIdx.x;
    for (int i = t; i < Np*3; i += 256) sp[i] = p[b*Np*3 + i];
    __syncthreads();
    float px[8], py[8], pz[8], dist[8];
    #pragma unroll
    for (int i = 0; i < 8; i++) {
        int n = t + 256*i;
        px[i] = sp[n*3+0]; py[i] = sp[n*3+1]; pz[i] = sp[n*3+2];
        dist[i] = 1e10f;
    }
    int lane = t & 31, wid = t >> 5;
    int cs = 0;
    for (int s = 0; s < NSd; s++) {
        if (t == 0) scs[s] = cs;
        float cx = sp[cs*3+0], cy = sp[cs*3+1], cz = sp[cs*3+2];
        unsigned long long best = 0ull;
        #pragma unroll
        for (int i = 0; i < 8; i++) {
            float dx = __fadd_rn(px[i], -cx);
            float dy = __fadd_rn(py[i], -cy);
            float dz = __fadd_rn(pz[i], -cz);
            float d = __fadd_rn(__fadd_rn(__fmul_rn(dx,dx), __fmul_rn(dy,dy)), __fmul_rn(dz,dz));
            dist[i] = fminf(dist[i], d);
            unsigned long long key = ((unsigned long long)__float_as_uint(dist[i]) << 32)
                                   | (unsigned)(Np - 1 - (t + 256*i));
            best = max(best, key);
        }
        #pragma unroll
        for (int off = 16; off; off >>= 1)
            best = max(best, __shfl_down_sync(0xffffffffu, best, off));
        if (lane == 0) skey[s & 1][wid] = best;
        __syncthreads();
        const unsigned long long* sk = skey[s & 1];
        unsigned long long k2 = max(max(max(sk[0], sk[1]), max(sk[2], sk[3])),
                                    max(max(sk[4], sk[5]), max(sk[6], sk[7])));
        cs = Np - 1 - (int)(unsigned)(k2 & 0xffffffffull);
    }
    __syncthreads();
    for (int s = t; s < NSd; s += 256) {
        int idx = scs[s];
        outc[(b*NSd + s)*3 + 0] = sp[idx*3+0];
        outc[(b*NSd + s)*3 + 1] = sp[idx*3+1];
        outc[(b*NSd + s)*3 + 2] = sp[idx*3+2];
    }
}

// ---------------- kNN: 512 blocks x 256 threads; 8 threads per centroid, split scan + merge ----------------
// dyn smem: shp4 (32768) + md (16384) + mi (16384) = 65536
#define KNN_SMEM 65536
__global__ void knnk(const float* __restrict__ p, const float* __restrict__ cntrd) {
    extern __shared__ __align__(16) char ksm[];
    float4* shp4 = (float4*)ksm;                   // 2048 x float4
    float*  md   = (float*)(ksm + 32768);          // [cl][q][16]  (32 cl x 8 q)
    int*    mi   = (int*)(ksm + 49152);            // [cl][q][16]
    __shared__ double s9[9];
    int t = threadIdx.x;
    int cl = t >> 3, q = t & 7;
    int gc = blockIdx.x*32 + cl;
    int b = blockIdx.x >> 4;                        // 16 blocks per batch
    for (int n = t; n < Np; n += 256) {
        float x = p[b*Np*3 + n*3 + 0];
        float y = p[b*Np*3 + n*3 + 1];
        float z = p[b*Np*3 + n*3 + 2];
        float p2 = __fadd_rn(__fadd_rn(__fmul_rn(x,x), __fmul_rn(y,y)), __fmul_rn(z,z));
        shp4[n] = make_float4(x, y, z, p2);
    }
    if (t < 9) s9[t] = 0.0;
    __syncthreads();
    float cx = cntrd[gc*3+0], cy = cntrd[gc*3+1], cz = cntrd[gc*3+2];
    float c2 = __fadd_rn(__fadd_rn(__fmul_rn(cx,cx), __fmul_rn(cy,cy)), __fmul_rn(cz,cz));
    float hd[KN]; int hi[KN];
    #pragma unroll
    for (int k = 0; k < KN; k++) { hd[k] = 3.4e38f; hi[k] = 0; }
    int n0 = q*256;
    for (int i = 0; i < 256; i++) {
        int n = n0 + i;
        float4 v = shp4[n];
        float dot = __fadd_rn(__fadd_rn(__fmul_rn(cx, v.x),
                                        __fmul_rn(cy, v.y)),
                              __fmul_rn(cz, v.z));
        float d2 = __fadd_rn(__fadd_rn(c2, v.w), -__fmul_rn(2.0f, dot));
        if (d2 < hd[KN-1]) {
            hd[KN-1] = d2; hi[KN-1] = n;
            #pragma unroll
            for (int j = KN-1; j > 0; --j) {
                bool sw = hd[j] < hd[j-1];
                float td = hd[j]; int ti = hi[j];
                float tdm = hd[j-1]; int tim = hi[j-1];
                hd[j]   = sw ? tdm : td;   hi[j]   = sw ? tim : ti;
                hd[j-1] = sw ? td  : tdm;  hi[j-1] = sw ? ti  : tim;
            }
        }
    }
    int base = (cl*8 + q)*16;
    #pragma unroll
    for (int k = 0; k < KN; k++) { md[base + k] = hd[k]; mi[base + k] = hi[k]; }
    __syncthreads();

    if (q == 0) {
        int lb = cl*128;               // this centroid's 8 lists start here
        int p0 = 0, p1 = 0, p2 = 0, p3 = 0, p4 = 0, p5 = 0, p6 = 0, p7 = 0;
        double sx=0, sy=0, sz=0, sxx=0, syy=0, szz=0, sxy=0, sxz=0, syz=0;
        #pragma unroll 1
        for (int k = 0; k < KN; k++) {
            float d0 = (p0 < 16) ? md[lb + p0]       : 3.4e38f;
            float d1 = (p1 < 16) ? md[lb + 16 + p1]  : 3.4e38f;
            float d2v= (p2 < 16) ? md[lb + 32 + p2]  : 3.4e38f;
            float d3 = (p3 < 16) ? md[lb + 48 + p3]  : 3.4e38f;
            float d4 = (p4 < 16) ? md[lb + 64 + p4]  : 3.4e38f;
            float d5 = (p5 < 16) ? md[lb + 80 + p5]  : 3.4e38f;
            float d6 = (p6 < 16) ? md[lb + 96 + p6]  : 3.4e38f;
            float d7 = (p7 < 16) ? md[lb + 112 + p7] : 3.4e38f;
            int bq = 0; float bd = d0;
            if (d1 < bd) { bd = d1; bq = 1; }
            if (d2v < bd) { bd = d2v; bq = 2; }
            if (d3 < bd) { bd = d3; bq = 3; }
            if (d4 < bd) { bd = d4; bq = 4; }
            if (d5 < bd) { bd = d5; bq = 5; }
            if (d6 < bd) { bd = d6; bq = 6; }
            if (d7 < bd) { bd = d7; bq = 7; }
            int n;
            if (bq == 0)      { n = mi[lb + p0];       p0++; }
            else if (bq == 1) { n = mi[lb + 16 + p1];  p1++; }
            else if (bq == 2) { n = mi[lb + 32 + p2];  p2++; }
            else if (bq == 3) { n = mi[lb + 48 + p3];  p3++; }
            else if (bq == 4) { n = mi[lb + 64 + p4];  p4++; }
            else if (bq == 5) { n = mi[lb + 80 + p5];  p5++; }
            else if (bq == 6) { n = mi[lb + 96 + p6];  p6++; }
            else              { n = mi[lb + 112 + p7]; p7++; }
            float4 v = shp4[n];
            g_grouped[(gc*KN + k)*3 + 0] = v.x;
            g_grouped[(gc*KN + k)*3 + 1] = v.y;
            g_grouped[(gc*KN + k)*3 + 2] = v.z;
            sx += v.x; sy += v.y; sz += v.z;
            sxx += (double)v.x*v.x; syy += (double)v.y*v.y; szz += (double)v.z*v.z;
            sxy += (double)v.x*v.y; sxz += (double)v.x*v.z; syz += (double)v.y*v.z;
        }
        atomicAdd(&s9[0], sx);  atomicAdd(&s9[1], sy);  atomicAdd(&s9[2], sz);
        atomicAdd(&s9[3], sxx); atomicAdd(&s9[4], syy); atomicAdd(&s9[5], szz);
        atomicAdd(&s9[6], sxy); atomicAdd(&s9[7], sxz); atomicAdd(&s9[8], syz);
    }
    __syncthreads();
    if (t < 9) atomicAdd(&g_sum9[t], s9[t]);
}

// ---------------- BN1 affine from analytic moments ----------------
__global__ void bn1k(const float* __restrict__ b2, const float* __restrict__ g1,
                     const float* __restrict__ b1) {
    int o = threadIdx.x;
    if (o >= 256) return;
    double inv = 1.0 / (double)JJ;
    double Ex = g_sum9[0]*inv, Ey = g_sum9[1]*inv, Ez = g_sum9[2]*inv;
    double Mxx = g_sum9[3]*inv, Myy = g_sum9[4]*inv, Mzz = g_sum9[5]*inv;
    double Mxy = g_sum9[6]*inv, Mxz = g_sum9[7]*inv, Myz = g_sum9[8]*inv;
    double w0 = g_Weff2[o*3], w1v = g_Weff2[o*3+1], w2v = g_Weff2[o*3+2];
    double bo = b2[o];
    double wEg = w0*Ex + w1v*Ey + w2v*Ez;
    double m = wEg + bo;
    double Ex2 = w0*w0*Mxx + w1v*w1v*Myy + w2v*w2v*Mzz
               + 2.0*(w0*w1v*Mxy + w0*w2v*Mxz + w1v*w2v*Myz)
               + 2.0*bo*wEg + bo*bo;
    double var = Ex2 - m*m;
    double s = (double)g1[o] / sqrt(var + EPSf);
    g_A1[o*3+0] = (float)(s*w0);
    g_A1[o*3+1] = (float)(s*w1v);
    g_A1[o*3+2] = (float)(s*w2v);
    g_c1v[o] = (float)((double)b1[o] + s*(bo - m));
}

// ---------------- pooled: Ph[tile][c] = fp16(max_k relu(A1.xyz + c1)) ----------------
__global__ void pgenk() {
    __shared__ float gsh[48];
    int t = threadIdx.x;
    float a0 = g_A1[t*3], a1 = g_A1[t*3+1], a2 = g_A1[t*3+2], c1 = g_c1v[t];
    for (int it = 0; it < 8; it++) {
        int tile = blockIdx.x*8 + it;
        __syncthreads();
        if (t < 48) gsh[t] = g_grouped[tile*48 + t];
        __syncthreads();
        float mx = 0.0f;
        #pragma unroll
        for (int k = 0; k < KN; k++)
            mx = fmaxf(mx, fmaxf(0.0f, fmaf(a0, gsh[k*3], fmaf(a1, gsh[k*3+1], fmaf(a2, gsh[k*3+2], c1)))));
        g_Ph[(size_t)tile*256 + t] = __float2half_rn(mx);
    }
}

// ================= GEMM0 (fp16): Zp[t][o] = sum_{c<256} w3[o][c]*pooled[t][c] =================
#define G0_SMEM 69120
__global__ __launch_bounds__(256, 2) void tcg0() {
    extern __shared__ __align__(16) char smc[];
    float* smf = (float*)smc;
    uint32_t sb = smem_u32(smc);
    int t = threadIdx.x, lane = t & 31, wid = t >> 5;
    int wm = wid & 3, wn = wid >> 2;
    int t0 = blockIdx.x * 128, o0 = blockIdx.y * 128;

    float acc[2][8][4];
    #pragma unroll
    for (int mf = 0; mf < 2; mf++)
        #pragma unroll
        for (int nf = 0; nf < 8; nf++)
            #pragma unroll
            for (int e = 0; e < 4; e++) acc[mf][nf][e] = 0.0f;

    auto issue = [&](int buf, int kc) {
        uint32_t abb = sb + buf*16384;
        uint32_t bbb = sb + 32768 + buf*16384;
        #pragma unroll
        for (int i = 0; i < 4; i++) {
            int slot = t + 256*i; int o = slot >> 3, chR = slot & 7;
            CPA(abb + o*128 + ((chR ^ (o & 7)) << 4),
                &g_w3h[(size_t)(o0+o)*512 + kc*64 + chR*8]);
        }
        #pragma unroll
        for (int i = 0; i < 4; i++) {
            int slot = t + 256*i; int j = slot >> 3, chR = slot & 7;
            CPA(bbb + j*128 + ((chR ^ (j & 7)) << 4),
                &g_Ph[(size_t)(t0 + j)*256 + kc*64 + chR*8]);
        }
        CPA_COMMIT();
    };

    auto compute = [&](int buf) {
        uint32_t abase = sb + buf*16384;
        uint32_t bbase = sb + 32768 + buf*16384;
        int t7 = lane & 7, mi = lane >> 3;
        #pragma unroll
        for (int s = 0; s < 4; s++) {
            uint32_t a[2][4], b[8][2];
            #pragma unroll
            for (int mf = 0; mf < 2; mf++) {
                int row = wm*32 + mf*16 + ((mi & 1) << 3) + t7;
                int ch = 2*s + (mi >> 1);
                LDM4(a[mf][0], a[mf][1], a[mf][2], a[mf][3],
                     abase + row*128 + ((ch ^ (row & 7)) << 4));
            }
            #pragma unroll
            for (int np = 0; np < 4; np++) {
                int row = wn*64 + np*16 + ((mi >> 1) << 3) + t7;
                int ch = 2*s + (mi & 1);
                LDM4(b[2*np][0], b[2*np][1], b[2*np+1][0], b[2*np+1][1],
                     bbase + row*128 + ((ch ^ (row & 7)) << 4));
            }
            #pragma unroll
            for (int mf = 0; mf < 2; mf++)
                #pragma unroll
                for (int nf = 0; nf < 8; nf++)
                    MMA16(acc[mf][nf], a[mf], b[nf]);
        }
    };

    issue(0, 0);
    for (int kc = 0; kc < 4; kc++) {
        int cur = kc & 1;
        CPA_WAIT0();
        __syncthreads();
        if (kc < 3) issue(cur ^ 1, kc + 1);
        compute(cur);
    }
    __syncthreads();

    int t4 = lane & 3, gr = lane >> 2;
    float* T = smf;
    #pragma unroll
    for (int mf = 0; mf < 2; mf++)
        #pragma unroll
        for (int nf = 0; nf < 8; nf++) {
            int orw = wm*32 + mf*16 + gr;
            int jl = wn*64 + nf*8 + 2*t4;
            T[jl*132 + orw]       = acc[mf][nf][0];
            T[(jl+1)*132 + orw]   = acc[mf][nf][1];
            T[jl*132 + orw + 8]   = acc[mf][nf][2];
            T[(jl+1)*132 + orw+8] = acc[mf][nf][3];
        }
    __syncthreads();
    int col4 = t & 31, wrow = t >> 5;
    #pragma unroll
    for (int r = 0; r < 16; r++) {
        int row = wrow + 8*r;
        float4 v = *(float4*)&T[row*132 + col4*4];
        *(float4*)&g_Zp[(size_t)(t0+row)*512 + o0 + col4*4] = v;
    }
}

// ================= GEMM1 (fp16): Z[j][o] = Zp[t(j)][o] + sum_c w3b[o][c]*H[j][c] =================
#define G1_SMEM 75264
__global__ __launch_bounds__(256, 2) void tcg1() {
    extern __shared__ __align__(16) char smc[];
    float* smf = (float*)smc;
    uint32_t sb = smem_u32(smc);
    int t = threadIdx.x, lane = t & 31, wid = t >> 5;
    int wm = wid & 3, wn = wid >> 2;
    int j0 = blockIdx.x * 128, o0 = blockIdx.y * 128;
    float* sXYZ = (float*)(smc + 65536);
    float* sA0 = (float*)(smc + 67072);
    float* sA1p = sA0 + 256; float* sA2p = sA0 + 512; float* sCp = sA0 + 768;
    float* zpS = (float*)(smc + 71168);

    for (int i = t; i < 384; i += 256) sXYZ[i] = g_grouped[(size_t)j0*3 + i];
    sA0[t] = g_A1[t*3]; sA1p[t] = g_A1[t*3+1]; sA2p[t] = g_A1[t*3+2]; sCp[t] = g_c1v[t];

    float acc[2][8][4];
    #pragma unroll
    for (int mf = 0; mf < 2; mf++)
        #pragma unroll
        for (int nf = 0; nf < 8; nf++)
            #pragma unroll
            for (int e = 0; e < 4; e++) acc[mf][nf][e] = 0.0f;

    auto issue = [&](int buf, int kc) {
        uint32_t abb = sb + buf*16384;
        #pragma unroll
        for (int i = 0; i < 4; i++) {
            int slot = t + 256*i; int o = slot >> 3, chR = slot & 7;
            CPA(abb + o*128 + ((chR ^ (o & 7)) << 4),
                &g_w3h[(size_t)(o0+o)*512 + 256 + kc*64 + chR*8]);
        }
        char* Bp = smc + 32768 + buf*16384;
        int cb = kc*64;
        #pragma unroll
        for (int i = 0; i < 4; i++) {
            int slot = t + 256*i; int j = slot >> 3, chR = slot & 7;
            float x = sXYZ[j*3], y = sXYZ[j*3+1], z = sXYZ[j*3+2];
            int c = cb + chR*8;
            __half h[8];
            #pragma unroll
            for (int e = 0; e < 8; e++)
                h[e] = __float2half_rn(fmaxf(0.f,
                    fmaf(sA0[c+e], x, fmaf(sA1p[c+e], y, fmaf(sA2p[c+e], z, sCp[c+e])))));
            *(uint4*)(Bp + j*128 + ((chR ^ (j & 7)) << 4)) = *(uint4*)h;
        }
        CPA_COMMIT();
    };

    auto compute = [&](int buf) {
        uint32_t abase = sb + buf*16384;
        uint32_t bbase = sb + 32768 + buf*16384;
        int t7 = lane & 7, mi = lane >> 3;
        #pragma unroll
        for (int s = 0; s < 4; s++) {
            uint32_t a[2][4], b[8][2];
            #pragma unroll
            for (int mf = 0; mf < 2; mf++) {
                int row = wm*32 + mf*16 + ((mi & 1) << 3) + t7;
                int ch = 2*s + (mi >> 1);
                LDM4(a[mf][0], a[mf][1], a[mf][2], a[mf][3],
                     abase + row*128 + ((ch ^ (row & 7)) << 4));
            }
            #pragma unroll
            for (int np = 0; np < 4; np++) {
                int row = wn*64 + np*16 + ((mi >> 1) << 3) + t7;
                int ch = 2*s + (mi & 1);
                LDM4(b[2*np][0], b[2*np][1], b[2*np+1][0], b[2*np+1][1],
                     bbase + row*128 + ((ch ^ (row & 7)) << 4));
            }
            #pragma unroll
            for (int mf = 0; mf < 2; mf++)
                #pragma unroll
                for (int nf = 0; nf < 8; nf++)
                    MMA16(acc[mf][nf], a[mf], b[nf]);
        }
    };

    __syncthreads();
    issue(0, 0);
    for (int kc = 0; kc < 4; kc++) {
        int cur = kc & 1;
        CPA_WAIT0();
        __syncthreads();
        if (kc < 3) issue(cur ^ 1, kc + 1);
        compute(cur);
    }
    __syncthreads();

    {
        int tb = j0 >> 4;
        int tl = t >> 5, ol = (t & 31) * 4;
        float4 v = *(const float4*)&g_Zp[(size_t)(tb + tl)*512 + o0 + ol];
        *(float4*)&zpS[tl*128 + ol] = v;
    }
    __syncthreads();

    int t4 = lane & 3, gr = lane >> 2;
    #pragma unroll
    for (int mf = 0; mf < 2; mf++) {
        int orw = wm*32 + mf*16 + gr;
        #pragma unroll
        for (int nf = 0; nf < 8; nf++) {
            int tl = wn*4 + (nf >> 1);
            float zp0 = zpS[tl*128 + orw];
            float zp1 = zpS[tl*128 + orw + 8];
            acc[mf][nf][0] += zp0; acc[mf][nf][1] += zp0;
            acc[mf][nf][2] += zp1; acc[mf][nf][3] += zp1;
        }
    }

    #pragma unroll
    for (int mf = 0; mf < 2; mf++)
        #pragma unroll
        for (int rs = 0; rs < 2; rs++) {
            double s = 0.0, q = 0.0;
            #pragma unroll
            for (int nf = 0; nf < 8; nf++) {
                float v0 = acc[mf][nf][rs*2], v1 = acc[mf][nf][rs*2+1];
                s += (double)v0 + (double)v1;
                q += (double)v0*(double)v0 + (double)v1*(double)v1;
            }
            s += __shfl_xor_sync(0xffffffffu, s, 1); s += __shfl_xor_sync(0xffffffffu, s, 2);
            q += __shfl_xor_sync(0xffffffffu, q, 1); q += __shfl_xor_sync(0xffffffffu, q, 2);
            if (t4 == 0) {
                int o = o0 + wm*32 + mf*16 + rs*8 + gr;
                atomicAdd(&g_bn3sum[o], s); atomicAdd(&g_bn3sq[o], q);
            }
        }

    float* T = smf;
    #pragma unroll
    for (int mf = 0; mf < 2; mf++)
        #pragma unroll
        for (int nf = 0; nf < 8; nf++) {
            int orw = wm*32 + mf*16 + gr;
            int jl = wn*64 + nf*8 + 2*t4;
            T[jl*132 + orw]       = acc[mf][nf][0];
            T[(jl+1)*132 + orw]   = acc[mf][nf][1];
            T[jl*132 + orw + 8]   = acc[mf][nf][2];
            T[(jl+1)*132 + orw+8] = acc[mf][nf][3];
        }
    __syncthreads();
    int cg16 = t & 15, rr = t >> 4;
    #pragma unroll
    for (int r = 0; r < 8; r++) {
        int row = rr + 16*r;
        float4 v0 = *(float4*)&T[row*132 + cg16*8];
        float4 v1 = *(float4*)&T[row*132 + cg16*8 + 4];
        __half h[8];
        h[0] = __float2half_rn(v0.x); h[1] = __float2half_rn(v0.y);
        h[2] = __float2half_rn(v0.z); h[3] = __float2half_rn(v0.w);
        h[4] = __float2half_rn(v1.x); h[5] = __float2half_rn(v1.y);
        h[6] = __float2half_rn(v1.z); h[7] = __float2half_rn(v1.w);
        *(uint4*)&g_Zh[(size_t)(j0+row)*512 + o0 + cg16*8] = *(uint4*)h;
    }
}

// ================= GEMM2 (fp16): stats + max_k of w4 @ relu(bn3(Z)) =================
// CTA 256o x 64j (occ 2), K=512 in 8 chunks of 64; 8 warps, warp tile 64x32.
#define G2_SMEM 86016
__global__ __launch_bounds__(256, 2) void tcg2() {
    extern __shared__ __align__(16) char smc[];
    uint32_t sb = smem_u32(smc);
    int t = threadIdx.x, lane = t & 31, wid = t >> 5;
    int wm = wid & 3, wn = wid >> 2;
    int j0 = blockIdx.x * 64;
    float* sa3 = (float*)(smc + 81920);
    float* sd3 = sa3 + 512;
    for (int i = t; i < 512; i += 256) { sa3[i] = g_a3[i]; sd3[i] = g_d3[i]; }

    float acc[4][4][4];
    #pragma unroll
    for (int mf = 0; mf < 4; mf++)
        #pragma unroll
        for (int nf = 0; nf < 4; nf++)
            #pragma unroll
            for (int e = 0; e < 4; e++) acc[mf][nf][e] = 0.0f;

    auto issueA = [&](int buf, int kc) {
        uint32_t abb = sb + buf*32768;
        #pragma unroll
        for (int i = 0; i < 8; i++) {
            int slot = t + 256*i; int o = slot >> 3, chR = slot & 7;
            CPA(abb + o*128 + ((chR ^ (o & 7)) << 4),
                &g_w4h[(size_t)o*512 + kc*64 + chR*8]);
        }
        CPA_COMMIT();
    };
    auto loadB = [&](int kc, uint4* br) {
        #pragma unroll
        for (int i = 0; i < 2; i++) {
            int slot = t + 256*i;
            int j = slot >> 3, chR = slot & 7;
            br[i] = *(const uint4*)&g_Zh[(size_t)(j0+j)*512 + kc*64 + chR*8];
        }
    };
    auto storeB = [&](int buf, int kc, const uint4* br) {
        char* Bp = smc + 65536 + buf*8192;
        #pragma unroll
        for (int i = 0; i < 2; i++) {
            int slot = t + 256*i;
            int j = slot >> 3, chR = slot & 7;
            const __half* h = (const __half*)&br[i];
            int c = kc*64 + chR*8;
            __half v[8];
            #pragma unroll
            for (int e = 0; e < 8; e++)
                v[e] = __float2half_rn(fmaxf(0.f, fmaf(__half2float(h[e]), sa3[c+e], sd3[c+e])));
            *(uint4*)(Bp + j*128 + ((chR ^ (j & 7)) << 4)) = *(uint4*)v;
        }
    };
    auto compute = [&](int buf) {
        uint32_t abase = sb + buf*32768;
        uint32_t bbase = sb + 65536 + buf*8192;
        int t7 = lane & 7, mi = lane >> 3;
        #pragma unroll
        for (int s = 0; s < 4; s++) {
            uint32_t a[4][4], b[4][2];
            #pragma unroll
            for (int mf = 0; mf < 4; mf++) {
                int row = wm*64 + mf*16 + ((mi & 1) << 3) + t7;
                int ch = 2*s + (mi >> 1);
                LDM4(a[mf][0], a[mf][1], a[mf][2], a[mf][3],
                     abase + row*128 + ((ch ^ (row & 7)) << 4));
            }
            #pragma unroll
            for (int np = 0; np < 2; np++) {
                int row = wn*32 + np*16 + ((mi >> 1) << 3) + t7;
                int ch = 2*s + (mi & 1);
                LDM4(b[2*np][0], b[2*np][1], b[2*np+1][0], b[2*np+1][1],
                     bbase + row*128 + ((ch ^ (row & 7)) << 4));
            }
            #pragma unroll
            for (int mf = 0; mf < 4; mf++)
                #pragma unroll
                for (int nf = 0; nf < 4; nf++)
                    MMA16(acc[mf][nf], a[mf], b[nf]);
        }
    };

    __syncthreads();
    issueA(0, 0);
    {
        uint4 br0[2];
        loadB(0, br0);
        storeB(0, 0, br0);
    }
    uint4 br[2];
    for (int kc = 0; kc < 8; kc++) {
        int cur = kc & 1;
        CPA_WAIT0();
        __syncthreads();
        if (kc < 7) { issueA(cur ^ 1, kc + 1); loadB(kc + 1, br); }
        compute(cur);
        if (kc < 7) storeB(cur ^ 1, kc + 1, br);
    }

    int t4 = lane & 3, gr = lane >> 2;
    int jt0 = (j0 >> 4) + wn*2;
    #pragma unroll
    for (int mf = 0; mf < 4; mf++)
        #pragma unroll
        for (int rs = 0; rs < 2; rs++) {
            int o = wm*64 + mf*16 + rs*8 + gr;
            double s = 0.0, q = 0.0;
            #pragma unroll
            for (int nf = 0; nf < 4; nf++) {
                float v0 = acc[mf][nf][rs*2], v1 = acc[mf][nf][rs*2+1];
                s += (double)v0 + (double)v1;
                q += (double)v0*(double)v0 + (double)v1*(double)v1;
            }
            s += __shfl_xor_sync(0xffffffffu, s, 1); s += __shfl_xor_sync(0xffffffffu, s, 2);
            q += __shfl_xor_sync(0xffffffffu, q, 1); q += __shfl_xor_sync(0xffffffffu, q, 2);
            if (t4 == 0) { atomicAdd(&g_bn4sum[o], s); atomicAdd(&g_bn4sq[o], q); }
            #pragma unroll
            for (int tt = 0; tt < 2; tt++) {
                float m = fmaxf(fmaxf(acc[mf][2*tt][rs*2], acc[mf][2*tt][rs*2+1]),
                                fmaxf(acc[mf][2*tt+1][rs*2], acc[mf][2*tt+1][rs*2+1]));
                m = fmaxf(m, __shfl_xor_sync(0xffffffffu, m, 1));
                m = fmaxf(m, __shfl_xor_sync(0xffffffffu, m, 2));
                if (t4 == 0) g_M4[(size_t)(jt0 + tt)*256 + o] = m;
            }
        }
}

// ---------------- BN affine params ----------------
__global__ void bn3aff(const float* __restrict__ g, const float* __restrict__ b) {
    int c = threadIdx.x;
    if (c >= 512) return;
    double inv = 1.0 / (double)JJ;
    double m = g_bn3sum[c]*inv;
    double var = g_bn3sq[c]*inv - m*m;
    float a = (float)((double)g[c] / sqrt(var + EPSf));
    g_a3[c] = a;
    g_d3[c] = b[c] - (float)m * a;
}
__global__ void bn4aff(const float* __restrict__ g, const float* __restrict__ b) {
    int c = threadIdx.x;
    if (c >= 256) return;
    double inv = 1.0 / (double)JJ;
    double m = g_bn4sum[c]*inv;
    double var = g_bn4sq[c]*inv - m*m;
    float a = (float)((double)g[c] / sqrt(var + EPSf));
    g_a4[c] = a;
    g_d4[c] = b[c] - (float)m * a;
}

// ---------------- final: feat[b][o][ns] = relu(a4*M4 + d4)  (a4>0) ----------------
__global__ void finalk(float* __restrict__ out) {
    __shared__ float sm[32*257];
    int b = blockIdx.x >> 4, chunk = blockIdx.x & 15, t = threadIdx.x;
    int tile0 = b*512 + chunk*32;
    for (int i = t; i < 8192; i += 256) {
        int tl = i >> 8, o = i & 255;
        sm[tl*257 + o] = g_M4[(size_t)(tile0 + tl)*256 + o];
    }
    __syncthreads();
    int nsl = t & 31, og = t >> 5;
    for (int pass = 0; pass < 32; pass++) {
        int o = pass*8 + og;
        float a = g_a4[o], d = g_d4[o];
        float v = fmaxf(0.0f, fmaf(sm[nsl*257 + o], a, d));
        out[Bb*NSd*3 + b*131072 + o*512 + chunk*32 + nsl] = v;
    }
}

// ---------------- launch ----------------
extern "C" void kernel_launch(void* const* d_in, const int* in_sizes, int n_in,
                              void* d_out, int out_size) {
    const float* p    = (const float*)d_in[0];
    const float* w1   = (const float*)d_in[1];
    const float* w2   = (const float*)d_in[2];
    const float* b2   = (const float*)d_in[3];
    const float* bn1g = (const float*)d_in[4];
    const float* bn1b = (const float*)d_in[5];
    const float* w3   = (const float*)d_in[6];
    const float* bn3g = (const float*)d_in[7];
    const float* bn3b = (const float*)d_in[8];
    const float* w4   = (const float*)d_in[9];
    const float* bn4g = (const float*)d_in[10];
    const float* bn4b = (const float*)d_in[11];
    float* out = (float*)d_out;

    cudaFuncSetAttribute(knnk, cudaFuncAttributeMaxDynamicSharedMemorySize, KNN_SMEM);
    cudaFuncSetAttribute(tcg0, cudaFuncAttributeMaxDynamicSharedMemorySize, G0_SMEM);
    cudaFuncSetAttribute(tcg1, cudaFuncAttributeMaxDynamicSharedMemorySize, G1_SMEM);
    cudaFuncSetAttribute(tcg2, cudaFuncAttributeMaxDynamicSharedMemorySize, G2_SMEM);

    zerok<<<1, 512>>>();
    precompk<<<1, 256>>>(w1, w2);
    fpsk<<<32, 256>>>(p, out);                 // centroids -> out[0:49152]
    knnk<<<512, 256, KNN_SMEM>>>(p, out);
    roundwk<<<512, 512>>>(w3, w4);
    bn1k<<<1, 256>>>(b2, bn1g, bn1b);
    pgenk<<<NT/8, 256>>>();
    tcg0<<<dim3(NT/128, 4), 256, G0_SMEM>>>();
    tcg1<<<dim3(JJ/128, 4), 256, G1_SMEM>>>();
    bn3aff<<<1, 512>>>(bn3g, bn3b);
    tcg2<<<JJ/64, 256, G2_SMEM>>>();
    bn4aff<<<1, 256>>>(bn4g, bn4b);
    finalk<<<Bb*16, 256>>>(out);
}